// round 1
// baseline (speedup 1.0000x reference)
#include <cuda_runtime.h>
#include <math.h>

#define NITEM   50000
#define NNODES  100000
#define EMB     512
#define BATCH   4096
#define NSLOT   8192
#define BK      16

// ---------------- static device scratch (no allocations allowed) ----------------
__device__ float g_egoA[51200000];   // 100000 x 512
__device__ float g_egoB[51200000];
__device__ float g_oge [51200000];
__device__ float g_edis[51200000];
__device__ float g_side[51200000];
__device__ float g_ego3[4194304];    // 8192 x 512 (layer-3 rows, per slot)
__device__ int   g_flag[NNODES];

// ---------------- init: ego0 = [vision;text], oge = [text;vision] ----------------
__global__ void k_init(const float* __restrict__ vis, const float* __restrict__ txt)
{
    size_t i = (size_t)blockIdx.x * blockDim.x + threadIdx.x;
    size_t half = (size_t)NITEM * EMB / 4;
    if (i >= half) return;
    float4 v = ((const float4*)vis)[i];
    float4 t = ((const float4*)txt)[i];
    ((float4*)g_egoA)[i]        = v;
    ((float4*)g_egoA)[half + i] = t;
    ((float4*)g_oge)[i]         = t;
    ((float4*)g_oge)[half + i]  = v;
}

// which: 0 = zero g_side, 1 = zero g_edis, 2 = zero g_flag
__global__ void k_zero(int which)
{
    size_t i = (size_t)blockIdx.x * blockDim.x + threadIdx.x;
    if (which == 2) { if (i < NNODES) g_flag[i] = 0; return; }
    size_t n4 = (size_t)NNODES * EMB / 4;
    if (i < n4) {
        float4 z = make_float4(0.f, 0.f, 0.f, 0.f);
        if (which == 0) ((float4*)g_side)[i] = z;
        else            ((float4*)g_edis)[i] = z;
    }
}

__global__ void k_setflag(const int* __restrict__ items)
{
    int j = blockIdx.x * blockDim.x + threadIdx.x;
    if (j < BATCH) {
        int it = items[j];
        g_flag[it] = 1;
        g_flag[it + NITEM] = 1;
    }
}

// ---------------- SpMM: one warp per edge, vectorized global reductions ----------------
// srcSel: 0=g_egoA 1=g_egoB 2=g_oge ; dstSel: 0=g_side 1=g_edis
__global__ void k_spmm(int srcSel, int dstSel,
                       const int* __restrict__ er, const int* __restrict__ ec,
                       const float* __restrict__ ev,
                       int nnz, int rlo, int rhi, int useFlag)
{
    const float* x = (srcSel == 0) ? g_egoA : (srcSel == 1) ? g_egoB : g_oge;
    float* outp = (dstSel == 0) ? g_side : g_edis;
    int lane = threadIdx.x & 31;
    int warp = (int)((blockIdx.x * blockDim.x + threadIdx.x) >> 5);
    int nw   = (int)((gridDim.x * blockDim.x) >> 5);
    for (int e = warp; e < nnz; e += nw) {
        int r = er[e];
        if (r < rlo || r >= rhi) continue;
        if (useFlag && !g_flag[r]) continue;
        int   c = ec[e];
        float v = ev[e];
        const float4* xs = (const float4*)(x + (size_t)c * EMB);
        float* o = outp + (size_t)r * EMB;
        #pragma unroll
        for (int i = 0; i < 4; i++) {
            float4 t = xs[i * 32 + lane];
            float* p = o + (size_t)(i * 32 + lane) * 4;
            asm volatile("red.global.add.v4.f32 [%0], {%1,%2,%3,%4};"
                         :: "l"(p), "f"(t.x * v), "f"(t.y * v), "f"(t.z * v), "f"(t.w * v)
                         : "memory");
        }
    }
}

// ---------------- fused GEMM: out = lrelu([side|edis|h] @ [Wgc;Wgc2;Wbi] + bsum) ----------------
// h built on-the-fly: h = ego*side + oge*edis
// egoSel: 0=g_egoA 1=g_egoB ; outSel: 0=g_egoB 1=g_egoA 2=g_ego3
// items==nullptr: row index == node index; items!=nullptr: row is a slot (layer 3)
__global__ __launch_bounds__(256, 2) void k_gemm(
    int egoSel, int outSel,
    const float* __restrict__ Wgc, const float* __restrict__ Wgc2, const float* __restrict__ Wbi,
    const float* __restrict__ bgc, const float* __restrict__ bgc2, const float* __restrict__ bbi,
    int M, const int* __restrict__ items)
{
    __shared__ float As[BK][128];
    __shared__ float Bs[BK][128];

    const float* Aego  = egoSel ? g_egoB : g_egoA;
    float* Cout = (outSel == 0) ? g_egoB : (outSel == 1) ? g_egoA : g_ego3;
    const float* Aside = g_side;
    const float* Aedis = g_edis;
    const float* Aoge  = g_oge;

    int tid = threadIdx.x;
    int tx = tid & 15, ty = tid >> 4;
    int row0 = blockIdx.y * 128;
    int col0 = blockIdx.x * 128;

    // A-load mapping: thread loads 2 float4 slots (tid, tid+256); slot -> (ar, kq)
    int nodeL[2], arL[2], kqL[2];
    #pragma unroll
    for (int l = 0; l < 2; l++) {
        int s = tid + l * 256;
        arL[l] = s >> 2; kqL[l] = s & 3;
        int grow = row0 + arL[l];
        int slot = (grow < M) ? grow : (M - 1);
        nodeL[l] = items ? ((slot < BATCH) ? items[slot] : (items[slot - BATCH] + NITEM)) : slot;
    }
    // B-load mapping
    int brL[2], bcL[2];
    #pragma unroll
    for (int l = 0; l < 2; l++) {
        int s = tid + l * 256;
        brL[l] = s >> 5; bcL[l] = s & 31;
    }

    float acc[8][8];
    #pragma unroll
    for (int u = 0; u < 8; u++)
        #pragma unroll
        for (int v = 0; v < 8; v++) acc[u][v] = 0.f;

    for (int kt = 0; kt < 1536 / BK; kt++) {
        int k0 = kt * BK;
        // load A tile (128 rows x 16 k), stored K-major in smem
        #pragma unroll
        for (int l = 0; l < 2; l++) {
            int i   = k0 + kqL[l] * 4;
            int seg = i >> 9, iloc = i & 511;
            size_t off = (size_t)nodeL[l] * EMB + iloc;
            float4 v;
            if (seg == 0)      v = *(const float4*)(Aside + off);
            else if (seg == 1) v = *(const float4*)(Aedis + off);
            else {
                float4 e4 = *(const float4*)(Aego  + off);
                float4 s4 = *(const float4*)(Aside + off);
                float4 o4 = *(const float4*)(Aoge  + off);
                float4 d4 = *(const float4*)(Aedis + off);
                v.x = fmaf(e4.x, s4.x, o4.x * d4.x);
                v.y = fmaf(e4.y, s4.y, o4.y * d4.y);
                v.z = fmaf(e4.z, s4.z, o4.z * d4.z);
                v.w = fmaf(e4.w, s4.w, o4.w * d4.w);
            }
            int kk = kqL[l] * 4;
            As[kk + 0][arL[l]] = v.x;
            As[kk + 1][arL[l]] = v.y;
            As[kk + 2][arL[l]] = v.z;
            As[kk + 3][arL[l]] = v.w;
        }
        // load B tile (16 k-rows x 128 cols)
        #pragma unroll
        for (int l = 0; l < 2; l++) {
            int i   = k0 + brL[l];
            int seg = i >> 9, iloc = i & 511;
            const float* Wp = (seg == 0) ? Wgc : (seg == 1) ? Wgc2 : Wbi;
            float4 v = *(const float4*)(Wp + (size_t)iloc * 512 + col0 + bcL[l] * 4);
            *(float4*)&Bs[brL[l]][bcL[l] * 4] = v;
        }
        __syncthreads();

        #pragma unroll
        for (int kk = 0; kk < BK; kk++) {
            float ra[8], rb[8];
            #pragma unroll
            for (int u = 0; u < 8; u++) ra[u] = As[kk][ty * 8 + u];
            #pragma unroll
            for (int v = 0; v < 8; v++) rb[v] = Bs[kk][tx * 8 + v];
            #pragma unroll
            for (int u = 0; u < 8; u++)
                #pragma unroll
                for (int v = 0; v < 8; v++)
                    acc[u][v] = fmaf(ra[u], rb[v], acc[u][v]);
        }
        __syncthreads();
    }

    // epilogue: combined bias + leaky_relu(0.2)
    #pragma unroll
    for (int u = 0; u < 8; u++) {
        int gr = row0 + ty * 8 + u;
        if (gr < M) {
            float xv[8];
            #pragma unroll
            for (int v = 0; v < 8; v++) {
                int gc = col0 + tx * 8 + v;
                float b = bgc[gc] + bgc2[gc] + bbi[gc];
                float x = acc[u][v] + b;
                xv[v] = (x > 0.f) ? x : 0.2f * x;
            }
            float* cp = Cout + (size_t)gr * EMB + col0 + tx * 8;
            *(float4*)(cp)     = make_float4(xv[0], xv[1], xv[2], xv[3]);
            *(float4*)(cp + 4) = make_float4(xv[4], xv[5], xv[6], xv[7]);
        }
    }
}

// ---------------- out[slot] = ego0[node]  (acc init) ----------------
__global__ void k_out_init(const int* __restrict__ items, float* __restrict__ out)
{
    int slot = blockIdx.x;
    int node = (slot < BATCH) ? items[slot] : (items[slot - BATCH] + NITEM);
    int t = threadIdx.x;
    float4 x = *(const float4*)(g_egoA + (size_t)node * EMB + t * 4);
    *(float4*)(out + (size_t)slot * EMB + t * 4) = x;
}

// ---------------- out[slot] += normalize(src_row) ----------------
// srcSel: 0=g_egoA(by node) 1=g_egoB(by node) 2=g_ego3(by slot)
__global__ void k_norm_acc(int srcSel, const int* __restrict__ items, float* __restrict__ out)
{
    int slot = blockIdx.x;
    int node = (slot < BATCH) ? items[slot] : (items[slot - BATCH] + NITEM);
    const float* row;
    if (srcSel == 0)      row = g_egoA + (size_t)node * EMB;
    else if (srcSel == 1) row = g_egoB + (size_t)node * EMB;
    else                  row = g_ego3 + (size_t)slot * EMB;

    int t = threadIdx.x;  // 128 threads, 4 floats each
    float4 x = *(const float4*)(row + t * 4);
    float ss = x.x * x.x + x.y * x.y + x.z * x.z + x.w * x.w;
    #pragma unroll
    for (int o = 16; o; o >>= 1) ss += __shfl_xor_sync(0xffffffffu, ss, o);
    __shared__ float ws[4];
    if ((t & 31) == 0) ws[t >> 5] = ss;
    __syncthreads();
    float tot = ws[0] + ws[1] + ws[2] + ws[3];
    float inv = 1.f / fmaxf(sqrtf(tot), 1e-12f);

    float* o4 = out + (size_t)slot * EMB + t * 4;
    float4 cur = *(float4*)o4;
    cur.x += x.x * inv; cur.y += x.y * inv; cur.z += x.z * inv; cur.w += x.w * inv;
    *(float4*)o4 = cur;
}

// ---------------- launch ----------------
extern "C" void kernel_launch(void* const* d_in, const int* in_sizes, int n_in,
                              void* d_out, int out_size)
{
    const float* vis   = (const float*)d_in[0];
    const float* txt   = (const float*)d_in[1];
    const int*   er    = (const int*)  d_in[2];
    const int*   ec    = (const int*)  d_in[3];
    const float* ev    = (const float*)d_in[4];
    const int*   items = (const int*)  d_in[5];
    const float* Wgc   = (const float*)d_in[6];
    const float* bgc   = (const float*)d_in[7];
    const float* Wgc2  = (const float*)d_in[8];
    const float* bgc2  = (const float*)d_in[9];
    const float* Wbi   = (const float*)d_in[10];
    const float* bbi   = (const float*)d_in[11];
    float* out = (float*)d_out;
    int nnz = in_sizes[2];

    const int ZB = 50000;            // zero grid for 12.8M float4
    const int SPMM_B = 4096;         // spmm grid

    // init ego0 / oge ; zero edis ; flags
    k_init<<<25000, 256>>>(vis, txt);
    k_zero<<<ZB, 256>>>(1);          // edis = 0
    k_zero<<<391, 256>>>(2);         // flag = 0
    k_setflag<<<16, 256>>>(items);

    // edis = spmm(oge)  (fixed across layers) - two row-chunk passes for L2 locality
    k_spmm<<<SPMM_B, 256>>>(2, 1, er, ec, ev, nnz, 0,      NITEM,  0);
    k_spmm<<<SPMM_B, 256>>>(2, 1, er, ec, ev, nnz, NITEM,  NNODES, 0);

    // acc init: out = ego0[gathered rows]
    k_out_init<<<NSLOT, 128>>>(items, out);

    // ---- layer 0: ego0(A) -> ego1(B) ----
    k_zero<<<ZB, 256>>>(0);
    k_spmm<<<SPMM_B, 256>>>(0, 0, er, ec, ev, nnz, 0,     NITEM,  0);
    k_spmm<<<SPMM_B, 256>>>(0, 0, er, ec, ev, nnz, NITEM, NNODES, 0);
    k_gemm<<<dim3(4, 782), 256>>>(0, 0,
        Wgc, Wgc2, Wbi, bgc, bgc2, bbi, NNODES, nullptr);
    k_norm_acc<<<NSLOT, 128>>>(1, items, out);

    // ---- layer 1: ego1(B) -> ego2(A) ----
    k_zero<<<ZB, 256>>>(0);
    k_spmm<<<SPMM_B, 256>>>(1, 0, er, ec, ev, nnz, 0,     NITEM,  0);
    k_spmm<<<SPMM_B, 256>>>(1, 0, er, ec, ev, nnz, NITEM, NNODES, 0);
    k_gemm<<<dim3(4, 782), 256>>>(1, 1,
        Wgc  + 1 * 512 * 512, Wgc2 + 1 * 512 * 512, Wbi + 1 * 512 * 512,
        bgc  + 1 * 512,       bgc2 + 1 * 512,       bbi + 1 * 512,
        NNODES, nullptr);
    k_norm_acc<<<NSLOT, 128>>>(0, items, out);

    // ---- layer 2 (subset): ego2(A) -> ego3 rows at gathered slots only ----
    k_zero<<<ZB, 256>>>(0);
    k_spmm<<<SPMM_B, 256>>>(0, 0, er, ec, ev, nnz, 0, NNODES, 1);   // row-filtered by flag
    k_gemm<<<dim3(4, 64), 256>>>(0, 2,
        Wgc  + 2 * 512 * 512, Wgc2 + 2 * 512 * 512, Wbi + 2 * 512 * 512,
        bgc  + 2 * 512,       bgc2 + 2 * 512,       bbi + 2 * 512,
        NSLOT, items);
    k_norm_acc<<<NSLOT, 128>>>(2, items, out);
}

// round 3
// speedup vs baseline: 1.4680x; 1.4680x over previous
#include <cuda_runtime.h>
#include <cuda_bf16.h>
#include <math.h>
#include <stdint.h>

#define NITEM   50000
#define NNODES  100000
#define EMB     512
#define BATCH   4096
#define NSLOT   8192
#define NCH     48          // 1536 / 32 K-chunks
#define STRB    80          // smem row stride in bytes (40 halves)

// ---------------- static device scratch ----------------
__device__ float g_egoA[51200000];   // 100000 x 512
__device__ float g_egoB[51200000];
__device__ float g_oge [51200000];
__device__ float g_edis[51200000];
__device__ float g_side[51200000];
__device__ float g_ego3[4194304];    // 8192 x 512
__device__ int   g_flag[NNODES];
__device__ __nv_bfloat16 g_wthi[512 * 1536];  // W^T hi, [N][K] K-contig
__device__ __nv_bfloat16 g_wtlo[512 * 1536];  // W^T lo

__device__ __forceinline__ uint32_t smem_u32(const void* p) {
    uint32_t a;
    asm("{ .reg .u64 t; cvta.to.shared.u64 t, %1; cvt.u32.u64 %0, t; }" : "=r"(a) : "l"(p));
    return a;
}
#define LDSM4(r0,r1,r2,r3,addr) \
    asm volatile("ldmatrix.sync.aligned.m8n8.x4.shared.b16 {%0,%1,%2,%3}, [%4];" \
                 : "=r"(r0),"=r"(r1),"=r"(r2),"=r"(r3) : "r"(addr))
#define MMA16816(d,a,b) \
    asm volatile("mma.sync.aligned.m16n8k16.row.col.f32.bf16.bf16.f32 " \
                 "{%0,%1,%2,%3}, {%4,%5,%6,%7}, {%8,%9}, {%0,%1,%2,%3};" \
                 : "+f"(d[0]),"+f"(d[1]),"+f"(d[2]),"+f"(d[3]) \
                 : "r"(a[0]),"r"(a[1]),"r"(a[2]),"r"(a[3]), "r"(b[0]),"r"(b[1]))

__device__ __forceinline__ uint32_t pack2(__nv_bfloat16 a, __nv_bfloat16 b) {
    __nv_bfloat162 p = __halves2bfloat162(a, b);
    return *reinterpret_cast<uint32_t*>(&p);
}

// ---------------- init: ego0 = [vision;text], oge = [text;vision] ----------------
__global__ void k_init(const float* __restrict__ vis, const float* __restrict__ txt)
{
    size_t i = (size_t)blockIdx.x * blockDim.x + threadIdx.x;
    size_t half = (size_t)NITEM * EMB / 4;
    if (i >= half) return;
    float4 v = ((const float4*)vis)[i];
    float4 t = ((const float4*)txt)[i];
    ((float4*)g_egoA)[i]        = v;
    ((float4*)g_egoA)[half + i] = t;
    ((float4*)g_oge)[i]         = t;
    ((float4*)g_oge)[half + i]  = v;
}

__global__ void k_zero(int which)
{
    size_t i = (size_t)blockIdx.x * blockDim.x + threadIdx.x;
    if (which == 2) { if (i < NNODES) g_flag[i] = 0; return; }
    size_t n4 = (size_t)NNODES * EMB / 4;
    if (i < n4) {
        float4 z = make_float4(0.f, 0.f, 0.f, 0.f);
        if (which == 0) ((float4*)g_side)[i] = z;
        else            ((float4*)g_edis)[i] = z;
    }
}

__global__ void k_setflag(const int* __restrict__ items)
{
    int j = blockIdx.x * blockDim.x + threadIdx.x;
    if (j < BATCH) {
        int it = items[j];
        g_flag[it] = 1;
        g_flag[it + NITEM] = 1;
    }
}

// ---------------- SpMM: one warp per edge, vectorized global reductions ----------------
__global__ void k_spmm(int srcSel, int dstSel,
                       const int* __restrict__ er, const int* __restrict__ ec,
                       const float* __restrict__ ev,
                       int nnz, int rlo, int rhi, int useFlag)
{
    const float* x = (srcSel == 0) ? g_egoA : (srcSel == 1) ? g_egoB : g_oge;
    float* outp = (dstSel == 0) ? g_side : g_edis;
    int lane = threadIdx.x & 31;
    int warp = (int)((blockIdx.x * blockDim.x + threadIdx.x) >> 5);
    int nw   = (int)((gridDim.x * blockDim.x) >> 5);
    for (int e = warp; e < nnz; e += nw) {
        int r = er[e];
        if (r < rlo || r >= rhi) continue;
        if (useFlag && !g_flag[r]) continue;
        int   c = ec[e];
        float v = ev[e];
        const float4* xs = (const float4*)(x + (size_t)c * EMB);
        float* o = outp + (size_t)r * EMB;
        #pragma unroll
        for (int i = 0; i < 4; i++) {
            float4 t = xs[i * 32 + lane];
            float* p = o + (size_t)(i * 32 + lane) * 4;
            asm volatile("red.global.add.v4.f32 [%0], {%1,%2,%3,%4};"
                         :: "l"(p), "f"(t.x * v), "f"(t.y * v), "f"(t.z * v), "f"(t.w * v)
                         : "memory");
        }
    }
}

// ---------------- weight transpose + bf16 hi/lo split ----------------
__global__ void k_wtconv(const float* __restrict__ Wgc, const float* __restrict__ Wgc2,
                         const float* __restrict__ Wbi)
{
    __shared__ float t[32][33];
    int kb = blockIdx.x * 32;
    int nb = blockIdx.y * 32;
    int tx = threadIdx.x & 31, ty = threadIdx.x >> 5;
    int seg = kb >> 9, kloc = kb & 511;
    const float* W = (seg == 0) ? Wgc : (seg == 1) ? Wgc2 : Wbi;
    #pragma unroll
    for (int j = 0; j < 4; j++)
        t[ty + 8 * j][tx] = W[(size_t)(kloc + ty + 8 * j) * 512 + nb + tx];
    __syncthreads();
    #pragma unroll
    for (int j = 0; j < 4; j++) {
        int n = nb + ty + 8 * j;
        float x = t[tx][ty + 8 * j];
        __nv_bfloat16 h = __float2bfloat16_rn(x);
        g_wthi[(size_t)n * 1536 + kb + tx] = h;
        g_wtlo[(size_t)n * 1536 + kb + tx] = __float2bfloat16_rn(x - __bfloat162float(h));
    }
}

// ---------------- mma.sync bf16x3 fused GEMM ----------------
// C[M,512] = lrelu([side|edis|ego*side+oge*edis] @ W + bias)
// 512 threads, tile 128x128, K-chunk 32; warp (wid/4, wid%4) -> 32x32 sub-tile.
__global__ void __launch_bounds__(512)
k_gemm(int egoSel, int outSel,
       const float* __restrict__ bgc, const float* __restrict__ bgc2,
       const float* __restrict__ bbi,
       int M, const int* __restrict__ items)
{
    __shared__ __align__(16) char smbuf[41472];
    const uint32_t OA_HI = 0, OA_LO = 10240, OB_HI = 20480, OB_LO = 30720;
    float* biasP = (float*)(smbuf + 40960);
    uint32_t smb = smem_u32(smbuf);

    int tid = threadIdx.x;
    int wid = tid >> 5, lid = tid & 31;
    int col0 = blockIdx.x * 128;
    int row0 = blockIdx.y * 128;
    int wM = wid >> 2, wN = wid & 3;

    if (tid < 128) {
        int c = col0 + tid;
        biasP[tid] = bgc[c] + bgc2[c] + bbi[c];
    }

    const float* ego = egoSel ? g_egoB : g_egoA;
    float* Cout = (outSel == 0) ? g_egoB : (outSel == 1) ? g_egoA : g_ego3;

    // A-load mapping: thread handles float4 slots f=tid and f=tid+512
    // slot f: m = f>>3, k4 = (f&7)*4 within 32-wide chunk
    int mA0 = tid >> 3, mA1 = (tid + 512) >> 3;
    int k4  = (tid & 7) * 4;
    int node0, node1;
    {
        int g0 = row0 + mA0, g1 = row0 + mA1;
        int s0 = (g0 < M) ? g0 : (M - 1);
        int s1 = (g1 < M) ? g1 : (M - 1);
        node0 = items ? ((s0 < BATCH) ? items[s0] : (items[s0 - BATCH] + NITEM)) : s0;
        node1 = items ? ((s1 < BATCH) ? items[s1] : (items[s1 - BATCH] + NITEM)) : s1;
    }
    // B-load mapping: n = tid>>2, kq = (tid&3)*8 halves
    int nB = tid >> 2, kqB = (tid & 3) * 8;

    float acc[2][4][4];
    #pragma unroll
    for (int mt = 0; mt < 2; mt++)
        #pragma unroll
        for (int nt = 0; nt < 4; nt++)
            #pragma unroll
            for (int q = 0; q < 4; q++) acc[mt][nt][q] = 0.f;

    // prefetch registers
    float  pa[2][4];     // two float4 A values
    uint4  pbh, pbl;     // B hi/lo

    auto prefetch = [&](int c) {
        int seg = c >> 4;
        int kloc = (c & 15) * 32;
        size_t off0 = (size_t)node0 * EMB + kloc + k4;
        size_t off1 = (size_t)node1 * EMB + kloc + k4;
        if (seg == 0) {
            *(float4*)pa[0] = *(const float4*)(g_side + off0);
            *(float4*)pa[1] = *(const float4*)(g_side + off1);
        } else if (seg == 1) {
            *(float4*)pa[0] = *(const float4*)(g_edis + off0);
            *(float4*)pa[1] = *(const float4*)(g_edis + off1);
        } else {
            float4 s0 = *(const float4*)(g_side + off0);
            float4 d0 = *(const float4*)(g_edis + off0);
            float4 e0 = *(const float4*)(ego   + off0);
            float4 o0 = *(const float4*)(g_oge + off0);
            pa[0][0] = fmaf(e0.x, s0.x, o0.x * d0.x);
            pa[0][1] = fmaf(e0.y, s0.y, o0.y * d0.y);
            pa[0][2] = fmaf(e0.z, s0.z, o0.z * d0.z);
            pa[0][3] = fmaf(e0.w, s0.w, o0.w * d0.w);
            float4 s1 = *(const float4*)(g_side + off1);
            float4 d1 = *(const float4*)(g_edis + off1);
            float4 e1 = *(const float4*)(ego   + off1);
            float4 o1 = *(const float4*)(g_oge + off1);
            pa[1][0] = fmaf(e1.x, s1.x, o1.x * d1.x);
            pa[1][1] = fmaf(e1.y, s1.y, o1.y * d1.y);
            pa[1][2] = fmaf(e1.z, s1.z, o1.z * d1.z);
            pa[1][3] = fmaf(e1.w, s1.w, o1.w * d1.w);
        }
        pbh = *(const uint4*)(g_wthi + (size_t)(col0 + nB) * 1536 + c * 32 + kqB);
        pbl = *(const uint4*)(g_wtlo + (size_t)(col0 + nB) * 1536 + c * 32 + kqB);
    };

    auto store_stage = [&]() {
        // A: two rows, 4 halves each at (m, k4)
        #pragma unroll
        for (int l = 0; l < 2; l++) {
            int m = l ? mA1 : mA0;
            uint32_t ad = m * STRB + k4 * 2;
            uint32_t h0 = pack2(__float2bfloat16_rn(pa[l][0]), __float2bfloat16_rn(pa[l][1]));
            uint32_t h1 = pack2(__float2bfloat16_rn(pa[l][2]), __float2bfloat16_rn(pa[l][3]));
            uint32_t l0 = pack2(__float2bfloat16_rn(pa[l][0] - __bfloat162float(__float2bfloat16_rn(pa[l][0]))),
                                __float2bfloat16_rn(pa[l][1] - __bfloat162float(__float2bfloat16_rn(pa[l][1]))));
            uint32_t l1 = pack2(__float2bfloat16_rn(pa[l][2] - __bfloat162float(__float2bfloat16_rn(pa[l][2]))),
                                __float2bfloat16_rn(pa[l][3] - __bfloat162float(__float2bfloat16_rn(pa[l][3]))));
            asm volatile("st.shared.v2.b32 [%0], {%1,%2};" :: "r"(smb + OA_HI + ad), "r"(h0), "r"(h1) : "memory");
            asm volatile("st.shared.v2.b32 [%0], {%1,%2};" :: "r"(smb + OA_LO + ad), "r"(l0), "r"(l1) : "memory");
        }
        // B: 8 halves at (n, kq)
        uint32_t bd = nB * STRB + kqB * 2;
        asm volatile("st.shared.v4.b32 [%0], {%1,%2,%3,%4};"
                     :: "r"(smb + OB_HI + bd), "r"(pbh.x), "r"(pbh.y), "r"(pbh.z), "r"(pbh.w) : "memory");
        asm volatile("st.shared.v4.b32 [%0], {%1,%2,%3,%4};"
                     :: "r"(smb + OB_LO + bd), "r"(pbl.x), "r"(pbl.y), "r"(pbl.z), "r"(pbl.w) : "memory");
    };

    prefetch(0);
    store_stage();
    __syncthreads();

    // precomputed ldmatrix lane addresses (byte offsets within a stage)
    uint32_t aRowOff = (uint32_t)((wM * 32 + (lid & 15)) * STRB + (lid >> 4) * 16);
    uint32_t bRowOff0 = (uint32_t)((wN * 32 + (lid & 7) + ((lid >> 4) << 3)) * STRB + (((lid >> 3) & 1) << 4));
    uint32_t bRowOff1 = bRowOff0 + 16 * STRB;

    for (int c = 0; c < NCH; c++) {
        if (c + 1 < NCH) prefetch(c + 1);

        #pragma unroll
        for (int kk = 0; kk < 2; kk++) {
            uint32_t ko = kk * 32;  // byte offset for k half-step
            uint32_t ah[2][4], al[2][4], bh[8], bl[8];
            LDSM4(ah[0][0], ah[0][1], ah[0][2], ah[0][3], smb + OA_HI + aRowOff + ko);
            LDSM4(ah[1][0], ah[1][1], ah[1][2], ah[1][3], smb + OA_HI + aRowOff + 16 * STRB + ko);
            LDSM4(al[0][0], al[0][1], al[0][2], al[0][3], smb + OA_LO + aRowOff + ko);
            LDSM4(al[1][0], al[1][1], al[1][2], al[1][3], smb + OA_LO + aRowOff + 16 * STRB + ko);
            LDSM4(bh[0], bh[1], bh[2], bh[3], smb + OB_HI + bRowOff0 + ko);
            LDSM4(bh[4], bh[5], bh[6], bh[7], smb + OB_HI + bRowOff1 + ko);
            LDSM4(bl[0], bl[1], bl[2], bl[3], smb + OB_LO + bRowOff0 + ko);
            LDSM4(bl[4], bl[5], bl[6], bl[7], smb + OB_LO + bRowOff1 + ko);
            #pragma unroll
            for (int mt = 0; mt < 2; mt++)
                #pragma unroll
                for (int nt = 0; nt < 4; nt++) {
                    MMA16816(acc[mt][nt], ah[mt], (bh + nt * 2));
                    MMA16816(acc[mt][nt], ah[mt], (bl + nt * 2));
                    MMA16816(acc[mt][nt], al[mt], (bh + nt * 2));
                }
        }
        __syncthreads();
        if (c + 1 < NCH) { store_stage(); }
        __syncthreads();
    }

    // ---- epilogue: bias + leaky_relu, write fp32 ----
    int rA = lid >> 2;            // 0..7
    int cA = (lid & 3) * 2;       // 0,2,4,6
    #pragma unroll
    for (int mt = 0; mt < 2; mt++) {
        #pragma unroll
        for (int half = 0; half < 2; half++) {
            int gr = row0 + wM * 32 + mt * 16 + rA + half * 8;
            if (gr < M) {
                float* cp = Cout + (size_t)gr * EMB + col0 + wN * 32;
                #pragma unroll
                for (int nt = 0; nt < 4; nt++) {
                    int cc = nt * 8 + cA;
                    float x0 = acc[mt][nt][half * 2 + 0] + biasP[wN * 32 + cc];
                    float x1 = acc[mt][nt][half * 2 + 1] + biasP[wN * 32 + cc + 1];
                    float2 o;
                    o.x = (x0 > 0.f) ? x0 : 0.2f * x0;
                    o.y = (x1 > 0.f) ? x1 : 0.2f * x1;
                    *(float2*)(cp + cc) = o;
                }
            }
        }
    }
}

// ---------------- out[slot] = ego0[node]  (acc init) ----------------
__global__ void k_out_init(const int* __restrict__ items, float* __restrict__ out)
{
    int slot = blockIdx.x;
    int node = (slot < BATCH) ? items[slot] : (items[slot - BATCH] + NITEM);
    int t = threadIdx.x;
    float4 x = *(const float4*)(g_egoA + (size_t)node * EMB + t * 4);
    *(float4*)(out + (size_t)slot * EMB + t * 4) = x;
}

// ---------------- out[slot] += normalize(src_row) ----------------
__global__ void k_norm_acc(int srcSel, const int* __restrict__ items, float* __restrict__ out)
{
    int slot = blockIdx.x;
    int node = (slot < BATCH) ? items[slot] : (items[slot - BATCH] + NITEM);
    const float* row;
    if (srcSel == 0)      row = g_egoA + (size_t)node * EMB;
    else if (srcSel == 1) row = g_egoB + (size_t)node * EMB;
    else                  row = g_ego3 + (size_t)slot * EMB;

    int t = threadIdx.x;  // 128 threads, 4 floats each
    float4 x = *(const float4*)(row + t * 4);
    float ss = x.x * x.x + x.y * x.y + x.z * x.z + x.w * x.w;
    #pragma unroll
    for (int o = 16; o; o >>= 1) ss += __shfl_xor_sync(0xffffffffu, ss, o);
    __shared__ float ws[4];
    if ((t & 31) == 0) ws[t >> 5] = ss;
    __syncthreads();
    float tot = ws[0] + ws[1] + ws[2] + ws[3];
    float inv = 1.f / fmaxf(sqrtf(tot), 1e-12f);

    float* o4 = out + (size_t)slot * EMB + t * 4;
    float4 cur = *(float4*)o4;
    cur.x += x.x * inv; cur.y += x.y * inv; cur.z += x.z * inv; cur.w += x.w * inv;
    *(float4*)o4 = cur;
}

// ---------------- launch ----------------
extern "C" void kernel_launch(void* const* d_in, const int* in_sizes, int n_in,
                              void* d_out, int out_size)
{
    const float* vis   = (const float*)d_in[0];
    const float* txt   = (const float*)d_in[1];
    const int*   er    = (const int*)  d_in[2];
    const int*   ec    = (const int*)  d_in[3];
    const float* ev    = (const float*)d_in[4];
    const int*   items = (const int*)  d_in[5];
    const float* Wgc   = (const float*)d_in[6];
    const float* bgc   = (const float*)d_in[7];
    const float* Wgc2  = (const float*)d_in[8];
    const float* bgc2  = (const float*)d_in[9];
    const float* Wbi   = (const float*)d_in[10];
    const float* bbi   = (const float*)d_in[11];
    float* out = (float*)d_out;
    int nnz = in_sizes[2];

    const int ZB = 50000;
    const int SPMM_B = 4096;
    dim3 gGrid(4, (NNODES + 127) / 128);   // (4, 782)
    dim3 gGrid3(4, NSLOT / 128);           // (4, 64)
    dim3 wGrid(48, 16);

    // init ego0 / oge ; zero edis ; flags
    k_init<<<25000, 256>>>(vis, txt);
    k_zero<<<ZB, 256>>>(1);
    k_zero<<<391, 256>>>(2);
    k_setflag<<<16, 256>>>(items);

    // edis = spmm(oge)  (fixed across layers)
    k_spmm<<<SPMM_B, 256>>>(2, 1, er, ec, ev, nnz, 0,      NITEM,  0);
    k_spmm<<<SPMM_B, 256>>>(2, 1, er, ec, ev, nnz, NITEM,  NNODES, 0);

    // acc init
    k_out_init<<<NSLOT, 128>>>(items, out);

    // ---- layer 0: ego0(A) -> ego1(B) ----
    k_zero<<<ZB, 256>>>(0);
    k_spmm<<<SPMM_B, 256>>>(0, 0, er, ec, ev, nnz, 0,     NITEM,  0);
    k_spmm<<<SPMM_B, 256>>>(0, 0, er, ec, ev, nnz, NITEM, NNODES, 0);
    k_wtconv<<<wGrid, 256>>>(Wgc, Wgc2, Wbi);
    k_gemm<<<gGrid, 512>>>(0, 0, bgc, bgc2, bbi, NNODES, nullptr);
    k_norm_acc<<<NSLOT, 128>>>(1, items, out);

    // ---- layer 1: ego1(B) -> ego2(A) ----
    k_zero<<<ZB, 256>>>(0);
    k_spmm<<<SPMM_B, 256>>>(1, 0, er, ec, ev, nnz, 0,     NITEM,  0);
    k_spmm<<<SPMM_B, 256>>>(1, 0, er, ec, ev, nnz, NITEM, NNODES, 0);
    k_wtconv<<<wGrid, 256>>>(Wgc + 1 * 512 * 512, Wgc2 + 1 * 512 * 512, Wbi + 1 * 512 * 512);
    k_gemm<<<gGrid, 512>>>(1, 1, bgc + 512, bgc2 + 512, bbi + 512, NNODES, nullptr);
    k_norm_acc<<<NSLOT, 128>>>(0, items, out);

    // ---- layer 2 (subset): ego2(A) -> g_ego3 (gathered slots) ----
    k_zero<<<ZB, 256>>>(0);
    k_spmm<<<SPMM_B, 256>>>(0, 0, er, ec, ev, nnz, 0, NNODES, 1);
    k_wtconv<<<wGrid, 256>>>(Wgc + 2 * 512 * 512, Wgc2 + 2 * 512 * 512, Wbi + 2 * 512 * 512);
    k_gemm<<<gGrid3, 512>>>(0, 2, bgc + 1024, bgc2 + 1024, bbi + 1024, NSLOT, items);
    k_norm_acc<<<NSLOT, 128>>>(2, items, out);
}

// round 4
// speedup vs baseline: 1.7716x; 1.2069x over previous
#include <cuda_runtime.h>
#include <cuda_bf16.h>
#include <math.h>
#include <stdint.h>

#define NITEM   50000
#define NNODES  100000
#define EMB     512
#define BATCH   4096
#define NSLOT   8192
#define NNZMAX  3200000
#define NCH     48          // 1536 / 32 K-chunks
#define STRB    80          // smem row stride bytes (40 halves)
#define STAGE_SZ 61440      // A hi/lo 20KB + B hi/lo 40KB
#define GEMM_SMEM 123904    // 2 stages + 1KB bias

// ---------------- static device scratch ----------------
__device__ float g_egoA[51200000];   // 100000 x 512
__device__ float g_egoB[51200000];
__device__ float g_oge [51200000];
__device__ float g_edis[51200000];
__device__ float g_side[51200000];
__device__ float g_ego3[4194304];    // 8192 x 512
__device__ int   g_flag[NNODES];
__device__ int   g_rowptr[NNODES + 1];
__device__ int   g_ofs[NNODES];
__device__ int   g_scol[NNZMAX];
__device__ float g_sval[NNZMAX];
__device__ __nv_bfloat16 g_wthi[512 * 1536];  // W^T hi, [N][K] K-contig
__device__ __nv_bfloat16 g_wtlo[512 * 1536];  // W^T lo

__device__ __forceinline__ uint32_t smem_u32(const void* p) {
    uint32_t a;
    asm("{ .reg .u64 t; cvta.to.shared.u64 t, %1; cvt.u32.u64 %0, t; }" : "=r"(a) : "l"(p));
    return a;
}
#define LDSM4(r0,r1,r2,r3,addr) \
    asm volatile("ldmatrix.sync.aligned.m8n8.x4.shared.b16 {%0,%1,%2,%3}, [%4];" \
                 : "=r"(r0),"=r"(r1),"=r"(r2),"=r"(r3) : "r"(addr))
#define MMA16816(d,a,b) \
    asm volatile("mma.sync.aligned.m16n8k16.row.col.f32.bf16.bf16.f32 " \
                 "{%0,%1,%2,%3}, {%4,%5,%6,%7}, {%8,%9}, {%0,%1,%2,%3};" \
                 : "+f"(d[0]),"+f"(d[1]),"+f"(d[2]),"+f"(d[3]) \
                 : "r"(a[0]),"r"(a[1]),"r"(a[2]),"r"(a[3]), "r"(b[0]),"r"(b[1]))

__device__ __forceinline__ uint32_t pack2(__nv_bfloat16 a, __nv_bfloat16 b) {
    __nv_bfloat162 p = __halves2bfloat162(a, b);
    return *reinterpret_cast<uint32_t*>(&p);
}

// ---------------- init: ego0 = [vision;text], oge = [text;vision] ----------------
__global__ void k_init(const float* __restrict__ vis, const float* __restrict__ txt)
{
    size_t i = (size_t)blockIdx.x * blockDim.x + threadIdx.x;
    size_t half = (size_t)NITEM * EMB / 4;
    if (i >= half) return;
    float4 v = ((const float4*)vis)[i];
    float4 t = ((const float4*)txt)[i];
    ((float4*)g_egoA)[i]        = v;
    ((float4*)g_egoA)[half + i] = t;
    ((float4*)g_oge)[i]         = t;
    ((float4*)g_oge)[half + i]  = v;
}

// zero per-row counters + flags
__global__ void k_zero2()
{
    int i = blockIdx.x * blockDim.x + threadIdx.x;
    if (i < NNODES) { g_ofs[i] = 0; g_flag[i] = 0; }
}

__global__ void k_setflag(const int* __restrict__ items)
{
    int j = blockIdx.x * blockDim.x + threadIdx.x;
    if (j < BATCH) {
        int it = items[j];
        g_flag[it] = 1;
        g_flag[it + NITEM] = 1;
    }
}

// ---------------- CSR build ----------------
__global__ void k_hist(const int* __restrict__ er, int nnz)
{
    int i = blockIdx.x * blockDim.x + threadIdx.x;
    int stride = gridDim.x * blockDim.x;
    for (int e = i; e < nnz; e += stride)
        atomicAdd(&g_ofs[er[e]], 1);
}

__global__ void k_scan()
{
    __shared__ int part[1024];
    int t = threadIdx.x;
    const int CH = (NNODES + 1023) / 1024;   // 98
    int base = t * CH;
    int s = 0;
    for (int i = 0; i < CH; i++) {
        int idx = base + i;
        if (idx < NNODES) s += g_ofs[idx];
    }
    part[t] = s;
    __syncthreads();
    #pragma unroll
    for (int off = 1; off < 1024; off <<= 1) {
        int add = (t >= off) ? part[t - off] : 0;
        __syncthreads();
        part[t] += add;
        __syncthreads();
    }
    int running = part[t] - s;   // exclusive prefix
    for (int i = 0; i < CH; i++) {
        int idx = base + i;
        if (idx < NNODES) {
            int cnt = g_ofs[idx];
            g_rowptr[idx] = running;
            g_ofs[idx] = running;
            running += cnt;
        }
    }
    if (t == 1023) g_rowptr[NNODES] = part[1023];
}

__global__ void k_scatter(const int* __restrict__ er, const int* __restrict__ ec,
                          const float* __restrict__ ev, int nnz)
{
    int i = blockIdx.x * blockDim.x + threadIdx.x;
    int stride = gridDim.x * blockDim.x;
    for (int e = i; e < nnz; e += stride) {
        int r = er[e];
        int pos = atomicAdd(&g_ofs[r], 1);
        g_scol[pos] = ec[e];
        g_sval[pos] = ev[e];
    }
}

// ---------------- CSR SpMM: warp per row, register accumulate, single store ----------------
__global__ void k_spmm_csr(int srcSel, int dstSel, int useFlag)
{
    const float* x = (srcSel == 0) ? g_egoA : (srcSel == 1) ? g_egoB : g_oge;
    float* outp = (dstSel == 0) ? g_side : g_edis;
    int lane = threadIdx.x & 31;
    int warp = (int)((blockIdx.x * blockDim.x + threadIdx.x) >> 5);
    int nw   = (int)((gridDim.x * blockDim.x) >> 5);

    for (int row = warp; row < NNODES; row += nw) {
        if (useFlag && !g_flag[row]) continue;
        int s = g_rowptr[row], e = g_rowptr[row + 1];
        float4 acc0 = make_float4(0.f, 0.f, 0.f, 0.f);
        float4 acc1 = acc0, acc2 = acc0, acc3 = acc0;
        int i = s;
        for (; i + 1 < e; i += 2) {
            int   c0 = g_scol[i],     c1 = g_scol[i + 1];
            float v0 = g_sval[i],     v1 = g_sval[i + 1];
            const float4* xa = (const float4*)(x + (size_t)c0 * EMB);
            const float4* xb = (const float4*)(x + (size_t)c1 * EMB);
            float4 a0 = xa[lane], a1 = xa[lane + 32], a2 = xa[lane + 64], a3 = xa[lane + 96];
            float4 b0 = xb[lane], b1 = xb[lane + 32], b2 = xb[lane + 64], b3 = xb[lane + 96];
            acc0.x = fmaf(a0.x, v0, acc0.x); acc0.y = fmaf(a0.y, v0, acc0.y);
            acc0.z = fmaf(a0.z, v0, acc0.z); acc0.w = fmaf(a0.w, v0, acc0.w);
            acc1.x = fmaf(a1.x, v0, acc1.x); acc1.y = fmaf(a1.y, v0, acc1.y);
            acc1.z = fmaf(a1.z, v0, acc1.z); acc1.w = fmaf(a1.w, v0, acc1.w);
            acc2.x = fmaf(a2.x, v0, acc2.x); acc2.y = fmaf(a2.y, v0, acc2.y);
            acc2.z = fmaf(a2.z, v0, acc2.z); acc2.w = fmaf(a2.w, v0, acc2.w);
            acc3.x = fmaf(a3.x, v0, acc3.x); acc3.y = fmaf(a3.y, v0, acc3.y);
            acc3.z = fmaf(a3.z, v0, acc3.z); acc3.w = fmaf(a3.w, v0, acc3.w);
            acc0.x = fmaf(b0.x, v1, acc0.x); acc0.y = fmaf(b0.y, v1, acc0.y);
            acc0.z = fmaf(b0.z, v1, acc0.z); acc0.w = fmaf(b0.w, v1, acc0.w);
            acc1.x = fmaf(b1.x, v1, acc1.x); acc1.y = fmaf(b1.y, v1, acc1.y);
            acc1.z = fmaf(b1.z, v1, acc1.z); acc1.w = fmaf(b1.w, v1, acc1.w);
            acc2.x = fmaf(b2.x, v1, acc2.x); acc2.y = fmaf(b2.y, v1, acc2.y);
            acc2.z = fmaf(b2.z, v1, acc2.z); acc2.w = fmaf(b2.w, v1, acc2.w);
            acc3.x = fmaf(b3.x, v1, acc3.x); acc3.y = fmaf(b3.y, v1, acc3.y);
            acc3.z = fmaf(b3.z, v1, acc3.z); acc3.w = fmaf(b3.w, v1, acc3.w);
        }
        if (i < e) {
            int   c0 = g_scol[i];
            float v0 = g_sval[i];
            const float4* xa = (const float4*)(x + (size_t)c0 * EMB);
            float4 a0 = xa[lane], a1 = xa[lane + 32], a2 = xa[lane + 64], a3 = xa[lane + 96];
            acc0.x = fmaf(a0.x, v0, acc0.x); acc0.y = fmaf(a0.y, v0, acc0.y);
            acc0.z = fmaf(a0.z, v0, acc0.z); acc0.w = fmaf(a0.w, v0, acc0.w);
            acc1.x = fmaf(a1.x, v0, acc1.x); acc1.y = fmaf(a1.y, v0, acc1.y);
            acc1.z = fmaf(a1.z, v0, acc1.z); acc1.w = fmaf(a1.w, v0, acc1.w);
            acc2.x = fmaf(a2.x, v0, acc2.x); acc2.y = fmaf(a2.y, v0, acc2.y);
            acc2.z = fmaf(a2.z, v0, acc2.z); acc2.w = fmaf(a2.w, v0, acc2.w);
            acc3.x = fmaf(a3.x, v0, acc3.x); acc3.y = fmaf(a3.y, v0, acc3.y);
            acc3.z = fmaf(a3.z, v0, acc3.z); acc3.w = fmaf(a3.w, v0, acc3.w);
        }
        float4* o = (float4*)(outp + (size_t)row * EMB);
        o[lane] = acc0; o[lane + 32] = acc1; o[lane + 64] = acc2; o[lane + 96] = acc3;
    }
}

// ---------------- weight transpose + bf16 hi/lo split ----------------
__global__ void k_wtconv(const float* __restrict__ Wgc, const float* __restrict__ Wgc2,
                         const float* __restrict__ Wbi)
{
    __shared__ float t[32][33];
    int kb = blockIdx.x * 32;
    int nb = blockIdx.y * 32;
    int tx = threadIdx.x & 31, ty = threadIdx.x >> 5;
    int seg = kb >> 9, kloc = kb & 511;
    const float* W = (seg == 0) ? Wgc : (seg == 1) ? Wgc2 : Wbi;
    #pragma unroll
    for (int j = 0; j < 4; j++)
        t[ty + 8 * j][tx] = W[(size_t)(kloc + ty + 8 * j) * 512 + nb + tx];
    __syncthreads();
    #pragma unroll
    for (int j = 0; j < 4; j++) {
        int n = nb + ty + 8 * j;
        float x = t[tx][ty + 8 * j];
        __nv_bfloat16 h = __float2bfloat16_rn(x);
        g_wthi[(size_t)n * 1536 + kb + tx] = h;
        g_wtlo[(size_t)n * 1536 + kb + tx] = __float2bfloat16_rn(x - __bfloat162float(h));
    }
}

// ---------------- mma.sync bf16x3 fused GEMM, tile 128x256, double-buffered ----------------
__global__ void __launch_bounds__(512)
k_gemm(int egoSel, int outSel,
       const float* __restrict__ bgc, const float* __restrict__ bgc2,
       const float* __restrict__ bbi,
       int M, const int* __restrict__ items)
{
    extern __shared__ __align__(16) char smbuf[];
    const uint32_t OA_HI = 0, OA_LO = 10240, OB_HI = 20480, OB_LO = 40960;
    float* biasP = (float*)(smbuf + 2 * STAGE_SZ);
    uint32_t smb = smem_u32(smbuf);

    int tid = threadIdx.x;
    int wid = tid >> 5, lid = tid & 31;
    int col0 = blockIdx.x * 256;
    int row0 = blockIdx.y * 128;
    int wM = wid >> 2, wN = wid & 3;   // 4x4 warps; warp tile 32x64

    if (tid < 256) {
        int c = col0 + tid;
        biasP[tid] = bgc[c] + bgc2[c] + bbi[c];
    }

    const float* ego = egoSel ? g_egoB : g_egoA;
    float* Cout = (outSel == 0) ? g_egoB : (outSel == 1) ? g_egoA : g_ego3;

    // A-load: slots tid, tid+512 -> (m = s>>3, k4 = (s&7)*4)
    int mA0 = tid >> 3, mA1 = (tid + 512) >> 3;
    int k4  = (tid & 7) * 4;
    int node0, node1;
    {
        int g0 = row0 + mA0, g1 = row0 + mA1;
        int s0 = (g0 < M) ? g0 : (M - 1);
        int s1 = (g1 < M) ? g1 : (M - 1);
        node0 = items ? ((s0 < BATCH) ? items[s0] : (items[s0 - BATCH] + NITEM)) : s0;
        node1 = items ? ((s1 < BATCH) ? items[s1] : (items[s1 - BATCH] + NITEM)) : s1;
    }
    // B-load: n = tid>>1 (0..255), kq = (tid&1)*16 halves; 2 uint4 each for hi/lo
    int nB = tid >> 1, kqB = (tid & 1) * 16;

    float acc[2][8][4];
    #pragma unroll
    for (int mt = 0; mt < 2; mt++)
        #pragma unroll
        for (int nt = 0; nt < 8; nt++)
            #pragma unroll
            for (int q = 0; q < 4; q++) acc[mt][nt][q] = 0.f;

    float pa[2][4];
    uint4 pbh[2], pbl[2];

    auto prefetch = [&](int c) {
        int seg = c >> 4;
        int kloc = (c & 15) * 32;
        size_t off0 = (size_t)node0 * EMB + kloc + k4;
        size_t off1 = (size_t)node1 * EMB + kloc + k4;
        if (seg == 0) {
            *(float4*)pa[0] = *(const float4*)(g_side + off0);
            *(float4*)pa[1] = *(const float4*)(g_side + off1);
        } else if (seg == 1) {
            *(float4*)pa[0] = *(const float4*)(g_edis + off0);
            *(float4*)pa[1] = *(const float4*)(g_edis + off1);
        } else {
            float4 s0 = *(const float4*)(g_side + off0);
            float4 d0 = *(const float4*)(g_edis + off0);
            float4 e0 = *(const float4*)(ego   + off0);
            float4 o0 = *(const float4*)(g_oge + off0);
            pa[0][0] = fmaf(e0.x, s0.x, o0.x * d0.x);
            pa[0][1] = fmaf(e0.y, s0.y, o0.y * d0.y);
            pa[0][2] = fmaf(e0.z, s0.z, o0.z * d0.z);
            pa[0][3] = fmaf(e0.w, s0.w, o0.w * d0.w);
            float4 s1 = *(const float4*)(g_side + off1);
            float4 d1 = *(const float4*)(g_edis + off1);
            float4 e1 = *(const float4*)(ego   + off1);
            float4 o1 = *(const float4*)(g_oge + off1);
            pa[1][0] = fmaf(e1.x, s1.x, o1.x * d1.x);
            pa[1][1] = fmaf(e1.y, s1.y, o1.y * d1.y);
            pa[1][2] = fmaf(e1.z, s1.z, o1.z * d1.z);
            pa[1][3] = fmaf(e1.w, s1.w, o1.w * d1.w);
        }
        const __nv_bfloat16* bh = g_wthi + (size_t)(col0 + nB) * 1536 + c * 32 + kqB;
        const __nv_bfloat16* bl = g_wtlo + (size_t)(col0 + nB) * 1536 + c * 32 + kqB;
        pbh[0] = ((const uint4*)bh)[0]; pbh[1] = ((const uint4*)bh)[1];
        pbl[0] = ((const uint4*)bl)[0]; pbl[1] = ((const uint4*)bl)[1];
    };

    auto store_stage = [&](int stage) {
        uint32_t base = smb + stage * STAGE_SZ;
        #pragma unroll
        for (int l = 0; l < 2; l++) {
            int m = l ? mA1 : mA0;
            uint32_t ad = m * STRB + k4 * 2;
            uint32_t h0 = pack2(__float2bfloat16_rn(pa[l][0]), __float2bfloat16_rn(pa[l][1]));
            uint32_t h1 = pack2(__float2bfloat16_rn(pa[l][2]), __float2bfloat16_rn(pa[l][3]));
            uint32_t l0 = pack2(__float2bfloat16_rn(pa[l][0] - __bfloat162float(__float2bfloat16_rn(pa[l][0]))),
                                __float2bfloat16_rn(pa[l][1] - __bfloat162float(__float2bfloat16_rn(pa[l][1]))));
            uint32_t l1 = pack2(__float2bfloat16_rn(pa[l][2] - __bfloat162float(__float2bfloat16_rn(pa[l][2]))),
                                __float2bfloat16_rn(pa[l][3] - __bfloat162float(__float2bfloat16_rn(pa[l][3]))));
            asm volatile("st.shared.v2.b32 [%0], {%1,%2};" :: "r"(base + OA_HI + ad), "r"(h0), "r"(h1) : "memory");
            asm volatile("st.shared.v2.b32 [%0], {%1,%2};" :: "r"(base + OA_LO + ad), "r"(l0), "r"(l1) : "memory");
        }
        uint32_t bd = nB * STRB + kqB * 2;
        asm volatile("st.shared.v4.b32 [%0], {%1,%2,%3,%4};"
                     :: "r"(base + OB_HI + bd), "r"(pbh[0].x), "r"(pbh[0].y), "r"(pbh[0].z), "r"(pbh[0].w) : "memory");
        asm volatile("st.shared.v4.b32 [%0], {%1,%2,%3,%4};"
                     :: "r"(base + OB_HI + bd + 16), "r"(pbh[1].x), "r"(pbh[1].y), "r"(pbh[1].z), "r"(pbh[1].w) : "memory");
        asm volatile("st.shared.v4.b32 [%0], {%1,%2,%3,%4};"
                     :: "r"(base + OB_LO + bd), "r"(pbl[0].x), "r"(pbl[0].y), "r"(pbl[0].z), "r"(pbl[0].w) : "memory");
        asm volatile("st.shared.v4.b32 [%0], {%1,%2,%3,%4};"
                     :: "r"(base + OB_LO + bd + 16), "r"(pbl[1].x), "r"(pbl[1].y), "r"(pbl[1].z), "r"(pbl[1].w) : "memory");
    };

    // ldmatrix lane offsets
    uint32_t aOff = (uint32_t)((wM * 32 + (lid & 15)) * STRB + (lid >> 4) * 16);
    uint32_t bOff[4];
    #pragma unroll
    for (int p = 0; p < 4; p++)
        bOff[p] = (uint32_t)((wN * 64 + p * 16 + (lid & 7) + ((lid >> 4) << 3)) * STRB + (((lid >> 3) & 1) << 4));

    prefetch(0);
    store_stage(0);
    __syncthreads();
    prefetch(1);

    for (int c = 0; c < NCH; c++) {
        uint32_t sb = smb + (c & 1) * STAGE_SZ;
        #pragma unroll
        for (int kk = 0; kk < 2; kk++) {
            uint32_t ko = kk * 32;
            uint32_t ah[2][4], al[2][4];
            LDSM4(ah[0][0], ah[0][1], ah[0][2], ah[0][3], sb + OA_HI + aOff + ko);
            LDSM4(ah[1][0], ah[1][1], ah[1][2], ah[1][3], sb + OA_HI + aOff + 16 * STRB + ko);
            LDSM4(al[0][0], al[0][1], al[0][2], al[0][3], sb + OA_LO + aOff + ko);
            LDSM4(al[1][0], al[1][1], al[1][2], al[1][3], sb + OA_LO + aOff + 16 * STRB + ko);
            #pragma unroll
            for (int p = 0; p < 4; p++) {
                uint32_t bh4[4], bl4[4];
                LDSM4(bh4[0], bh4[1], bh4[2], bh4[3], sb + OB_HI + bOff[p] + ko);
                LDSM4(bl4[0], bl4[1], bl4[2], bl4[3], sb + OB_LO + bOff[p] + ko);
                #pragma unroll
                for (int mt = 0; mt < 2; mt++) {
                    MMA16816(acc[mt][2 * p],     ah[mt], (bh4 + 0));
                    MMA16816(acc[mt][2 * p + 1], ah[mt], (bh4 + 2));
                    MMA16816(acc[mt][2 * p],     ah[mt], (bl4 + 0));
                    MMA16816(acc[mt][2 * p + 1], ah[mt], (bl4 + 2));
                    MMA16816(acc[mt][2 * p],     al[mt], (bh4 + 0));
                    MMA16816(acc[mt][2 * p + 1], al[mt], (bh4 + 2));
                }
            }
        }
        if (c + 1 < NCH) {
            store_stage((c + 1) & 1);
            if (c + 2 < NCH) prefetch(c + 2);
            __syncthreads();
        }
    }

    // ---- epilogue: bias + leaky_relu ----
    int rA = lid >> 2;
    int cA = (lid & 3) * 2;
    #pragma unroll
    for (int mt = 0; mt < 2; mt++) {
        #pragma unroll
        for (int half = 0; half < 2; half++) {
            int gr = row0 + wM * 32 + mt * 16 + rA + half * 8;
            if (gr < M) {
                float* cp = Cout + (size_t)gr * EMB + col0 + wN * 64;
                #pragma unroll
                for (int nt = 0; nt < 8; nt++) {
                    int cc = nt * 8 + cA;
                    float x0 = acc[mt][nt][half * 2 + 0] + biasP[wN * 64 + cc];
                    float x1 = acc[mt][nt][half * 2 + 1] + biasP[wN * 64 + cc + 1];
                    float2 o;
                    o.x = (x0 > 0.f) ? x0 : 0.2f * x0;
                    o.y = (x1 > 0.f) ? x1 : 0.2f * x1;
                    *(float2*)(cp + cc) = o;
                }
            }
        }
    }
}

// ---------------- out[slot] = ego0[node]  (acc init) ----------------
__global__ void k_out_init(const int* __restrict__ items, float* __restrict__ out)
{
    int slot = blockIdx.x;
    int node = (slot < BATCH) ? items[slot] : (items[slot - BATCH] + NITEM);
    int t = threadIdx.x;
    float4 x = *(const float4*)(g_egoA + (size_t)node * EMB + t * 4);
    *(float4*)(out + (size_t)slot * EMB + t * 4) = x;
}

// ---------------- out[slot] += normalize(src_row) ----------------
__global__ void k_norm_acc(int srcSel, const int* __restrict__ items, float* __restrict__ out)
{
    int slot = blockIdx.x;
    int node = (slot < BATCH) ? items[slot] : (items[slot - BATCH] + NITEM);
    const float* row;
    if (srcSel == 0)      row = g_egoA + (size_t)node * EMB;
    else if (srcSel == 1) row = g_egoB + (size_t)node * EMB;
    else                  row = g_ego3 + (size_t)slot * EMB;

    int t = threadIdx.x;  // 128 threads
    float4 x = *(const float4*)(row + t * 4);
    float ss = x.x * x.x + x.y * x.y + x.z * x.z + x.w * x.w;
    #pragma unroll
    for (int o = 16; o; o >>= 1) ss += __shfl_xor_sync(0xffffffffu, ss, o);
    __shared__ float ws[4];
    if ((t & 31) == 0) ws[t >> 5] = ss;
    __syncthreads();
    float tot = ws[0] + ws[1] + ws[2] + ws[3];
    float inv = 1.f / fmaxf(sqrtf(tot), 1e-12f);

    float* o4 = out + (size_t)slot * EMB + t * 4;
    float4 cur = *(float4*)o4;
    cur.x += x.x * inv; cur.y += x.y * inv; cur.z += x.z * inv; cur.w += x.w * inv;
    *(float4*)o4 = cur;
}

// ---------------- launch ----------------
extern "C" void kernel_launch(void* const* d_in, const int* in_sizes, int n_in,
                              void* d_out, int out_size)
{
    const float* vis   = (const float*)d_in[0];
    const float* txt   = (const float*)d_in[1];
    const int*   er    = (const int*)  d_in[2];
    const int*   ec    = (const int*)  d_in[3];
    const float* ev    = (const float*)d_in[4];
    const int*   items = (const int*)  d_in[5];
    const float* Wgc   = (const float*)d_in[6];
    const float* bgc   = (const float*)d_in[7];
    const float* Wgc2  = (const float*)d_in[8];
    const float* bgc2  = (const float*)d_in[9];
    const float* Wbi   = (const float*)d_in[10];
    const float* bbi   = (const float*)d_in[11];
    float* out = (float*)d_out;
    int nnz = in_sizes[2];

    cudaFuncSetAttribute(k_gemm, cudaFuncAttributeMaxDynamicSharedMemorySize, GEMM_SMEM);

    const int SPMM_B = 2048;
    dim3 gGrid(2, (NNODES + 127) / 128);   // (2, 782)
    dim3 gGrid3(2, NSLOT / 128);           // (2, 64)
    dim3 wGrid(48, 16);

    // init + CSR build
    k_init<<<25000, 256>>>(vis, txt);
    k_zero2<<<391, 256>>>();
    k_setflag<<<16, 256>>>(items);
    k_hist<<<2048, 256>>>(er, nnz);
    k_scan<<<1, 1024>>>();
    k_scatter<<<2048, 256>>>(er, ec, ev, nnz);

    // edis = spmm(oge)  (fixed across layers)
    k_spmm_csr<<<SPMM_B, 256>>>(2, 1, 0);

    // acc init
    k_out_init<<<NSLOT, 128>>>(items, out);

    // ---- layer 0: ego0(A) -> ego1(B) ----
    k_spmm_csr<<<SPMM_B, 256>>>(0, 0, 0);
    k_wtconv<<<wGrid, 256>>>(Wgc, Wgc2, Wbi);
    k_gemm<<<gGrid, 512, GEMM_SMEM>>>(0, 0, bgc, bgc2, bbi, NNODES, nullptr);
    k_norm_acc<<<NSLOT, 128>>>(1, items, out);

    // ---- layer 1: ego1(B) -> ego2(A) ----
    k_spmm_csr<<<SPMM_B, 256>>>(1, 0, 0);
    k_wtconv<<<wGrid, 256>>>(Wgc + 1 * 512 * 512, Wgc2 + 1 * 512 * 512, Wbi + 1 * 512 * 512);
    k_gemm<<<gGrid, 512, GEMM_SMEM>>>(1, 1, bgc + 512, bgc2 + 512, bbi + 512, NNODES, nullptr);
    k_norm_acc<<<NSLOT, 128>>>(0, items, out);

    // ---- layer 2 (subset): ego2(A) -> g_ego3 (gathered slots) ----
    k_spmm_csr<<<SPMM_B, 256>>>(0, 0, 1);
    k_wtconv<<<wGrid, 256>>>(Wgc + 2 * 512 * 512, Wgc2 + 2 * 512 * 512, Wbi + 2 * 512 * 512);
    k_gemm<<<gGrid3, 512, GEMM_SMEM>>>(0, 2, bgc + 1024, bgc2 + 1024, bbi + 1024, NSLOT, items);
    k_norm_acc<<<NSLOT, 128>>>(2, items, out);
}

// round 6
// speedup vs baseline: 2.8044x; 1.5830x over previous
#include <cuda_runtime.h>
#include <cuda_bf16.h>
#include <math.h>
#include <stdint.h>

#define NITEM   50000
#define NNODES  100000
#define NSEG    200000      // 2 * NNODES (row, col-half) segments
#define EMB     512
#define BATCH   4096
#define NSLOT   8192
#define NNZMAX  3200000
#define NCH     48          // 1536 / 32 K-chunks
#define STRB    80          // smem row stride bytes (40 halves)
#define STAGE_SZ 61440      // A hi/lo 20KB + B hi/lo 40KB
#define GEMM_SMEM 123904    // 2 stages + 1KB bias

// ---------------- static device scratch ----------------
__device__ float g_egoA[51200000];   // ego0 = [vision;text], preserved
__device__ float g_egoB[51200000];   // layer-1 activations
__device__ float g_egoC[51200000];   // layer-2 activations
__device__ float g_edis[51200000];
__device__ float g_side[51200000];
__device__ float g_ego3[4194304];    // 8192 x 512
__device__ int   g_rowptr[NSEG + 1];
__device__ int   g_ofs[NSEG];
__device__ int   g_scol[NNZMAX];
__device__ float g_sval[NNZMAX];
__device__ __nv_bfloat16 g_wthi[3 * 512 * 1536];  // W^T hi, [layer][N][K] K-contig
__device__ __nv_bfloat16 g_wtlo[3 * 512 * 1536];  // W^T lo

__device__ __forceinline__ uint32_t smem_u32(const void* p) {
    uint32_t a;
    asm("{ .reg .u64 t; cvta.to.shared.u64 t, %1; cvt.u32.u64 %0, t; }" : "=r"(a) : "l"(p));
    return a;
}
#define LDSM4(r0,r1,r2,r3,addr) \
    asm volatile("ldmatrix.sync.aligned.m8n8.x4.shared.b16 {%0,%1,%2,%3}, [%4];" \
                 : "=r"(r0),"=r"(r1),"=r"(r2),"=r"(r3) : "r"(addr))
#define MMA16816(d,a,b) \
    asm volatile("mma.sync.aligned.m16n8k16.row.col.f32.bf16.bf16.f32 " \
                 "{%0,%1,%2,%3}, {%4,%5,%6,%7}, {%8,%9}, {%0,%1,%2,%3};" \
                 : "+f"(d[0]),"+f"(d[1]),"+f"(d[2]),"+f"(d[3]) \
                 : "r"(a[0]),"r"(a[1]),"r"(a[2]),"r"(a[3]), "r"(b[0]),"r"(b[1]))
#define CP16(smaddr, gptr) \
    asm volatile("cp.async.ca.shared.global [%0], [%1], 16;" :: "r"(smaddr), "l"(gptr) : "memory")
#define CP_COMMIT() asm volatile("cp.async.commit_group;" ::: "memory")
#define CP_WAIT0()  asm volatile("cp.async.wait_group 0;" ::: "memory")

__device__ __forceinline__ uint32_t pack2(__nv_bfloat16 a, __nv_bfloat16 b) {
    __nv_bfloat162 p = __halves2bfloat162(a, b);
    return *reinterpret_cast<uint32_t*>(&p);
}

// ---------------- init: ego0 = [vision;text] ----------------
__global__ void k_init(const float* __restrict__ vis, const float* __restrict__ txt)
{
    size_t i = (size_t)blockIdx.x * blockDim.x + threadIdx.x;
    size_t half = (size_t)NITEM * EMB / 4;
    if (i >= half) return;
    ((float4*)g_egoA)[i]        = ((const float4*)vis)[i];
    ((float4*)g_egoA)[half + i] = ((const float4*)txt)[i];
}

__global__ void k_zero2()
{
    int i = blockIdx.x * blockDim.x + threadIdx.x;
    if (i < NSEG) g_ofs[i] = 0;
}

// ---------------- CSR build: key = 2*row + (col >= NITEM) ----------------
__global__ void k_hist(const int* __restrict__ er, const int* __restrict__ ec, int nnz)
{
    int i = blockIdx.x * blockDim.x + threadIdx.x;
    int stride = gridDim.x * blockDim.x;
    for (int e = i; e < nnz; e += stride)
        atomicAdd(&g_ofs[2 * er[e] + (ec[e] >= NITEM)], 1);
}

__global__ void k_scan()
{
    __shared__ int part[1024];
    int t = threadIdx.x;
    const int CH = (NSEG + 1023) / 1024;   // 196
    int base = t * CH;
    int s = 0;
    for (int i = 0; i < CH; i++) {
        int idx = base + i;
        if (idx < NSEG) s += g_ofs[idx];
    }
    part[t] = s;
    __syncthreads();
    #pragma unroll
    for (int off = 1; off < 1024; off <<= 1) {
        int add = (t >= off) ? part[t - off] : 0;
        __syncthreads();
        part[t] += add;
        __syncthreads();
    }
    int running = part[t] - s;   // exclusive prefix
    for (int i = 0; i < CH; i++) {
        int idx = base + i;
        if (idx < NSEG) {
            int cnt = g_ofs[idx];
            g_rowptr[idx] = running;
            g_ofs[idx] = running;
            running += cnt;
        }
    }
    if (t == 1023) g_rowptr[NSEG] = part[1023];
}

__global__ void k_scatter(const int* __restrict__ er, const int* __restrict__ ec,
                          const float* __restrict__ ev, int nnz)
{
    int i = blockIdx.x * blockDim.x + threadIdx.x;
    int stride = gridDim.x * blockDim.x;
    for (int e = i; e < nnz; e += stride) {
        int c = ec[e];
        int pos = atomicAdd(&g_ofs[2 * er[e] + (c >= NITEM)], 1);
        g_scol[pos] = c;
        g_sval[pos] = ev[e];
    }
}

// ---------------- SpMM helpers ----------------
__device__ __forceinline__ void accum_seg(const float* __restrict__ x, int s, int e,
                                          int adj, int lane, float4* acc)
{
    int i = s;
    for (; i + 1 < e; i += 2) {
        int   c0 = g_scol[i] + adj, c1 = g_scol[i + 1] + adj;
        float v0 = g_sval[i],       v1 = g_sval[i + 1];
        const float4* xa = (const float4*)(x + (size_t)c0 * EMB);
        const float4* xb = (const float4*)(x + (size_t)c1 * EMB);
        float4 a0 = xa[lane], a1 = xa[lane + 32], a2 = xa[lane + 64], a3 = xa[lane + 96];
        float4 b0 = xb[lane], b1 = xb[lane + 32], b2 = xb[lane + 64], b3 = xb[lane + 96];
        acc[0].x = fmaf(a0.x, v0, acc[0].x); acc[0].y = fmaf(a0.y, v0, acc[0].y);
        acc[0].z = fmaf(a0.z, v0, acc[0].z); acc[0].w = fmaf(a0.w, v0, acc[0].w);
        acc[1].x = fmaf(a1.x, v0, acc[1].x); acc[1].y = fmaf(a1.y, v0, acc[1].y);
        acc[1].z = fmaf(a1.z, v0, acc[1].z); acc[1].w = fmaf(a1.w, v0, acc[1].w);
        acc[2].x = fmaf(a2.x, v0, acc[2].x); acc[2].y = fmaf(a2.y, v0, acc[2].y);
        acc[2].z = fmaf(a2.z, v0, acc[2].z); acc[2].w = fmaf(a2.w, v0, acc[2].w);
        acc[3].x = fmaf(a3.x, v0, acc[3].x); acc[3].y = fmaf(a3.y, v0, acc[3].y);
        acc[3].z = fmaf(a3.z, v0, acc[3].z); acc[3].w = fmaf(a3.w, v0, acc[3].w);
        acc[0].x = fmaf(b0.x, v1, acc[0].x); acc[0].y = fmaf(b0.y, v1, acc[0].y);
        acc[0].z = fmaf(b0.z, v1, acc[0].z); acc[0].w = fmaf(b0.w, v1, acc[0].w);
        acc[1].x = fmaf(b1.x, v1, acc[1].x); acc[1].y = fmaf(b1.y, v1, acc[1].y);
        acc[1].z = fmaf(b1.z, v1, acc[1].z); acc[1].w = fmaf(b1.w, v1, acc[1].w);
        acc[2].x = fmaf(b2.x, v1, acc[2].x); acc[2].y = fmaf(b2.y, v1, acc[2].y);
        acc[2].z = fmaf(b2.z, v1, acc[2].z); acc[2].w = fmaf(b2.w, v1, acc[2].w);
        acc[3].x = fmaf(b3.x, v1, acc[3].x); acc[3].y = fmaf(b3.y, v1, acc[3].y);
        acc[3].z = fmaf(b3.z, v1, acc[3].z); acc[3].w = fmaf(b3.w, v1, acc[3].w);
    }
    if (i < e) {
        int   c0 = g_scol[i] + adj;
        float v0 = g_sval[i];
        const float4* xa = (const float4*)(x + (size_t)c0 * EMB);
        float4 a0 = xa[lane], a1 = xa[lane + 32], a2 = xa[lane + 64], a3 = xa[lane + 96];
        acc[0].x = fmaf(a0.x, v0, acc[0].x); acc[0].y = fmaf(a0.y, v0, acc[0].y);
        acc[0].z = fmaf(a0.z, v0, acc[0].z); acc[0].w = fmaf(a0.w, v0, acc[0].w);
        acc[1].x = fmaf(a1.x, v0, acc[1].x); acc[1].y = fmaf(a1.y, v0, acc[1].y);
        acc[1].z = fmaf(a1.z, v0, acc[1].z); acc[1].w = fmaf(a1.w, v0, acc[1].w);
        acc[2].x = fmaf(a2.x, v0, acc[2].x); acc[2].y = fmaf(a2.y, v0, acc[2].y);
        acc[2].z = fmaf(a2.z, v0, acc[2].z); acc[2].w = fmaf(a2.w, v0, acc[2].w);
        acc[3].x = fmaf(a3.x, v0, acc[3].x); acc[3].y = fmaf(a3.y, v0, acc[3].y);
        acc[3].z = fmaf(a3.z, v0, acc[3].z); acc[3].w = fmaf(a3.w, v0, acc[3].w);
    }
}

__device__ __forceinline__ void write_acc(float* outp, int row, int lane, int pass,
                                          const float4* acc)
{
    float4* o = (float4*)(outp + (size_t)row * EMB);
    if (pass == 0) {
        __stcs(&o[lane], acc[0]);       __stcs(&o[lane + 32], acc[1]);
        __stcs(&o[lane + 64], acc[2]);  __stcs(&o[lane + 96], acc[3]);
    } else {
        #pragma unroll
        for (int q = 0; q < 4; q++) {
            float4 cur = __ldcs(&o[lane + 32 * q]);
            cur.x += acc[q].x; cur.y += acc[q].y; cur.z += acc[q].z; cur.w += acc[q].w;
            __stcs(&o[lane + 32 * q], cur);
        }
    }
}

// ---------------- SpMM full: warp per row, col-half split, 2 passes ----------------
// pass p gathers only from x[ p*NITEM .. (p+1)*NITEM ).
// doEdis: also compute edis (layer-0), gathering oge[c] = x[(c+NITEM)%NNODES].
__global__ void k_spmm_full(int srcSel, int doEdis, int pass)
{
    const float* x = (srcSel == 0) ? g_egoA : (srcSel == 1) ? g_egoB : g_egoC;
    int lane = threadIdx.x & 31;
    int warp = (int)((blockIdx.x * blockDim.x + threadIdx.x) >> 5);
    int nw   = (int)((gridDim.x * blockDim.x) >> 5);

    for (int row = warp; row < NNODES; row += nw) {
        int b0 = g_rowptr[2 * row], b1 = g_rowptr[2 * row + 1], b2 = g_rowptr[2 * row + 2];
        float4 sacc[4] = { {0,0,0,0}, {0,0,0,0}, {0,0,0,0}, {0,0,0,0} };
        // side: pass0 -> seg0 (c < N), pass1 -> seg1 (c >= N); gather x[c]
        if (pass == 0) accum_seg(x, b0, b1, 0, lane, sacc);
        else           accum_seg(x, b1, b2, 0, lane, sacc);
        if (doEdis) {
            float4 dacc[4] = { {0,0,0,0}, {0,0,0,0}, {0,0,0,0}, {0,0,0,0} };
            // edis: pass0 -> seg1 edges gather x[c-N] (half0); pass1 -> seg0 gather x[c+N]
            if (pass == 0) accum_seg(x, b1, b2, -NITEM, lane, dacc);
            else           accum_seg(x, b0, b1, +NITEM, lane, dacc);
            write_acc(g_edis, row, lane, pass, dacc);
        }
        write_acc(g_side, row, lane, pass, sacc);
    }
}

// ---------------- SpMM slots: warp per gathered slot (layer 2) ----------------
__global__ void k_spmm_slots(int srcSel, const int* __restrict__ items)
{
    const float* x = (srcSel == 0) ? g_egoA : (srcSel == 1) ? g_egoB : g_egoC;
    int lane = threadIdx.x & 31;
    int slot = (int)((blockIdx.x * blockDim.x + threadIdx.x) >> 5);
    if (slot >= NSLOT) return;
    int row = (slot < BATCH) ? items[slot] : (items[slot - BATCH] + NITEM);
    int b0 = g_rowptr[2 * row], b2 = g_rowptr[2 * row + 2];
    float4 sacc[4] = { {0,0,0,0}, {0,0,0,0}, {0,0,0,0}, {0,0,0,0} };
    accum_seg(x, b0, b2, 0, lane, sacc);
    float4* o = (float4*)(g_side + (size_t)row * EMB);
    o[lane] = sacc[0]; o[lane + 32] = sacc[1]; o[lane + 64] = sacc[2]; o[lane + 96] = sacc[3];
}

// ---------------- weight transpose + bf16 hi/lo split ----------------
__global__ void k_wtconv(const float* __restrict__ Wgc, const float* __restrict__ Wgc2,
                         const float* __restrict__ Wbi, int layer)
{
    __shared__ float t[32][33];
    int kb = blockIdx.x * 32;
    int nb = blockIdx.y * 32;
    int tx = threadIdx.x & 31, ty = threadIdx.x >> 5;
    int seg = kb >> 9, kloc = kb & 511;
    const float* W = (seg == 0) ? Wgc : (seg == 1) ? Wgc2 : Wbi;
    size_t lbase = (size_t)layer * 512 * 1536;
    #pragma unroll
    for (int j = 0; j < 4; j++)
        t[ty + 8 * j][tx] = W[(size_t)(kloc + ty + 8 * j) * 512 + nb + tx];
    __syncthreads();
    #pragma unroll
    for (int j = 0; j < 4; j++) {
        int n = nb + ty + 8 * j;
        float x = t[tx][ty + 8 * j];
        __nv_bfloat16 h = __float2bfloat16_rn(x);
        g_wthi[lbase + (size_t)n * 1536 + kb + tx] = h;
        g_wtlo[lbase + (size_t)n * 1536 + kb + tx] = __float2bfloat16_rn(x - __bfloat162float(h));
    }
}

// ---------------- mma.sync bf16x3 fused GEMM, 128x256, cp.async B ----------------
// egoSel: 0=egoA 1=egoB 2=egoC ; outSel: 0=egoB 1=egoC 2=ego3
__global__ void __launch_bounds__(512)
k_gemm(int egoSel, int outSel, int layer,
       const float* __restrict__ bgc, const float* __restrict__ bgc2,
       const float* __restrict__ bbi,
       int M, const int* __restrict__ items)
{
    extern __shared__ __align__(16) char smbuf[];
    const uint32_t OA_HI = 0, OA_LO = 10240, OB_HI = 20480, OB_LO = 40960;
    float* biasP = (float*)(smbuf + 2 * STAGE_SZ);
    uint32_t smb = smem_u32(smbuf);

    int tid = threadIdx.x;
    int wid = tid >> 5, lid = tid & 31;
    int col0 = blockIdx.x * 256;
    int row0 = blockIdx.y * 128;
    int wM = wid >> 2, wN = wid & 3;

    if (tid < 256) {
        int c = col0 + tid;
        biasP[tid] = bgc[c] + bgc2[c] + bbi[c];
    }

    const float* ego = (egoSel == 0) ? g_egoA : (egoSel == 1) ? g_egoB : g_egoC;
    float* Cout = (outSel == 0) ? g_egoB : (outSel == 1) ? g_egoC : g_ego3;
    const __nv_bfloat16* wthi = g_wthi + (size_t)layer * 512 * 1536;
    const __nv_bfloat16* wtlo = g_wtlo + (size_t)layer * 512 * 1536;

    int mA0 = tid >> 3, mA1 = (tid + 512) >> 3;
    int k4  = (tid & 7) * 4;
    int node0, node1, node0o, node1o;
    {
        int g0 = row0 + mA0, g1 = row0 + mA1;
        int s0 = (g0 < M) ? g0 : (M - 1);
        int s1 = (g1 < M) ? g1 : (M - 1);
        node0 = items ? ((s0 < BATCH) ? items[s0] : (items[s0 - BATCH] + NITEM)) : s0;
        node1 = items ? ((s1 < BATCH) ? items[s1] : (items[s1 - BATCH] + NITEM)) : s1;
        node0o = (node0 < NITEM) ? node0 + NITEM : node0 - NITEM;  // oge index
        node1o = (node1 < NITEM) ? node1 + NITEM : node1 - NITEM;
    }
    int nB = tid >> 1, kqB = (tid & 1) * 16;

    float acc[2][8][4];
    #pragma unroll
    for (int mt = 0; mt < 2; mt++)
        #pragma unroll
        for (int nt = 0; nt < 8; nt++)
            #pragma unroll
            for (int q = 0; q < 4; q++) acc[mt][nt][q] = 0.f;

    float pa[2][4];

    auto prefetchA = [&](int c) {
        int seg = c >> 4;
        int kloc = (c & 15) * 32;
        size_t off0 = (size_t)node0 * EMB + kloc + k4;
        size_t off1 = (size_t)node1 * EMB + kloc + k4;
        if (seg == 0) {
            *(float4*)pa[0] = *(const float4*)(g_side + off0);
            *(float4*)pa[1] = *(const float4*)(g_side + off1);
        } else if (seg == 1) {
            *(float4*)pa[0] = *(const float4*)(g_edis + off0);
            *(float4*)pa[1] = *(const float4*)(g_edis + off1);
        } else {
            size_t oo0 = (size_t)node0o * EMB + kloc + k4;
            size_t oo1 = (size_t)node1o * EMB + kloc + k4;
            float4 s0 = *(const float4*)(g_side + off0);
            float4 d0 = *(const float4*)(g_edis + off0);
            float4 e0 = *(const float4*)(ego   + off0);
            float4 o0 = *(const float4*)(g_egoA + oo0);
            pa[0][0] = fmaf(e0.x, s0.x, o0.x * d0.x);
            pa[0][1] = fmaf(e0.y, s0.y, o0.y * d0.y);
            pa[0][2] = fmaf(e0.z, s0.z, o0.z * d0.z);
            pa[0][3] = fmaf(e0.w, s0.w, o0.w * d0.w);
            float4 s1 = *(const float4*)(g_side + off1);
            float4 d1 = *(const float4*)(g_edis + off1);
            float4 e1 = *(const float4*)(ego   + off1);
            float4 o1 = *(const float4*)(g_egoA + oo1);
            pa[1][0] = fmaf(e1.x, s1.x, o1.x * d1.x);
            pa[1][1] = fmaf(e1.y, s1.y, o1.y * d1.y);
            pa[1][2] = fmaf(e1.z, s1.z, o1.z * d1.z);
            pa[1][3] = fmaf(e1.w, s1.w, o1.w * d1.w);
        }
    };

    auto storeA = [&](int stage) {
        uint32_t base = smb + stage * STAGE_SZ;
        #pragma unroll
        for (int l = 0; l < 2; l++) {
            int m = l ? mA1 : mA0;
            uint32_t ad = m * STRB + k4 * 2;
            uint32_t h0 = pack2(__float2bfloat16_rn(pa[l][0]), __float2bfloat16_rn(pa[l][1]));
            uint32_t h1 = pack2(__float2bfloat16_rn(pa[l][2]), __float2bfloat16_rn(pa[l][3]));
            uint32_t l0 = pack2(__float2bfloat16_rn(pa[l][0] - __bfloat162float(__float2bfloat16_rn(pa[l][0]))),
                                __float2bfloat16_rn(pa[l][1] - __bfloat162float(__float2bfloat16_rn(pa[l][1]))));
            uint32_t l1 = pack2(__float2bfloat16_rn(pa[l][2] - __bfloat162float(__float2bfloat16_rn(pa[l][2]))),
                                __float2bfloat16_rn(pa[l][3] - __bfloat162float(__float2bfloat16_rn(pa[l][3]))));
            asm volatile("st.shared.v2.b32 [%0], {%1,%2};" :: "r"(base + OA_HI + ad), "r"(h0), "r"(h1) : "memory");
            asm volatile("st.shared.v2.b32 [%0], {%1,%2};" :: "r"(base + OA_LO + ad), "r"(l0), "r"(l1) : "memory");
        }
    };

    auto cpasyncB = [&](int c) {
        uint32_t base = smb + (c & 1) * STAGE_SZ;
        const char* gh = (const char*)(wthi + (size_t)(col0 + nB) * 1536 + c * 32 + kqB);
        const char* gl = (const char*)(wtlo + (size_t)(col0 + nB) * 1536 + c * 32 + kqB);
        uint32_t bd  = base + OB_HI + nB * STRB + kqB * 2;
        uint32_t bdl = base + OB_LO + nB * STRB + kqB * 2;
        CP16(bd, gh);       CP16(bd + 16, gh + 16);
        CP16(bdl, gl);      CP16(bdl + 16, gl + 16);
    };

    uint32_t aOff = (uint32_t)((wM * 32 + (lid & 15)) * STRB + (lid >> 4) * 16);
    uint32_t bOff[4];
    #pragma unroll
    for (int p = 0; p < 4; p++)
        bOff[p] = (uint32_t)((wN * 64 + p * 16 + (lid & 7) + ((lid >> 4) << 3)) * STRB + (((lid >> 3) & 1) << 4));

    prefetchA(0);
    storeA(0);
    cpasyncB(0);
    CP_COMMIT();
    prefetchA(1);
    CP_WAIT0();
    __syncthreads();

    for (int c = 0; c < NCH; c++) {
        if (c + 1 < NCH) { cpasyncB(c + 1); CP_COMMIT(); }
        uint32_t sb = smb + (c & 1) * STAGE_SZ;
        #pragma unroll
        for (int kk = 0; kk < 2; kk++) {
            uint32_t ko = kk * 32;
            uint32_t ah[2][4], al[2][4];
            LDSM4(ah[0][0], ah[0][1], ah[0][2], ah[0][3], sb + OA_HI + aOff + ko);
            LDSM4(ah[1][0], ah[1][1], ah[1][2], ah[1][3], sb + OA_HI + aOff + 16 * STRB + ko);
            LDSM4(al[0][0], al[0][1], al[0][2], al[0][3], sb + OA_LO + aOff + ko);
            LDSM4(al[1][0], al[1][1], al[1][2], al[1][3], sb + OA_LO + aOff + 16 * STRB + ko);
            #pragma unroll
            for (int p = 0; p < 4; p++) {
                uint32_t bh4[4], bl4[4];
                LDSM4(bh4[0], bh4[1], bh4[2], bh4[3], sb + OB_HI + bOff[p] + ko);
                LDSM4(bl4[0], bl4[1], bl4[2], bl4[3], sb + OB_LO + bOff[p] + ko);
                #pragma unroll
                for (int mt = 0; mt < 2; mt++) {
                    MMA16816(acc[mt][2 * p],     ah[mt], (bh4 + 0));
                    MMA16816(acc[mt][2 * p + 1], ah[mt], (bh4 + 2));
                    MMA16816(acc[mt][2 * p],     ah[mt], (bl4 + 0));
                    MMA16816(acc[mt][2 * p + 1], ah[mt], (bl4 + 2));
                    MMA16816(acc[mt][2 * p],     al[mt], (bh4 + 0));
                    MMA16816(acc[mt][2 * p + 1], al[mt], (bh4 + 2));
                }
            }
        }
        if (c + 1 < NCH) {
            storeA((c + 1) & 1);
            if (c + 2 < NCH) prefetchA(c + 2);
            CP_WAIT0();
            __syncthreads();
        }
    }

    // ---- epilogue: bias + leaky_relu ----
    int rA = lid >> 2;
    int cA = (lid & 3) * 2;
    #pragma unroll
    for (int mt = 0; mt < 2; mt++) {
        #pragma unroll
        for (int half = 0; half < 2; half++) {
            int gr = row0 + wM * 32 + mt * 16 + rA + half * 8;
            if (gr < M) {
                float* cp = Cout + (size_t)gr * EMB + col0 + wN * 64;
                #pragma unroll
                for (int nt = 0; nt < 8; nt++) {
                    int cc = nt * 8 + cA;
                    float x0 = acc[mt][nt][half * 2 + 0] + biasP[wN * 64 + cc];
                    float x1 = acc[mt][nt][half * 2 + 1] + biasP[wN * 64 + cc + 1];
                    float2 o;
                    o.x = (x0 > 0.f) ? x0 : 0.2f * x0;
                    o.y = (x1 > 0.f) ? x1 : 0.2f * x1;
                    *(float2*)(cp + cc) = o;
                }
            }
        }
    }
}

// ---------------- out[slot] = ego0[node]  (acc init) ----------------
__global__ void k_out_init(const int* __restrict__ items, float* __restrict__ out)
{
    int slot = blockIdx.x;
    int node = (slot < BATCH) ? items[slot] : (items[slot - BATCH] + NITEM);
    int t = threadIdx.x;
    float4 x = *(const float4*)(g_egoA + (size_t)node * EMB + t * 4);
    *(float4*)(out + (size_t)slot * EMB + t * 4) = x;
}

// ---------------- out[slot] += normalize(src_row) ----------------
// srcSel: 0=egoB(by node) 1=egoC(by node) 2=ego3(by slot)
__global__ void k_norm_acc(int srcSel, const int* __restrict__ items, float* __restrict__ out)
{
    int slot = blockIdx.x;
    int node = (slot < BATCH) ? items[slot] : (items[slot - BATCH] + NITEM);
    const float* row;
    if (srcSel == 0)      row = g_egoB + (size_t)node * EMB;
    else if (srcSel == 1) row = g_egoC + (size_t)node * EMB;
    else                  row = g_ego3 + (size_t)slot * EMB;

    int t = threadIdx.x;  // 128 threads
    float4 x = *(const float4*)(row + t * 4);
    float ss = x.x * x.x + x.y * x.y + x.z * x.z + x.w * x.w;
    #pragma unroll
    for (int o = 16; o; o >>= 1) ss += __shfl_xor_sync(0xffffffffu, ss, o);
    __shared__ float ws[4];
    if ((t & 31) == 0) ws[t >> 5] = ss;
    __syncthreads();
    float tot = ws[0] + ws[1] + ws[2] + ws[3];
    float inv = 1.f / fmaxf(sqrtf(tot), 1e-12f);

    float* o4 = out + (size_t)slot * EMB + t * 4;
    float4 cur = *(float4*)o4;
    cur.x += x.x * inv; cur.y += x.y * inv; cur.z += x.z * inv; cur.w += x.w * inv;
    *(float4*)o4 = cur;
}

// ---------------- launch ----------------
extern "C" void kernel_launch(void* const* d_in, const int* in_sizes, int n_in,
                              void* d_out, int out_size)
{
    const float* vis   = (const float*)d_in[0];
    const float* txt   = (const float*)d_in[1];
    const int*   er    = (const int*)  d_in[2];
    const int*   ec    = (const int*)  d_in[3];
    const float* ev    = (const float*)d_in[4];
    const int*   items = (const int*)  d_in[5];
    const float* Wgc   = (const float*)d_in[6];
    const float* bgc   = (const float*)d_in[7];
    const float* Wgc2  = (const float*)d_in[8];
    const float* bgc2  = (const float*)d_in[9];
    const float* Wbi   = (const float*)d_in[10];
    const float* bbi   = (const float*)d_in[11];
    float* out = (float*)d_out;
    int nnz = in_sizes[2];

    cudaFuncSetAttribute(k_gemm, cudaFuncAttributeMaxDynamicSharedMemorySize, GEMM_SMEM);

    const int SPMM_B = 2048;
    dim3 gGrid(2, (NNODES + 127) / 128);   // (2, 782)
    dim3 gGrid3(2, NSLOT / 128);           // (2, 64)
    dim3 wGrid(48, 16);

    // init + CSR build (+ all weight conversions upfront)
    k_init<<<25000, 256>>>(vis, txt);
    k_zero2<<<782, 256>>>();
    k_hist<<<2048, 256>>>(er, ec, nnz);
    k_scan<<<1, 1024>>>();
    k_scatter<<<2048, 256>>>(er, ec, ev, nnz);
    k_wtconv<<<wGrid, 256>>>(Wgc, Wgc2, Wbi, 0);
    k_wtconv<<<wGrid, 256>>>(Wgc + 1 * 512 * 512, Wgc2 + 1 * 512 * 512, Wbi + 1 * 512 * 512, 1);
    k_wtconv<<<wGrid, 256>>>(Wgc + 2 * 512 * 512, Wgc2 + 2 * 512 * 512, Wbi + 2 * 512 * 512, 2);

    // acc init
    k_out_init<<<NSLOT, 128>>>(items, out);

    // ---- layer 0: combined side+edis spmm (ego0 in egoA) -> gemm -> egoB ----
    k_spmm_full<<<SPMM_B, 256>>>(0, 1, 0);
    k_spmm_full<<<SPMM_B, 256>>>(0, 1, 1);
    k_gemm<<<gGrid, 512, GEMM_SMEM>>>(0, 0, 0, bgc, bgc2, bbi, NNODES, nullptr);
    k_norm_acc<<<NSLOT, 128>>>(0, items, out);

    // ---- layer 1: egoB -> egoC ----
    k_spmm_full<<<SPMM_B, 256>>>(1, 0, 0);
    k_spmm_full<<<SPMM_B, 256>>>(1, 0, 1);
    k_gemm<<<gGrid, 512, GEMM_SMEM>>>(1, 1, 1, bgc + 512, bgc2 + 512, bbi + 512, NNODES, nullptr);
    k_norm_acc<<<NSLOT, 128>>>(1, items, out);

    // ---- layer 2 (subset): egoC -> ego3 (gathered slots) ----
    k_spmm_slots<<<1024, 256>>>(2, items);
    k_gemm<<<gGrid3, 512, GEMM_SMEM>>>(2, 2, 2, bgc + 1024, bgc2 + 1024, bbi + 1024, NSLOT, items);
    k_norm_acc<<<NSLOT, 128>>>(2, items, out);
}

// round 7
// speedup vs baseline: 2.8705x; 1.0236x over previous
#include <cuda_runtime.h>
#include <cuda_bf16.h>
#include <math.h>
#include <stdint.h>

#define NITEM   50000
#define NNODES  100000
#define NSEG    200000      // 2 * NNODES (row, col-half) segments
#define EMB     512
#define BATCH   4096
#define NSLOT   8192
#define NNZMAX  3200000
#define NCH     48          // 1536 / 32 K-chunks
#define STRB    80          // smem row stride bytes (40 halves)
#define STAGE_SZ 61440      // A hi/lo 20KB + B hi/lo 40KB
#define GEMM_SMEM 123904    // 2 stages + 1KB bias
#define SCANB   782         // scan blocks (782*256 >= NSEG)

// ---------------- static device scratch ----------------
__device__ float g_egoA[51200000];   // ego0 = [vision;text], preserved
__device__ float g_egoB[51200000];   // layer-1 activations
__device__ float g_egoC[51200000];   // layer-2 activations
__device__ float g_edis[51200000];
__device__ float g_side[51200000];
__device__ float g_ego3[4194304];    // 8192 x 512
__device__ int   g_rowptr[NSEG + 1];
__device__ int   g_ofs[NSEG];
__device__ int   g_bsum[1024];
__device__ int   g_boff[1024];
__device__ int   g_scol[NNZMAX];
__device__ float g_sval[NNZMAX];
__device__ __nv_bfloat16 g_wthi[3 * 512 * 1536];  // W^T hi, [layer][N][K] K-contig
__device__ __nv_bfloat16 g_wtlo[3 * 512 * 1536];  // W^T lo

__device__ __forceinline__ uint32_t smem_u32(const void* p) {
    uint32_t a;
    asm("{ .reg .u64 t; cvta.to.shared.u64 t, %1; cvt.u32.u64 %0, t; }" : "=r"(a) : "l"(p));
    return a;
}
#define LDSM4(r0,r1,r2,r3,addr) \
    asm volatile("ldmatrix.sync.aligned.m8n8.x4.shared.b16 {%0,%1,%2,%3}, [%4];" \
                 : "=r"(r0),"=r"(r1),"=r"(r2),"=r"(r3) : "r"(addr))
#define MMA16816(d,a,b) \
    asm volatile("mma.sync.aligned.m16n8k16.row.col.f32.bf16.bf16.f32 " \
                 "{%0,%1,%2,%3}, {%4,%5,%6,%7}, {%8,%9}, {%0,%1,%2,%3};" \
                 : "+f"(d[0]),"+f"(d[1]),"+f"(d[2]),"+f"(d[3]) \
                 : "r"(a[0]),"r"(a[1]),"r"(a[2]),"r"(a[3]), "r"(b[0]),"r"(b[1]))
#define CP16(smaddr, gptr) \
    asm volatile("cp.async.ca.shared.global [%0], [%1], 16;" :: "r"(smaddr), "l"(gptr) : "memory")
#define CP_COMMIT() asm volatile("cp.async.commit_group;" ::: "memory")
#define CP_WAIT0()  asm volatile("cp.async.wait_group 0;" ::: "memory")

__device__ __forceinline__ uint32_t pack2(__nv_bfloat16 a, __nv_bfloat16 b) {
    __nv_bfloat162 p = __halves2bfloat162(a, b);
    return *reinterpret_cast<uint32_t*>(&p);
}

// ---------------- init: ego0 = [vision;text] ----------------
__global__ void k_init(const float* __restrict__ vis, const float* __restrict__ txt)
{
    size_t i = (size_t)blockIdx.x * blockDim.x + threadIdx.x;
    size_t half = (size_t)NITEM * EMB / 4;
    if (i >= half) return;
    ((float4*)g_egoA)[i]        = ((const float4*)vis)[i];
    ((float4*)g_egoA)[half + i] = ((const float4*)txt)[i];
}

__global__ void k_zero2()
{
    int i = blockIdx.x * blockDim.x + threadIdx.x;
    if (i < NSEG) g_ofs[i] = 0;
}

// ---------------- CSR build: key = 2*row + (col >= NITEM) ----------------
__global__ void k_hist(const int* __restrict__ er, const int* __restrict__ ec, int nnz)
{
    int i = blockIdx.x * blockDim.x + threadIdx.x;
    int stride = gridDim.x * blockDim.x;
    for (int e = i; e < nnz; e += stride)
        atomicAdd(&g_ofs[2 * er[e] + (ec[e] >= NITEM)], 1);
}

// ---- parallel scan: 3 kernels ----
__global__ void k_scan1()   // per-block reduce (256 elems/block)
{
    __shared__ int sm[256];
    int t = threadIdx.x;
    int idx = blockIdx.x * 256 + t;
    int v = (idx < NSEG) ? g_ofs[idx] : 0;
    sm[t] = v;
    __syncthreads();
    #pragma unroll
    for (int off = 128; off; off >>= 1) {
        if (t < off) sm[t] += sm[t + off];
        __syncthreads();
    }
    if (t == 0) g_bsum[blockIdx.x] = sm[0];
}

__global__ void k_scan2()   // single block: scan 782 block sums
{
    __shared__ int sm[1024];
    int t = threadIdx.x;
    int v = (t < SCANB) ? g_bsum[t] : 0;
    sm[t] = v;
    __syncthreads();
    #pragma unroll
    for (int off = 1; off < 1024; off <<= 1) {
        int add = (t >= off) ? sm[t - off] : 0;
        __syncthreads();
        sm[t] += add;
        __syncthreads();
    }
    if (t < SCANB) g_boff[t] = sm[t] - v;  // exclusive
    if (t == 1023) g_rowptr[NSEG] = sm[1023];
}

__global__ void k_scan3()   // per-block exclusive scan + offset, write rowptr/ofs
{
    __shared__ int sm[256];
    int t = threadIdx.x;
    int idx = blockIdx.x * 256 + t;
    int v = (idx < NSEG) ? g_ofs[idx] : 0;
    sm[t] = v;
    __syncthreads();
    #pragma unroll
    for (int off = 1; off < 256; off <<= 1) {
        int add = (t >= off) ? sm[t - off] : 0;
        __syncthreads();
        sm[t] += add;
        __syncthreads();
    }
    int ex = sm[t] - v + g_boff[blockIdx.x];
    if (idx < NSEG) { g_rowptr[idx] = ex; g_ofs[idx] = ex; }
}

__global__ void k_scatter(const int* __restrict__ er, const int* __restrict__ ec,
                          const float* __restrict__ ev, int nnz)
{
    int i = blockIdx.x * blockDim.x + threadIdx.x;
    int stride = gridDim.x * blockDim.x;
    for (int e = i; e < nnz; e += stride) {
        int c = ec[e];
        int pos = atomicAdd(&g_ofs[2 * er[e] + (c >= NITEM)], 1);
        g_scol[pos] = c;
        g_sval[pos] = ev[e];
    }
}

// ---------------- SpMM helpers ----------------
__device__ __forceinline__ void accum_seg(const float* __restrict__ x, int s, int e,
                                          int adj, int lane, float4* acc)
{
    int i = s;
    for (; i + 1 < e; i += 2) {
        int   c0 = g_scol[i] + adj, c1 = g_scol[i + 1] + adj;
        float v0 = g_sval[i],       v1 = g_sval[i + 1];
        const float4* xa = (const float4*)(x + (size_t)c0 * EMB);
        const float4* xb = (const float4*)(x + (size_t)c1 * EMB);
        float4 a0 = __ldcg(&xa[lane]),      a1 = __ldcg(&xa[lane + 32]);
        float4 a2 = __ldcg(&xa[lane + 64]), a3 = __ldcg(&xa[lane + 96]);
        float4 b0 = __ldcg(&xb[lane]),      b1 = __ldcg(&xb[lane + 32]);
        float4 b2 = __ldcg(&xb[lane + 64]), b3 = __ldcg(&xb[lane + 96]);
        acc[0].x = fmaf(a0.x, v0, acc[0].x); acc[0].y = fmaf(a0.y, v0, acc[0].y);
        acc[0].z = fmaf(a0.z, v0, acc[0].z); acc[0].w = fmaf(a0.w, v0, acc[0].w);
        acc[1].x = fmaf(a1.x, v0, acc[1].x); acc[1].y = fmaf(a1.y, v0, acc[1].y);
        acc[1].z = fmaf(a1.z, v0, acc[1].z); acc[1].w = fmaf(a1.w, v0, acc[1].w);
        acc[2].x = fmaf(a2.x, v0, acc[2].x); acc[2].y = fmaf(a2.y, v0, acc[2].y);
        acc[2].z = fmaf(a2.z, v0, acc[2].z); acc[2].w = fmaf(a2.w, v0, acc[2].w);
        acc[3].x = fmaf(a3.x, v0, acc[3].x); acc[3].y = fmaf(a3.y, v0, acc[3].y);
        acc[3].z = fmaf(a3.z, v0, acc[3].z); acc[3].w = fmaf(a3.w, v0, acc[3].w);
        acc[0].x = fmaf(b0.x, v1, acc[0].x); acc[0].y = fmaf(b0.y, v1, acc[0].y);
        acc[0].z = fmaf(b0.z, v1, acc[0].z); acc[0].w = fmaf(b0.w, v1, acc[0].w);
        acc[1].x = fmaf(b1.x, v1, acc[1].x); acc[1].y = fmaf(b1.y, v1, acc[1].y);
        acc[1].z = fmaf(b1.z, v1, acc[1].z); acc[1].w = fmaf(b1.w, v1, acc[1].w);
        acc[2].x = fmaf(b2.x, v1, acc[2].x); acc[2].y = fmaf(b2.y, v1, acc[2].y);
        acc[2].z = fmaf(b2.z, v1, acc[2].z); acc[2].w = fmaf(b2.w, v1, acc[2].w);
        acc[3].x = fmaf(b3.x, v1, acc[3].x); acc[3].y = fmaf(b3.y, v1, acc[3].y);
        acc[3].z = fmaf(b3.z, v1, acc[3].z); acc[3].w = fmaf(b3.w, v1, acc[3].w);
    }
    if (i < e) {
        int   c0 = g_scol[i] + adj;
        float v0 = g_sval[i];
        const float4* xa = (const float4*)(x + (size_t)c0 * EMB);
        float4 a0 = __ldcg(&xa[lane]),      a1 = __ldcg(&xa[lane + 32]);
        float4 a2 = __ldcg(&xa[lane + 64]), a3 = __ldcg(&xa[lane + 96]);
        acc[0].x = fmaf(a0.x, v0, acc[0].x); acc[0].y = fmaf(a0.y, v0, acc[0].y);
        acc[0].z = fmaf(a0.z, v0, acc[0].z); acc[0].w = fmaf(a0.w, v0, acc[0].w);
        acc[1].x = fmaf(a1.x, v0, acc[1].x); acc[1].y = fmaf(a1.y, v0, acc[1].y);
        acc[1].z = fmaf(a1.z, v0, acc[1].z); acc[1].w = fmaf(a1.w, v0, acc[1].w);
        acc[2].x = fmaf(a2.x, v0, acc[2].x); acc[2].y = fmaf(a2.y, v0, acc[2].y);
        acc[2].z = fmaf(a2.z, v0, acc[2].z); acc[2].w = fmaf(a2.w, v0, acc[2].w);
        acc[3].x = fmaf(a3.x, v0, acc[3].x); acc[3].y = fmaf(a3.y, v0, acc[3].y);
        acc[3].z = fmaf(a3.z, v0, acc[3].z); acc[3].w = fmaf(a3.w, v0, acc[3].w);
    }
}

__device__ __forceinline__ void write_acc(float* outp, int row, int lane, int pass,
                                          const float4* acc)
{
    float4* o = (float4*)(outp + (size_t)row * EMB);
    if (pass == 0) {
        __stcs(&o[lane], acc[0]);       __stcs(&o[lane + 32], acc[1]);
        __stcs(&o[lane + 64], acc[2]);  __stcs(&o[lane + 96], acc[3]);
    } else {
        #pragma unroll
        for (int q = 0; q < 4; q++) {
            float4 cur = __ldcs(&o[lane + 32 * q]);
            cur.x += acc[q].x; cur.y += acc[q].y; cur.z += acc[q].z; cur.w += acc[q].w;
            __stcs(&o[lane + 32 * q], cur);
        }
    }
}

// ---------------- SpMM full: warp per row, col-half split, 2 passes ----------------
__global__ void k_spmm_full(int srcSel, int doEdis, int pass)
{
    const float* x = (srcSel == 0) ? g_egoA : (srcSel == 1) ? g_egoB : g_egoC;
    int lane = threadIdx.x & 31;
    int warp = (int)((blockIdx.x * blockDim.x + threadIdx.x) >> 5);
    int nw   = (int)((gridDim.x * blockDim.x) >> 5);

    for (int row = warp; row < NNODES; row += nw) {
        int b0 = g_rowptr[2 * row], b1 = g_rowptr[2 * row + 1], b2 = g_rowptr[2 * row + 2];
        float4 sacc[4] = { {0,0,0,0}, {0,0,0,0}, {0,0,0,0}, {0,0,0,0} };
        if (pass == 0) accum_seg(x, b0, b1, 0, lane, sacc);
        else           accum_seg(x, b1, b2, 0, lane, sacc);
        if (doEdis) {
            float4 dacc[4] = { {0,0,0,0}, {0,0,0,0}, {0,0,0,0}, {0,0,0,0} };
            if (pass == 0) accum_seg(x, b1, b2, -NITEM, lane, dacc);
            else           accum_seg(x, b0, b1, +NITEM, lane, dacc);
            write_acc(g_edis, row, lane, pass, dacc);
        }
        write_acc(g_side, row, lane, pass, sacc);
    }
}

// ---------------- SpMM slots: warp per gathered slot (layer 2) ----------------
__global__ void k_spmm_slots(int srcSel, const int* __restrict__ items)
{
    const float* x = (srcSel == 0) ? g_egoA : (srcSel == 1) ? g_egoB : g_egoC;
    int lane = threadIdx.x & 31;
    int slot = (int)((blockIdx.x * blockDim.x + threadIdx.x) >> 5);
    if (slot >= NSLOT) return;
    int row = (slot < BATCH) ? items[slot] : (items[slot - BATCH] + NITEM);
    int b0 = g_rowptr[2 * row], b2 = g_rowptr[2 * row + 2];
    float4 sacc[4] = { {0,0,0,0}, {0,0,0,0}, {0,0,0,0}, {0,0,0,0} };
    accum_seg(x, b0, b2, 0, lane, sacc);
    float4* o = (float4*)(g_side + (size_t)row * EMB);
    o[lane] = sacc[0]; o[lane + 32] = sacc[1]; o[lane + 64] = sacc[2]; o[lane + 96] = sacc[3];
}

// ---------------- weight transpose + bf16 hi/lo split ----------------
__global__ void k_wtconv(const float* __restrict__ Wgc, const float* __restrict__ Wgc2,
                         const float* __restrict__ Wbi, int layer)
{
    __shared__ float t[32][33];
    int kb = blockIdx.x * 32;
    int nb = blockIdx.y * 32;
    int tx = threadIdx.x & 31, ty = threadIdx.x >> 5;
    int seg = kb >> 9, kloc = kb & 511;
    const float* W = (seg == 0) ? Wgc : (seg == 1) ? Wgc2 : Wbi;
    size_t lbase = (size_t)layer * 512 * 1536;
    #pragma unroll
    for (int j = 0; j < 4; j++)
        t[ty + 8 * j][tx] = W[(size_t)(kloc + ty + 8 * j) * 512 + nb + tx];
    __syncthreads();
    #pragma unroll
    for (int j = 0; j < 4; j++) {
        int n = nb + ty + 8 * j;
        float x = t[tx][ty + 8 * j];
        __nv_bfloat16 h = __float2bfloat16_rn(x);
        g_wthi[lbase + (size_t)n * 1536 + kb + tx] = h;
        g_wtlo[lbase + (size_t)n * 1536 + kb + tx] = __float2bfloat16_rn(x - __bfloat162float(h));
    }
}

// ---------------- mma.sync bf16x3 fused GEMM, 128x256, cp.async B ----------------
__global__ void __launch_bounds__(512)
k_gemm(int egoSel, int outSel, int layer,
       const float* __restrict__ bgc, const float* __restrict__ bgc2,
       const float* __restrict__ bbi,
       int M, const int* __restrict__ items)
{
    extern __shared__ __align__(16) char smbuf[];
    const uint32_t OA_HI = 0, OA_LO = 10240, OB_HI = 20480, OB_LO = 40960;
    float* biasP = (float*)(smbuf + 2 * STAGE_SZ);
    uint32_t smb = smem_u32(smbuf);

    int tid = threadIdx.x;
    int wid = tid >> 5, lid = tid & 31;
    int col0 = blockIdx.x * 256;
    int row0 = blockIdx.y * 128;
    int wM = wid >> 2, wN = wid & 3;

    if (tid < 256) {
        int c = col0 + tid;
        biasP[tid] = bgc[c] + bgc2[c] + bbi[c];
    }

    const float* ego = (egoSel == 0) ? g_egoA : (egoSel == 1) ? g_egoB : g_egoC;
    float* Cout = (outSel == 0) ? g_egoB : (outSel == 1) ? g_egoC : g_ego3;
    const __nv_bfloat16* wthi = g_wthi + (size_t)layer * 512 * 1536;
    const __nv_bfloat16* wtlo = g_wtlo + (size_t)layer * 512 * 1536;

    int mA0 = tid >> 3, mA1 = (tid + 512) >> 3;
    int k4  = (tid & 7) * 4;
    int node0, node1, node0o, node1o;
    {
        int g0 = row0 + mA0, g1 = row0 + mA1;
        int s0 = (g0 < M) ? g0 : (M - 1);
        int s1 = (g1 < M) ? g1 : (M - 1);
        node0 = items ? ((s0 < BATCH) ? items[s0] : (items[s0 - BATCH] + NITEM)) : s0;
        node1 = items ? ((s1 < BATCH) ? items[s1] : (items[s1 - BATCH] + NITEM)) : s1;
        node0o = (node0 < NITEM) ? node0 + NITEM : node0 - NITEM;  // oge index
        node1o = (node1 < NITEM) ? node1 + NITEM : node1 - NITEM;
    }
    int nB = tid >> 1, kqB = (tid & 1) * 16;

    float acc[2][8][4];
    #pragma unroll
    for (int mt = 0; mt < 2; mt++)
        #pragma unroll
        for (int nt = 0; nt < 8; nt++)
            #pragma unroll
            for (int q = 0; q < 4; q++) acc[mt][nt][q] = 0.f;

    float pa[2][4];

    auto prefetchA = [&](int c) {
        int seg = c >> 4;
        int kloc = (c & 15) * 32;
        size_t off0 = (size_t)node0 * EMB + kloc + k4;
        size_t off1 = (size_t)node1 * EMB + kloc + k4;
        if (seg == 0) {
            *(float4*)pa[0] = *(const float4*)(g_side + off0);
            *(float4*)pa[1] = *(const float4*)(g_side + off1);
        } else if (seg == 1) {
            *(float4*)pa[0] = *(const float4*)(g_edis + off0);
            *(float4*)pa[1] = *(const float4*)(g_edis + off1);
        } else {
            size_t oo0 = (size_t)node0o * EMB + kloc + k4;
            size_t oo1 = (size_t)node1o * EMB + kloc + k4;
            float4 s0 = *(const float4*)(g_side + off0);
            float4 d0 = *(const float4*)(g_edis + off0);
            float4 e0 = *(const float4*)(ego   + off0);
            float4 o0 = *(const float4*)(g_egoA + oo0);
            pa[0][0] = fmaf(e0.x, s0.x, o0.x * d0.x);
            pa[0][1] = fmaf(e0.y, s0.y, o0.y * d0.y);
            pa[0][2] = fmaf(e0.z, s0.z, o0.z * d0.z);
            pa[0][3] = fmaf(e0.w, s0.w, o0.w * d0.w);
            float4 s1 = *(const float4*)(g_side + off1);
            float4 d1 = *(const float4*)(g_edis + off1);
            float4 e1 = *(const float4*)(ego   + off1);
            float4 o1 = *(const float4*)(g_egoA + oo1);
            pa[1][0] = fmaf(e1.x, s1.x, o1.x * d1.x);
            pa[1][1] = fmaf(e1.y, s1.y, o1.y * d1.y);
            pa[1][2] = fmaf(e1.z, s1.z, o1.z * d1.z);
            pa[1][3] = fmaf(e1.w, s1.w, o1.w * d1.w);
        }
    };

    auto storeA = [&](int stage) {
        uint32_t base = smb + stage * STAGE_SZ;
        #pragma unroll
        for (int l = 0; l < 2; l++) {
            int m = l ? mA1 : mA0;
            uint32_t ad = m * STRB + k4 * 2;
            uint32_t h0 = pack2(__float2bfloat16_rn(pa[l][0]), __float2bfloat16_rn(pa[l][1]));
            uint32_t h1 = pack2(__float2bfloat16_rn(pa[l][2]), __float2bfloat16_rn(pa[l][3]));
            uint32_t l0 = pack2(__float2bfloat16_rn(pa[l][0] - __bfloat162float(__float2bfloat16_rn(pa[l][0]))),
                                __float2bfloat16_rn(pa[l][1] - __bfloat162float(__float2bfloat16_rn(pa[l][1]))));
            uint32_t l1 = pack2(__float2bfloat16_rn(pa[l][2] - __bfloat162float(__float2bfloat16_rn(pa[l][2]))),
                                __float2bfloat16_rn(pa[l][3] - __bfloat162float(__float2bfloat16_rn(pa[l][3]))));
            asm volatile("st.shared.v2.b32 [%0], {%1,%2};" :: "r"(base + OA_HI + ad), "r"(h0), "r"(h1) : "memory");
            asm volatile("st.shared.v2.b32 [%0], {%1,%2};" :: "r"(base + OA_LO + ad), "r"(l0), "r"(l1) : "memory");
        }
    };

    auto cpasyncB = [&](int c) {
        uint32_t base = smb + (c & 1) * STAGE_SZ;
        const char* gh = (const char*)(wthi + (size_t)(col0 + nB) * 1536 + c * 32 + kqB);
        const char* gl = (const char*)(wtlo + (size_t)(col0 + nB) * 1536 + c * 32 + kqB);
        uint32_t bd  = base + OB_HI + nB * STRB + kqB * 2;
        uint32_t bdl = base + OB_LO + nB * STRB + kqB * 2;
        CP16(bd, gh);       CP16(bd + 16, gh + 16);
        CP16(bdl, gl);      CP16(bdl + 16, gl + 16);
    };

    uint32_t aOff = (uint32_t)((wM * 32 + (lid & 15)) * STRB + (lid >> 4) * 16);
    uint32_t bOff[4];
    #pragma unroll
    for (int p = 0; p < 4; p++)
        bOff[p] = (uint32_t)((wN * 64 + p * 16 + (lid & 7) + ((lid >> 4) << 3)) * STRB + (((lid >> 3) & 1) << 4));

    prefetchA(0);
    storeA(0);
    cpasyncB(0);
    CP_COMMIT();
    prefetchA(1);
    CP_WAIT0();
    __syncthreads();

    for (int c = 0; c < NCH; c++) {
        if (c + 1 < NCH) { cpasyncB(c + 1); CP_COMMIT(); }
        uint32_t sb = smb + (c & 1) * STAGE_SZ;
        #pragma unroll
        for (int kk = 0; kk < 2; kk++) {
            uint32_t ko = kk * 32;
            uint32_t ah[2][4], al[2][4];
            LDSM4(ah[0][0], ah[0][1], ah[0][2], ah[0][3], sb + OA_HI + aOff + ko);
            LDSM4(ah[1][0], ah[1][1], ah[1][2], ah[1][3], sb + OA_HI + aOff + 16 * STRB + ko);
            LDSM4(al[0][0], al[0][1], al[0][2], al[0][3], sb + OA_LO + aOff + ko);
            LDSM4(al[1][0], al[1][1], al[1][2], al[1][3], sb + OA_LO + aOff + 16 * STRB + ko);
            #pragma unroll
            for (int p = 0; p < 4; p++) {
                uint32_t bh4[4], bl4[4];
                LDSM4(bh4[0], bh4[1], bh4[2], bh4[3], sb + OB_HI + bOff[p] + ko);
                LDSM4(bl4[0], bl4[1], bl4[2], bl4[3], sb + OB_LO + bOff[p] + ko);
                #pragma unroll
                for (int mt = 0; mt < 2; mt++) {
                    MMA16816(acc[mt][2 * p],     ah[mt], (bh4 + 0));
                    MMA16816(acc[mt][2 * p + 1], ah[mt], (bh4 + 2));
                    MMA16816(acc[mt][2 * p],     ah[mt], (bl4 + 0));
                    MMA16816(acc[mt][2 * p + 1], ah[mt], (bl4 + 2));
                    MMA16816(acc[mt][2 * p],     al[mt], (bh4 + 0));
                    MMA16816(acc[mt][2 * p + 1], al[mt], (bh4 + 2));
                }
            }
        }
        if (c + 1 < NCH) {
            storeA((c + 1) & 1);
            if (c + 2 < NCH) prefetchA(c + 2);
            CP_WAIT0();
            __syncthreads();
        }
    }

    // ---- epilogue: bias + leaky_relu ----
    int rA = lid >> 2;
    int cA = (lid & 3) * 2;
    #pragma unroll
    for (int mt = 0; mt < 2; mt++) {
        #pragma unroll
        for (int half = 0; half < 2; half++) {
            int gr = row0 + wM * 32 + mt * 16 + rA + half * 8;
            if (gr < M) {
                float* cp = Cout + (size_t)gr * EMB + col0 + wN * 64;
                #pragma unroll
                for (int nt = 0; nt < 8; nt++) {
                    int cc = nt * 8 + cA;
                    float x0 = acc[mt][nt][half * 2 + 0] + biasP[wN * 64 + cc];
                    float x1 = acc[mt][nt][half * 2 + 1] + biasP[wN * 64 + cc + 1];
                    float2 o;
                    o.x = (x0 > 0.f) ? x0 : 0.2f * x0;
                    o.y = (x1 > 0.f) ? x1 : 0.2f * x1;
                    *(float2*)(cp + cc) = o;
                }
            }
        }
    }
}

// ---------------- out[slot] = ego0[node]  (acc init) ----------------
__global__ void k_out_init(const int* __restrict__ items, float* __restrict__ out)
{
    int slot = blockIdx.x;
    int node = (slot < BATCH) ? items[slot] : (items[slot - BATCH] + NITEM);
    int t = threadIdx.x;
    float4 x = *(const float4*)(g_egoA + (size_t)node * EMB + t * 4);
    *(float4*)(out + (size_t)slot * EMB + t * 4) = x;
}

// ---------------- out[slot] += normalize(src_row) ----------------
__global__ void k_norm_acc(int srcSel, const int* __restrict__ items, float* __restrict__ out)
{
    int slot = blockIdx.x;
    int node = (slot < BATCH) ? items[slot] : (items[slot - BATCH] + NITEM);
    const float* row;
    if (srcSel == 0)      row = g_egoB + (size_t)node * EMB;
    else if (srcSel == 1) row = g_egoC + (size_t)node * EMB;
    else                  row = g_ego3 + (size_t)slot * EMB;

    int t = threadIdx.x;  // 128 threads
    float4 x = *(const float4*)(row + t * 4);
    float ss = x.x * x.x + x.y * x.y + x.z * x.z + x.w * x.w;
    #pragma unroll
    for (int o = 16; o; o >>= 1) ss += __shfl_xor_sync(0xffffffffu, ss, o);
    __shared__ float ws[4];
    if ((t & 31) == 0) ws[t >> 5] = ss;
    __syncthreads();
    float tot = ws[0] + ws[1] + ws[2] + ws[3];
    float inv = 1.f / fmaxf(sqrtf(tot), 1e-12f);

    float* o4 = out + (size_t)slot * EMB + t * 4;
    float4 cur = *(float4*)o4;
    cur.x += x.x * inv; cur.y += x.y * inv; cur.z += x.z * inv; cur.w += x.w * inv;
    *(float4*)o4 = cur;
}

// ---------------- launch ----------------
extern "C" void kernel_launch(void* const* d_in, const int* in_sizes, int n_in,
                              void* d_out, int out_size)
{
    const float* vis   = (const float*)d_in[0];
    const float* txt   = (const float*)d_in[1];
    const int*   er    = (const int*)  d_in[2];
    const int*   ec    = (const int*)  d_in[3];
    const float* ev    = (const float*)d_in[4];
    const int*   items = (const int*)  d_in[5];
    const float* Wgc   = (const float*)d_in[6];
    const float* bgc   = (const float*)d_in[7];
    const float* Wgc2  = (const float*)d_in[8];
    const float* bgc2  = (const float*)d_in[9];
    const float* Wbi   = (const float*)d_in[10];
    const float* bbi   = (const float*)d_in[11];
    float* out = (float*)d_out;
    int nnz = in_sizes[2];

    cudaFuncSetAttribute(k_gemm, cudaFuncAttributeMaxDynamicSharedMemorySize, GEMM_SMEM);

    const int SPMM_B = 2048;
    dim3 gGrid(2, (NNODES + 127) / 128);   // (2, 782)
    dim3 gGrid3(2, NSLOT / 128);           // (2, 64)
    dim3 wGrid(48, 16);

    // init + CSR build (+ all weight conversions upfront)
    k_init<<<25000, 256>>>(vis, txt);
    k_zero2<<<782, 256>>>();
    k_hist<<<2048, 256>>>(er, ec, nnz);
    k_scan1<<<SCANB, 256>>>();
    k_scan2<<<1, 1024>>>();
    k_scan3<<<SCANB, 256>>>();
    k_scatter<<<2048, 256>>>(er, ec, ev, nnz);
    k_wtconv<<<wGrid, 256>>>(Wgc, Wgc2, Wbi, 0);
    k_wtconv<<<wGrid, 256>>>(Wgc + 1 * 512 * 512, Wgc2 + 1 * 512 * 512, Wbi + 1 * 512 * 512, 1);
    k_wtconv<<<wGrid, 256>>>(Wgc + 2 * 512 * 512, Wgc2 + 2 * 512 * 512, Wbi + 2 * 512 * 512, 2);

    // acc init
    k_out_init<<<NSLOT, 128>>>(items, out);

    // ---- layer 0: combined side+edis spmm (ego0 in egoA) -> gemm -> egoB ----
    k_spmm_full<<<SPMM_B, 256>>>(0, 1, 0);
    k_spmm_full<<<SPMM_B, 256>>>(0, 1, 1);
    k_gemm<<<gGrid, 512, GEMM_SMEM>>>(0, 0, 0, bgc, bgc2, bbi, NNODES, nullptr);
    k_norm_acc<<<NSLOT, 128>>>(0, items, out);

    // ---- layer 1: egoB -> egoC ----
    k_spmm_full<<<SPMM_B, 256>>>(1, 0, 0);
    k_spmm_full<<<SPMM_B, 256>>>(1, 0, 1);
    k_gemm<<<gGrid, 512, GEMM_SMEM>>>(1, 1, 1, bgc + 512, bgc2 + 512, bbi + 512, NNODES, nullptr);
    k_norm_acc<<<NSLOT, 128>>>(1, items, out);

    // ---- layer 2 (subset): egoC -> ego3 (gathered slots) ----
    k_spmm_slots<<<1024, 256>>>(2, items);
    k_gemm<<<gGrid3, 512, GEMM_SMEM>>>(2, 2, 2, bgc + 1024, bgc2 + 1024, bbi + 1024, NSLOT, items);
    k_norm_acc<<<NSLOT, 128>>>(2, items, out);
}

// round 9
// speedup vs baseline: 2.9275x; 1.0199x over previous
#include <cuda_runtime.h>
#include <cuda_bf16.h>
#include <math.h>
#include <stdint.h>

#define NITEM   50000
#define NNODES  100000
#define NSEG    200000      // 2 * NNODES (row, col-half) segments
#define EMB     512
#define BATCH   4096
#define NSLOT   8192
#define NNZMAX  3200000
#define NCH     48          // 1536 / 32 K-chunks
#define STRB    80          // smem row stride bytes (40 halves)
#define STAGE_SZ 61440      // A hi/lo 20KB + B hi/lo 40KB
#define GEMM_SMEM 123904    // 2 stages + 1KB bias
#define SCANB   782         // scan blocks (782*256 >= NSEG)

// ---------------- static device scratch ----------------
__device__ float g_egoA[51200000];   // ego0 = [vision;text], preserved
__device__ float g_egoB[51200000];   // layer-1 activations
__device__ float g_egoC[51200000];   // layer-2 activations
__device__ float g_edis[51200000];
__device__ float g_side[51200000];
__device__ float g_hbuf[51200000];   // h = ego*side + oge*edis (fused in spmm)
__device__ float g_ego3[4194304];    // 8192 x 512
__device__ int   g_rowptr[NSEG + 1];
__device__ int   g_ofs[NSEG];
__device__ int   g_bsum[1024];
__device__ int   g_boff[1024];
__device__ int   g_scol[NNZMAX];
__device__ float g_sval[NNZMAX];
__device__ __nv_bfloat16 g_wthi[3 * 512 * 1536];  // W^T hi, [layer][N][K] K-contig
__device__ __nv_bfloat16 g_wtlo[3 * 512 * 1536];  // W^T lo

__device__ __forceinline__ uint32_t smem_u32(const void* p) {
    uint32_t a;
    asm("{ .reg .u64 t; cvta.to.shared.u64 t, %1; cvt.u32.u64 %0, t; }" : "=r"(a) : "l"(p));
    return a;
}
#define LDSM4(r0,r1,r2,r3,addr) \
    asm volatile("ldmatrix.sync.aligned.m8n8.x4.shared.b16 {%0,%1,%2,%3}, [%4];" \
                 : "=r"(r0),"=r"(r1),"=r"(r2),"=r"(r3) : "r"(addr))
#define MMA16816(d,a,b) \
    asm volatile("mma.sync.aligned.m16n8k16.row.col.f32.bf16.bf16.f32 " \
                 "{%0,%1,%2,%3}, {%4,%5,%6,%7}, {%8,%9}, {%0,%1,%2,%3};" \
                 : "+f"(d[0]),"+f"(d[1]),"+f"(d[2]),"+f"(d[3]) \
                 : "r"(a[0]),"r"(a[1]),"r"(a[2]),"r"(a[3]), "r"(b[0]),"r"(b[1]))
#define CP16(smaddr, gptr) \
    asm volatile("cp.async.ca.shared.global [%0], [%1], 16;" :: "r"(smaddr), "l"(gptr) : "memory")
#define CP_COMMIT() asm volatile("cp.async.commit_group;" ::: "memory")
#define CP_WAIT0()  asm volatile("cp.async.wait_group 0;" ::: "memory")

__device__ __forceinline__ uint32_t pack2(__nv_bfloat16 a, __nv_bfloat16 b) {
    __nv_bfloat162 p = __halves2bfloat162(a, b);
    return *reinterpret_cast<uint32_t*>(&p);
}

// ---------------- init: ego0 = [vision;text] ----------------
__global__ void k_init(const float* __restrict__ vis, const float* __restrict__ txt)
{
    size_t i = (size_t)blockIdx.x * blockDim.x + threadIdx.x;
    size_t half = (size_t)NITEM * EMB / 4;
    if (i >= half) return;
    ((float4*)g_egoA)[i]        = ((const float4*)vis)[i];
    ((float4*)g_egoA)[half + i] = ((const float4*)txt)[i];
}

__global__ void k_zero2()
{
    int i = blockIdx.x * blockDim.x + threadIdx.x;
    if (i < NSEG) g_ofs[i] = 0;
}

// ---------------- CSR build: key = 2*row + (col >= NITEM) ----------------
__global__ void k_hist(const int* __restrict__ er, const int* __restrict__ ec, int nnz)
{
    int i = blockIdx.x * blockDim.x + threadIdx.x;
    int stride = gridDim.x * blockDim.x;
    for (int e = i; e < nnz; e += stride)
        atomicAdd(&g_ofs[2 * er[e] + (ec[e] >= NITEM)], 1);
}

__global__ void k_scan1()
{
    __shared__ int sm[256];
    int t = threadIdx.x;
    int idx = blockIdx.x * 256 + t;
    int v = (idx < NSEG) ? g_ofs[idx] : 0;
    sm[t] = v;
    __syncthreads();
    #pragma unroll
    for (int off = 128; off; off >>= 1) {
        if (t < off) sm[t] += sm[t + off];
        __syncthreads();
    }
    if (t == 0) g_bsum[blockIdx.x] = sm[0];
}

__global__ void k_scan2()
{
    __shared__ int sm[1024];
    int t = threadIdx.x;
    int v = (t < SCANB) ? g_bsum[t] : 0;
    sm[t] = v;
    __syncthreads();
    #pragma unroll
    for (int off = 1; off < 1024; off <<= 1) {
        int add = (t >= off) ? sm[t - off] : 0;
        __syncthreads();
        sm[t] += add;
        __syncthreads();
    }
    if (t < SCANB) g_boff[t] = sm[t] - v;
    if (t == 1023) g_rowptr[NSEG] = sm[1023];
}

__global__ void k_scan3()
{
    __shared__ int sm[256];
    int t = threadIdx.x;
    int idx = blockIdx.x * 256 + t;
    int v = (idx < NSEG) ? g_ofs[idx] : 0;
    sm[t] = v;
    __syncthreads();
    #pragma unroll
    for (int off = 1; off < 256; off <<= 1) {
        int add = (t >= off) ? sm[t - off] : 0;
        __syncthreads();
        sm[t] += add;
        __syncthreads();
    }
    int ex = sm[t] - v + g_boff[blockIdx.x];
    if (idx < NSEG) { g_rowptr[idx] = ex; g_ofs[idx] = ex; }
}

__global__ void k_scatter(const int* __restrict__ er, const int* __restrict__ ec,
                          const float* __restrict__ ev, int nnz)
{
    int i = blockIdx.x * blockDim.x + threadIdx.x;
    int stride = gridDim.x * blockDim.x;
    for (int e = i; e < nnz; e += stride) {
        int c = ec[e];
        int pos = atomicAdd(&g_ofs[2 * er[e] + (c >= NITEM)], 1);
        g_scol[pos] = c;
        g_sval[pos] = ev[e];
    }
}

// ---------------- SpMM helpers ----------------
__device__ __forceinline__ void accum_seg(const float* __restrict__ x, int s, int e,
                                          int adj, int lane, float4* acc)
{
    int i = s;
    for (; i + 1 < e; i += 2) {
        int   c0 = g_scol[i] + adj, c1 = g_scol[i + 1] + adj;
        float v0 = g_sval[i],       v1 = g_sval[i + 1];
        const float4* xa = (const float4*)(x + (size_t)c0 * EMB);
        const float4* xb = (const float4*)(x + (size_t)c1 * EMB);
        float4 a0 = __ldcg(&xa[lane]),      a1 = __ldcg(&xa[lane + 32]);
        float4 a2 = __ldcg(&xa[lane + 64]), a3 = __ldcg(&xa[lane + 96]);
        float4 b0 = __ldcg(&xb[lane]),      b1 = __ldcg(&xb[lane + 32]);
        float4 b2 = __ldcg(&xb[lane + 64]), b3 = __ldcg(&xb[lane + 96]);
        acc[0].x = fmaf(a0.x, v0, acc[0].x); acc[0].y = fmaf(a0.y, v0, acc[0].y);
        acc[0].z = fmaf(a0.z, v0, acc[0].z); acc[0].w = fmaf(a0.w, v0, acc[0].w);
        acc[1].x = fmaf(a1.x, v0, acc[1].x); acc[1].y = fmaf(a1.y, v0, acc[1].y);
        acc[1].z = fmaf(a1.z, v0, acc[1].z); acc[1].w = fmaf(a1.w, v0, acc[1].w);
        acc[2].x = fmaf(a2.x, v0, acc[2].x); acc[2].y = fmaf(a2.y, v0, acc[2].y);
        acc[2].z = fmaf(a2.z, v0, acc[2].z); acc[2].w = fmaf(a2.w, v0, acc[2].w);
        acc[3].x = fmaf(a3.x, v0, acc[3].x); acc[3].y = fmaf(a3.y, v0, acc[3].y);
        acc[3].z = fmaf(a3.z, v0, acc[3].z); acc[3].w = fmaf(a3.w, v0, acc[3].w);
        acc[0].x = fmaf(b0.x, v1, acc[0].x); acc[0].y = fmaf(b0.y, v1, acc[0].y);
        acc[0].z = fmaf(b0.z, v1, acc[0].z); acc[0].w = fmaf(b0.w, v1, acc[0].w);
        acc[1].x = fmaf(b1.x, v1, acc[1].x); acc[1].y = fmaf(b1.y, v1, acc[1].y);
        acc[1].z = fmaf(b1.z, v1, acc[1].z); acc[1].w = fmaf(b1.w, v1, acc[1].w);
        acc[2].x = fmaf(b2.x, v1, acc[2].x); acc[2].y = fmaf(b2.y, v1, acc[2].y);
        acc[2].z = fmaf(b2.z, v1, acc[2].z); acc[2].w = fmaf(b2.w, v1, acc[2].w);
        acc[3].x = fmaf(b3.x, v1, acc[3].x); acc[3].y = fmaf(b3.y, v1, acc[3].y);
        acc[3].z = fmaf(b3.z, v1, acc[3].z); acc[3].w = fmaf(b3.w, v1, acc[3].w);
    }
    if (i < e) {
        int   c0 = g_scol[i] + adj;
        float v0 = g_sval[i];
        const float4* xa = (const float4*)(x + (size_t)c0 * EMB);
        float4 a0 = __ldcg(&xa[lane]),      a1 = __ldcg(&xa[lane + 32]);
        float4 a2 = __ldcg(&xa[lane + 64]), a3 = __ldcg(&xa[lane + 96]);
        acc[0].x = fmaf(a0.x, v0, acc[0].x); acc[0].y = fmaf(a0.y, v0, acc[0].y);
        acc[0].z = fmaf(a0.z, v0, acc[0].z); acc[0].w = fmaf(a0.w, v0, acc[0].w);
        acc[1].x = fmaf(a1.x, v0, acc[1].x); acc[1].y = fmaf(a1.y, v0, acc[1].y);
        acc[1].z = fmaf(a1.z, v0, acc[1].z); acc[1].w = fmaf(a1.w, v0, acc[1].w);
        acc[2].x = fmaf(a2.x, v0, acc[2].x); acc[2].y = fmaf(a2.y, v0, acc[2].y);
        acc[2].z = fmaf(a2.z, v0, acc[2].z); acc[2].w = fmaf(a2.w, v0, acc[2].w);
        acc[3].x = fmaf(a3.x, v0, acc[3].x); acc[3].y = fmaf(a3.y, v0, acc[3].y);
        acc[3].z = fmaf(a3.z, v0, acc[3].z); acc[3].w = fmaf(a3.w, v0, acc[3].w);
    }
}

// ---------------- SpMM full: warp per row, col-half split, 2 passes ----------------
// pass0: partial sums stored; pass1: finalize side (and edis if doEdis), then
// fuse h = ego*side + oge*edis into g_hbuf.
__global__ void k_spmm_full(int srcSel, int doEdis, int pass)
{
    const float* x = (srcSel == 0) ? g_egoA : (srcSel == 1) ? g_egoB : g_egoC;
    int lane = threadIdx.x & 31;
    int warp = (int)((blockIdx.x * blockDim.x + threadIdx.x) >> 5);
    int nw   = (int)((gridDim.x * blockDim.x) >> 5);

    for (int row = warp; row < NNODES; row += nw) {
        int b0 = g_rowptr[2 * row], b1 = g_rowptr[2 * row + 1], b2 = g_rowptr[2 * row + 2];
        float4 sacc[4] = { {0,0,0,0}, {0,0,0,0}, {0,0,0,0}, {0,0,0,0} };
        if (pass == 0) accum_seg(x, b0, b1, 0, lane, sacc);
        else           accum_seg(x, b1, b2, 0, lane, sacc);

        float4* so = (float4*)(g_side + (size_t)row * EMB);
        float4* de = (float4*)(g_edis + (size_t)row * EMB);

        if (pass == 0) {
            if (doEdis) {
                float4 dacc[4] = { {0,0,0,0}, {0,0,0,0}, {0,0,0,0}, {0,0,0,0} };
                accum_seg(x, b1, b2, -NITEM, lane, dacc);
                __stcs(&de[lane], dacc[0]);       __stcs(&de[lane + 32], dacc[1]);
                __stcs(&de[lane + 64], dacc[2]);  __stcs(&de[lane + 96], dacc[3]);
            }
            __stcs(&so[lane], sacc[0]);       __stcs(&so[lane + 32], sacc[1]);
            __stcs(&so[lane + 64], sacc[2]);  __stcs(&so[lane + 96], sacc[3]);
        } else {
            // finalize edis (or read fixed edis), finalize side, fuse h
            float4 dfin[4];
            if (doEdis) {
                float4 dacc[4] = { {0,0,0,0}, {0,0,0,0}, {0,0,0,0}, {0,0,0,0} };
                accum_seg(x, b0, b1, +NITEM, lane, dacc);
                #pragma unroll
                for (int q = 0; q < 4; q++) {
                    float4 cur = __ldcs(&de[lane + 32 * q]);
                    cur.x += dacc[q].x; cur.y += dacc[q].y;
                    cur.z += dacc[q].z; cur.w += dacc[q].w;
                    __stcs(&de[lane + 32 * q], cur);
                    dfin[q] = cur;
                }
            } else {
                #pragma unroll
                for (int q = 0; q < 4; q++) dfin[q] = __ldcg(&de[lane + 32 * q]);
            }
            int rowo = (row < NITEM) ? row + NITEM : row - NITEM;
            const float4* eg = (const float4*)(x + (size_t)row * EMB);
            const float4* og = (const float4*)(g_egoA + (size_t)rowo * EMB);
            float4* ho = (float4*)(g_hbuf + (size_t)row * EMB);
            #pragma unroll
            for (int q = 0; q < 4; q++) {
                float4 s = __ldcs(&so[lane + 32 * q]);
                s.x += sacc[q].x; s.y += sacc[q].y; s.z += sacc[q].z; s.w += sacc[q].w;
                __stcs(&so[lane + 32 * q], s);
                float4 e = eg[lane + 32 * q];
                float4 o = og[lane + 32 * q];
                float4 d = dfin[q];
                float4 h;
                h.x = fmaf(e.x, s.x, o.x * d.x);
                h.y = fmaf(e.y, s.y, o.y * d.y);
                h.z = fmaf(e.z, s.z, o.z * d.z);
                h.w = fmaf(e.w, s.w, o.w * d.w);
                __stcs(&ho[lane + 32 * q], h);
            }
        }
    }
}

// ---------------- SpMM slots: warp per gathered slot (layer 2), h fused ----------------
__global__ void k_spmm_slots(const int* __restrict__ items)
{
    const float* x = g_egoC;
    int lane = threadIdx.x & 31;
    int slot = (int)((blockIdx.x * blockDim.x + threadIdx.x) >> 5);
    if (slot >= NSLOT) return;
    int row = (slot < BATCH) ? items[slot] : (items[slot - BATCH] + NITEM);
    int b0 = g_rowptr[2 * row], b2 = g_rowptr[2 * row + 2];
    float4 sacc[4] = { {0,0,0,0}, {0,0,0,0}, {0,0,0,0}, {0,0,0,0} };
    accum_seg(x, b0, b2, 0, lane, sacc);
    int rowo = (row < NITEM) ? row + NITEM : row - NITEM;
    const float4* eg = (const float4*)(x + (size_t)row * EMB);
    const float4* og = (const float4*)(g_egoA + (size_t)rowo * EMB);
    const float4* de = (const float4*)(g_edis + (size_t)row * EMB);
    float4* so = (float4*)(g_side + (size_t)row * EMB);
    float4* ho = (float4*)(g_hbuf + (size_t)row * EMB);
    #pragma unroll
    for (int q = 0; q < 4; q++) {
        float4 s = sacc[q];
        so[lane + 32 * q] = s;
        float4 e = eg[lane + 32 * q];
        float4 o = og[lane + 32 * q];
        float4 d = de[lane + 32 * q];
        float4 h;
        h.x = fmaf(e.x, s.x, o.x * d.x);
        h.y = fmaf(e.y, s.y, o.y * d.y);
        h.z = fmaf(e.z, s.z, o.z * d.z);
        h.w = fmaf(e.w, s.w, o.w * d.w);
        ho[lane + 32 * q] = h;
    }
}

// ---------------- weight transpose + bf16 hi/lo split ----------------
__global__ void k_wtconv(const float* __restrict__ Wgc, const float* __restrict__ Wgc2,
                         const float* __restrict__ Wbi, int layer)
{
    __shared__ float t[32][33];
    int kb = blockIdx.x * 32;
    int nb = blockIdx.y * 32;
    int tx = threadIdx.x & 31, ty = threadIdx.x >> 5;
    int seg = kb >> 9, kloc = kb & 511;
    const float* W = (seg == 0) ? Wgc : (seg == 1) ? Wgc2 : Wbi;
    size_t lbase = (size_t)layer * 512 * 1536;
    #pragma unroll
    for (int j = 0; j < 4; j++)
        t[ty + 8 * j][tx] = W[(size_t)(kloc + ty + 8 * j) * 512 + nb + tx];
    __syncthreads();
    #pragma unroll
    for (int j = 0; j < 4; j++) {
        int n = nb + ty + 8 * j;
        float x = t[tx][ty + 8 * j];
        __nv_bfloat16 h = __float2bfloat16_rn(x);
        g_wthi[lbase + (size_t)n * 1536 + kb + tx] = h;
        g_wtlo[lbase + (size_t)n * 1536 + kb + tx] = __float2bfloat16_rn(x - __bfloat162float(h));
    }
}

// ---------------- mma.sync bf16x3 fused GEMM, 128x256, cp.async B ----------------
// A = [side | edis | hbuf]; outSel: 0=egoB 1=egoC 2=ego3
__global__ void __launch_bounds__(512)
k_gemm(int outSel, int layer,
       const float* __restrict__ bgc, const float* __restrict__ bgc2,
       const float* __restrict__ bbi,
       int M, const int* __restrict__ items)
{
    extern __shared__ __align__(16) char smbuf[];
    const uint32_t OA_HI = 0, OA_LO = 10240, OB_HI = 20480, OB_LO = 40960;
    float* biasP = (float*)(smbuf + 2 * STAGE_SZ);
    uint32_t smb = smem_u32(smbuf);

    int tid = threadIdx.x;
    int wid = tid >> 5, lid = tid & 31;
    int col0 = blockIdx.x * 256;
    int row0 = blockIdx.y * 128;
    int wM = wid >> 2, wN = wid & 3;

    if (tid < 256) {
        int c = col0 + tid;
        biasP[tid] = bgc[c] + bgc2[c] + bbi[c];
    }

    float* Cout = (outSel == 0) ? g_egoB : (outSel == 1) ? g_egoC : g_ego3;
    const __nv_bfloat16* wthi = g_wthi + (size_t)layer * 512 * 1536;
    const __nv_bfloat16* wtlo = g_wtlo + (size_t)layer * 512 * 1536;

    int mA0 = tid >> 3, mA1 = (tid + 512) >> 3;
    int k4  = (tid & 7) * 4;
    int node0, node1;
    {
        int g0 = row0 + mA0, g1 = row0 + mA1;
        int s0 = (g0 < M) ? g0 : (M - 1);
        int s1 = (g1 < M) ? g1 : (M - 1);
        node0 = items ? ((s0 < BATCH) ? items[s0] : (items[s0 - BATCH] + NITEM)) : s0;
        node1 = items ? ((s1 < BATCH) ? items[s1] : (items[s1 - BATCH] + NITEM)) : s1;
    }
    int nB = tid >> 1, kqB = (tid & 1) * 16;

    float acc[2][8][4];
    #pragma unroll
    for (int mt = 0; mt < 2; mt++)
        #pragma unroll
        for (int nt = 0; nt < 8; nt++)
            #pragma unroll
            for (int q = 0; q < 4; q++) acc[mt][nt][q] = 0.f;

    float pa[2][4];

    auto prefetchA = [&](int c) {
        int seg = c >> 4;
        int kloc = (c & 15) * 32;
        const float* src = (seg == 0) ? g_side : (seg == 1) ? g_edis : g_hbuf;
        *(float4*)pa[0] = *(const float4*)(src + (size_t)node0 * EMB + kloc + k4);
        *(float4*)pa[1] = *(const float4*)(src + (size_t)node1 * EMB + kloc + k4);
    };

    auto storeA = [&](int stage) {
        uint32_t base = smb + stage * STAGE_SZ;
        #pragma unroll
        for (int l = 0; l < 2; l++) {
            int m = l ? mA1 : mA0;
            uint32_t ad = m * STRB + k4 * 2;
            uint32_t h0 = pack2(__float2bfloat16_rn(pa[l][0]), __float2bfloat16_rn(pa[l][1]));
            uint32_t h1 = pack2(__float2bfloat16_rn(pa[l][2]), __float2bfloat16_rn(pa[l][3]));
            uint32_t l0 = pack2(__float2bfloat16_rn(pa[l][0] - __bfloat162float(__float2bfloat16_rn(pa[l][0]))),
                                __float2bfloat16_rn(pa[l][1] - __bfloat162float(__float2bfloat16_rn(pa[l][1]))));
            uint32_t l1 = pack2(__float2bfloat16_rn(pa[l][2] - __bfloat162float(__float2bfloat16_rn(pa[l][2]))),
                                __float2bfloat16_rn(pa[l][3] - __bfloat162float(__float2bfloat16_rn(pa[l][3]))));
            asm volatile("st.shared.v2.b32 [%0], {%1,%2};" :: "r"(base + OA_HI + ad), "r"(h0), "r"(h1) : "memory");
            asm volatile("st.shared.v2.b32 [%0], {%1,%2};" :: "r"(base + OA_LO + ad), "r"(l0), "r"(l1) : "memory");
        }
    };

    auto cpasyncB = [&](int c) {
        uint32_t base = smb + (c & 1) * STAGE_SZ;
        const char* gh = (const char*)(wthi + (size_t)(col0 + nB) * 1536 + c * 32 + kqB);
        const char* gl = (const char*)(wtlo + (size_t)(col0 + nB) * 1536 + c * 32 + kqB);
        uint32_t bd  = base + OB_HI + nB * STRB + kqB * 2;
        uint32_t bdl = base + OB_LO + nB * STRB + kqB * 2;
        CP16(bd, gh);       CP16(bd + 16, gh + 16);
        CP16(bdl, gl);      CP16(bdl + 16, gl + 16);
    };

    uint32_t aOff = (uint32_t)((wM * 32 + (lid & 15)) * STRB + (lid >> 4) * 16);
    uint32_t bOff[4];
    #pragma unroll
    for (int p = 0; p < 4; p++)
        bOff[p] = (uint32_t)((wN * 64 + p * 16 + (lid & 7) + ((lid >> 4) << 3)) * STRB + (((lid >> 3) & 1) << 4));

    prefetchA(0);
    storeA(0);
    cpasyncB(0);
    CP_COMMIT();
    prefetchA(1);
    CP_WAIT0();
    __syncthreads();

    for (int c = 0; c < NCH; c++) {
        if (c + 1 < NCH) { cpasyncB(c + 1); CP_COMMIT(); }
        uint32_t sb = smb + (c & 1) * STAGE_SZ;
        #pragma unroll
        for (int kk = 0; kk < 2; kk++) {
            uint32_t ko = kk * 32;
            uint32_t ah[2][4], al[2][4];
            LDSM4(ah[0][0], ah[0][1], ah[0][2], ah[0][3], sb + OA_HI + aOff + ko);
            LDSM4(ah[1][0], ah[1][1], ah[1][2], ah[1][3], sb + OA_HI + aOff + 16 * STRB + ko);
            LDSM4(al[0][0], al[0][1], al[0][2], al[0][3], sb + OA_LO + aOff + ko);
            LDSM4(al[1][0], al[1][1], al[1][2], al[1][3], sb + OA_LO + aOff + 16 * STRB + ko);
            #pragma unroll
            for (int p = 0; p < 4; p++) {
                uint32_t bh4[4], bl4[4];
                LDSM4(bh4[0], bh4[1], bh4[2], bh4[3], sb + OB_HI + bOff[p] + ko);
                LDSM4(bl4[0], bl4[1], bl4[2], bl4[3], sb + OB_LO + bOff[p] + ko);
                #pragma unroll
                for (int mt = 0; mt < 2; mt++) {
                    MMA16816(acc[mt][2 * p],     ah[mt], (bh4 + 0));
                    MMA16816(acc[mt][2 * p + 1], ah[mt], (bh4 + 2));
                    MMA16816(acc[mt][2 * p],     ah[mt], (bl4 + 0));
                    MMA16816(acc[mt][2 * p + 1], ah[mt], (bl4 + 2));
                    MMA16816(acc[mt][2 * p],     al[mt], (bh4 + 0));
                    MMA16816(acc[mt][2 * p + 1], al[mt], (bh4 + 2));
                }
            }
        }
        if (c + 1 < NCH) {
            storeA((c + 1) & 1);
            if (c + 2 < NCH) prefetchA(c + 2);
            CP_WAIT0();
            __syncthreads();
        }
    }

    // ---- epilogue: bias + leaky_relu ----
    int rA = lid >> 2;
    int cA = (lid & 3) * 2;
    #pragma unroll
    for (int mt = 0; mt < 2; mt++) {
        #pragma unroll
        for (int half = 0; half < 2; half++) {
            int gr = row0 + wM * 32 + mt * 16 + rA + half * 8;
            if (gr < M) {
                float* cp = Cout + (size_t)gr * EMB + col0 + wN * 64;
                #pragma unroll
                for (int nt = 0; nt < 8; nt++) {
                    int cc = nt * 8 + cA;
                    float x0 = acc[mt][nt][half * 2 + 0] + biasP[wN * 64 + cc];
                    float x1 = acc[mt][nt][half * 2 + 1] + biasP[wN * 64 + cc + 1];
                    float2 o;
                    o.x = (x0 > 0.f) ? x0 : 0.2f * x0;
                    o.y = (x1 > 0.f) ? x1 : 0.2f * x1;
                    *(float2*)(cp + cc) = o;
                }
            }
        }
    }
}

// ---------------- out[slot] = ego0[node]  (acc init) ----------------
__global__ void k_out_init(const int* __restrict__ items, float* __restrict__ out)
{
    int slot = blockIdx.x;
    int node = (slot < BATCH) ? items[slot] : (items[slot - BATCH] + NITEM);
    int t = threadIdx.x;
    float4 x = *(const float4*)(g_egoA + (size_t)node * EMB + t * 4);
    *(float4*)(out + (size_t)slot * EMB + t * 4) = x;
}

// ---------------- out[slot] += normalize(src_row) ----------------
__global__ void k_norm_acc(int srcSel, const int* __restrict__ items, float* __restrict__ out)
{
    int slot = blockIdx.x;
    int node = (slot < BATCH) ? items[slot] : (items[slot - BATCH] + NITEM);
    const float* row;
    if (srcSel == 0)      row = g_egoB + (size_t)node * EMB;
    else if (srcSel == 1) row = g_egoC + (size_t)node * EMB;
    else                  row = g_ego3 + (size_t)slot * EMB;

    int t = threadIdx.x;  // 128 threads
    float4 x = *(const float4*)(row + t * 4);
    float ss = x.x * x.x + x.y * x.y + x.z * x.z + x.w * x.w;
    #pragma unroll
    for (int o = 16; o; o >>= 1) ss += __shfl_xor_sync(0xffffffffu, ss, o);
    __shared__ float ws[4];
    if ((t & 31) == 0) ws[t >> 5] = ss;
    __syncthreads();
    float tot = ws[0] + ws[1] + ws[2] + ws[3];
    float inv = 1.f / fmaxf(sqrtf(tot), 1e-12f);

    float* o4 = out + (size_t)slot * EMB + t * 4;
    float4 cur = *(float4*)o4;
    cur.x += x.x * inv; cur.y += x.y * inv; cur.z += x.z * inv; cur.w += x.w * inv;
    *(float4*)o4 = cur;
}

// ---------------- launch ----------------
extern "C" void kernel_launch(void* const* d_in, const int* in_sizes, int n_in,
                              void* d_out, int out_size)
{
    const float* vis   = (const float*)d_in[0];
    const float* txt   = (const float*)d_in[1];
    const int*   er    = (const int*)  d_in[2];
    const int*   ec    = (const int*)  d_in[3];
    const float* ev    = (const float*)d_in[4];
    const int*   items = (const int*)  d_in[5];
    const float* Wgc   = (const float*)d_in[6];
    const float* bgc   = (const float*)d_in[7];
    const float* Wgc2  = (const float*)d_in[8];
    const float* bgc2  = (const float*)d_in[9];
    const float* Wbi   = (const float*)d_in[10];
    const float* bbi   = (const float*)d_in[11];
    float* out = (float*)d_out;
    int nnz = in_sizes[2];

    cudaFuncSetAttribute(k_gemm, cudaFuncAttributeMaxDynamicSharedMemorySize, GEMM_SMEM);

    const int SPMM_B = 2048;
    dim3 gGrid(2, (NNODES + 127) / 128);   // (2, 782)
    dim3 gGrid3(2, NSLOT / 128);           // (2, 64)
    dim3 wGrid(48, 16);

    // init + CSR build (+ all weight conversions upfront)
    k_init<<<25000, 256>>>(vis, txt);
    k_zero2<<<782, 256>>>();
    k_hist<<<2048, 256>>>(er, ec, nnz);
    k_scan1<<<SCANB, 256>>>();
    k_scan2<<<1, 1024>>>();
    k_scan3<<<SCANB, 256>>>();
    k_scatter<<<2048, 256>>>(er, ec, ev, nnz);
    k_wtconv<<<wGrid, 256>>>(Wgc, Wgc2, Wbi, 0);
    k_wtconv<<<wGrid, 256>>>(Wgc + 1 * 512 * 512, Wgc2 + 1 * 512 * 512, Wbi + 1 * 512 * 512, 1);
    k_wtconv<<<wGrid, 256>>>(Wgc + 2 * 512 * 512, Wgc2 + 2 * 512 * 512, Wbi + 2 * 512 * 512, 2);

    // acc init
    k_out_init<<<NSLOT, 128>>>(items, out);

    // ---- layer 0: combined side+edis spmm (ego0 in egoA), h fused -> gemm -> egoB ----
    k_spmm_full<<<SPMM_B, 256>>>(0, 1, 0);
    k_spmm_full<<<SPMM_B, 256>>>(0, 1, 1);
    k_gemm<<<gGrid, 512, GEMM_SMEM>>>(0, 0, bgc, bgc2, bbi, NNODES, nullptr);
    k_norm_acc<<<NSLOT, 128>>>(0, items, out);

    // ---- layer 1: egoB -> egoC ----
    k_spmm_full<<<SPMM_B, 256>>>(1, 0, 0);
    k_spmm_full<<<SPMM_B, 256>>>(1, 0, 1);
    k_gemm<<<gGrid, 512, GEMM_SMEM>>>(1, 1, bgc + 512, bgc2 + 512, bbi + 512, NNODES, nullptr);
    k_norm_acc<<<NSLOT, 128>>>(1, items, out);

    // ---- layer 2 (subset): egoC -> ego3 (gathered slots) ----
    k_spmm_slots<<<1024, 256>>>(items);
    k_gemm<<<gGrid3, 512, GEMM_SMEM>>>(2, 2, bgc + 1024, bgc2 + 1024, bbi + 1024, NSLOT, items);
    k_norm_acc<<<NSLOT, 128>>>(2, items, out);
}

// round 10
// speedup vs baseline: 3.3506x; 1.1445x over previous
#include <cuda_runtime.h>
#include <cuda_bf16.h>
#include <cuda_fp16.h>
#include <math.h>
#include <stdint.h>

#define NITEM   50000
#define NNODES  100000
#define NSEG    200000      // 2 * NNODES (row, col-half) segments
#define EMB     512
#define BATCH   4096
#define NSLOT   8192
#define NNZMAX  3200000
#define NCH     48          // 1536 / 32 K-chunks
#define STRB    80          // smem row stride bytes (40 halves)
#define STAGE_SZ 61440      // A hi/lo 20KB + B hi/lo 40KB
#define GEMM_SMEM 123904    // 2 stages + 1KB bias
#define SCANB   782         // scan blocks (782*256 >= NSEG)

// ---------------- static device scratch ----------------
__device__ float g_egoA[51200000];   // ego0 = [vision;text], preserved
__device__ float g_egoB[51200000];   // layer-1 activations
__device__ float g_egoC[51200000];   // layer-2 activations
__device__ float g_edis[51200000];
__device__ float g_side[51200000];
__device__ float g_hbuf[51200000];   // h = ego*side + oge*edis (fused in spmm)
__device__ float g_ego3[4194304];    // 8192 x 512
__device__ __half g_a16[51200000];   // fp16 copy of ego0 (gather source, layer 0)
__device__ __half g_x16[51200000];   // fp16 copy of current layer ego (gather source)
__device__ int   g_rowptr[NSEG + 1];
__device__ int   g_ofs[NSEG];
__device__ int   g_bsum[1024];
__device__ int   g_boff[1024];
__device__ int   g_scol[NNZMAX];
__device__ float g_sval[NNZMAX];
__device__ __nv_bfloat16 g_wthi[3 * 512 * 1536];  // W^T hi, [layer][N][K] K-contig
__device__ __nv_bfloat16 g_wtlo[3 * 512 * 1536];  // W^T lo

__device__ __forceinline__ uint32_t smem_u32(const void* p) {
    uint32_t a;
    asm("{ .reg .u64 t; cvta.to.shared.u64 t, %1; cvt.u32.u64 %0, t; }" : "=r"(a) : "l"(p));
    return a;
}
#define LDSM4(r0,r1,r2,r3,addr) \
    asm volatile("ldmatrix.sync.aligned.m8n8.x4.shared.b16 {%0,%1,%2,%3}, [%4];" \
                 : "=r"(r0),"=r"(r1),"=r"(r2),"=r"(r3) : "r"(addr))
#define MMA16816(d,a,b) \
    asm volatile("mma.sync.aligned.m16n8k16.row.col.f32.bf16.bf16.f32 " \
                 "{%0,%1,%2,%3}, {%4,%5,%6,%7}, {%8,%9}, {%0,%1,%2,%3};" \
                 : "+f"(d[0]),"+f"(d[1]),"+f"(d[2]),"+f"(d[3]) \
                 : "r"(a[0]),"r"(a[1]),"r"(a[2]),"r"(a[3]), "r"(b[0]),"r"(b[1]))
#define CP16(smaddr, gptr) \
    asm volatile("cp.async.ca.shared.global [%0], [%1], 16;" :: "r"(smaddr), "l"(gptr) : "memory")
#define CP_COMMIT() asm volatile("cp.async.commit_group;" ::: "memory")
#define CP_WAIT0()  asm volatile("cp.async.wait_group 0;" ::: "memory")

__device__ __forceinline__ uint32_t pack2(__nv_bfloat16 a, __nv_bfloat16 b) {
    __nv_bfloat162 p = __halves2bfloat162(a, b);
    return *reinterpret_cast<uint32_t*>(&p);
}

// ---------------- init: ego0 = [vision;text] (fp32 + fp16 copy) ----------------
__global__ void k_init(const float* __restrict__ vis, const float* __restrict__ txt)
{
    size_t i = (size_t)blockIdx.x * blockDim.x + threadIdx.x;
    size_t half = (size_t)NITEM * EMB / 4;
    if (i >= half) return;
    float4 v = ((const float4*)vis)[i];
    float4 t = ((const float4*)txt)[i];
    ((float4*)g_egoA)[i]        = v;
    ((float4*)g_egoA)[half + i] = t;
    __half2 hv[2] = { __floats2half2_rn(v.x, v.y), __floats2half2_rn(v.z, v.w) };
    __half2 ht[2] = { __floats2half2_rn(t.x, t.y), __floats2half2_rn(t.z, t.w) };
    *(uint2*)(g_a16 + 4 * i)              = *(uint2*)hv;
    *(uint2*)(g_a16 + 4 * (half + i))     = *(uint2*)ht;
}

__global__ void k_zero2()
{
    int i = blockIdx.x * blockDim.x + threadIdx.x;
    if (i < NSEG) g_ofs[i] = 0;
}

// ---------------- CSR build: key = 2*row + (col >= NITEM) ----------------
__global__ void k_hist(const int* __restrict__ er, const int* __restrict__ ec, int nnz)
{
    int i = blockIdx.x * blockDim.x + threadIdx.x;
    int stride = gridDim.x * blockDim.x;
    for (int e = i; e < nnz; e += stride)
        atomicAdd(&g_ofs[2 * er[e] + (ec[e] >= NITEM)], 1);
}

__global__ void k_scan1()
{
    __shared__ int sm[256];
    int t = threadIdx.x;
    int idx = blockIdx.x * 256 + t;
    int v = (idx < NSEG) ? g_ofs[idx] : 0;
    sm[t] = v;
    __syncthreads();
    #pragma unroll
    for (int off = 128; off; off >>= 1) {
        if (t < off) sm[t] += sm[t + off];
        __syncthreads();
    }
    if (t == 0) g_bsum[blockIdx.x] = sm[0];
}

__global__ void k_scan2()
{
    __shared__ int sm[1024];
    int t = threadIdx.x;
    int v = (t < SCANB) ? g_bsum[t] : 0;
    sm[t] = v;
    __syncthreads();
    #pragma unroll
    for (int off = 1; off < 1024; off <<= 1) {
        int add = (t >= off) ? sm[t - off] : 0;
        __syncthreads();
        sm[t] += add;
        __syncthreads();
    }
    if (t < SCANB) g_boff[t] = sm[t] - v;
    if (t == 1023) g_rowptr[NSEG] = sm[1023];
}

__global__ void k_scan3()
{
    __shared__ int sm[256];
    int t = threadIdx.x;
    int idx = blockIdx.x * 256 + t;
    int v = (idx < NSEG) ? g_ofs[idx] : 0;
    sm[t] = v;
    __syncthreads();
    #pragma unroll
    for (int off = 1; off < 256; off <<= 1) {
        int add = (t >= off) ? sm[t - off] : 0;
        __syncthreads();
        sm[t] += add;
        __syncthreads();
    }
    int ex = sm[t] - v + g_boff[blockIdx.x];
    if (idx < NSEG) { g_rowptr[idx] = ex; g_ofs[idx] = ex; }
}

__global__ void k_scatter(const int* __restrict__ er, const int* __restrict__ ec,
                          const float* __restrict__ ev, int nnz)
{
    int i = blockIdx.x * blockDim.x + threadIdx.x;
    int stride = gridDim.x * blockDim.x;
    for (int e = i; e < nnz; e += stride) {
        int c = ec[e];
        int pos = atomicAdd(&g_ofs[2 * er[e] + (c >= NITEM)], 1);
        g_scol[pos] = c;
        g_sval[pos] = ev[e];
    }
}

// ---------------- SpMM helpers (fp16 gathers, fp32 accumulate) ----------------
// Per-lane layout: f[0..7]  = elements [8*lane,   8*lane+8)
//                  f[8..15] = elements [256+8*lane, 256+8*lane+8)
__device__ __forceinline__ void fma8(float* f, uint4 u, float v)
{
    const __half2* h = (const __half2*)&u;
    #pragma unroll
    for (int j = 0; j < 4; j++) {
        float2 t = __half22float2(h[j]);
        f[2 * j]     = fmaf(t.x, v, f[2 * j]);
        f[2 * j + 1] = fmaf(t.y, v, f[2 * j + 1]);
    }
}

__device__ __forceinline__ void accum16(const __half* __restrict__ x, int s, int e,
                                        int adj, int lane, float* f)
{
    int i = s;
    for (; i + 1 < e; i += 2) {
        int   c0 = g_scol[i] + adj, c1 = g_scol[i + 1] + adj;
        float v0 = g_sval[i],       v1 = g_sval[i + 1];
        const uint4* xa = (const uint4*)(x + (size_t)c0 * EMB);
        const uint4* xb = (const uint4*)(x + (size_t)c1 * EMB);
        uint4 a0 = __ldcg(&xa[lane]), a1 = __ldcg(&xa[lane + 32]);
        uint4 b0 = __ldcg(&xb[lane]), b1 = __ldcg(&xb[lane + 32]);
        fma8(f,     a0, v0); fma8(f + 8, a1, v0);
        fma8(f,     b0, v1); fma8(f + 8, b1, v1);
    }
    if (i < e) {
        int   c0 = g_scol[i] + adj;
        float v0 = g_sval[i];
        const uint4* xa = (const uint4*)(x + (size_t)c0 * EMB);
        uint4 a0 = __ldcg(&xa[lane]), a1 = __ldcg(&xa[lane + 32]);
        fma8(f, a0, v0); fma8(f + 8, a1, v0);
    }
}

// ---------------- SpMM full: warp per row, col-half split, 2 passes ----------------
// srcSel: 0 = layer0 (x16=g_a16, ego=g_egoA), 1 = layer1 (x16=g_x16, ego=g_egoB)
// pass0: partial sums stored; pass1: finalize side (and edis if doEdis), fuse h.
__global__ void k_spmm_full(int srcSel, int doEdis, int pass)
{
    const __half* x16 = srcSel ? g_x16 : g_a16;
    const float* egoF = srcSel ? g_egoB : g_egoA;
    int lane = threadIdx.x & 31;
    int warp = (int)((blockIdx.x * blockDim.x + threadIdx.x) >> 5);
    int nw   = (int)((gridDim.x * blockDim.x) >> 5);

    int fi0 = 2 * lane, fi1 = 2 * lane + 1, fi2 = 2 * lane + 64, fi3 = 2 * lane + 65;
    int fi[4] = { fi0, fi1, fi2, fi3 };

    for (int row = warp; row < NNODES; row += nw) {
        int b0 = g_rowptr[2 * row], b1 = g_rowptr[2 * row + 1], b2 = g_rowptr[2 * row + 2];
        float sacc[16];
        #pragma unroll
        for (int q = 0; q < 16; q++) sacc[q] = 0.f;
        if (pass == 0) accum16(x16, b0, b1, 0, lane, sacc);
        else           accum16(x16, b1, b2, 0, lane, sacc);

        float4* so = (float4*)(g_side + (size_t)row * EMB);
        float4* de = (float4*)(g_edis + (size_t)row * EMB);

        if (pass == 0) {
            if (doEdis) {
                float dacc[16];
                #pragma unroll
                for (int q = 0; q < 16; q++) dacc[q] = 0.f;
                accum16(x16, b1, b2, -NITEM, lane, dacc);
                #pragma unroll
                for (int q = 0; q < 4; q++)
                    __stcs(&de[fi[q]], *(float4*)(dacc + 4 * q));
            }
            #pragma unroll
            for (int q = 0; q < 4; q++)
                __stcs(&so[fi[q]], *(float4*)(sacc + 4 * q));
        } else {
            float4 dfin[4];
            if (doEdis) {
                float dacc[16];
                #pragma unroll
                for (int q = 0; q < 16; q++) dacc[q] = 0.f;
                accum16(x16, b0, b1, +NITEM, lane, dacc);
                #pragma unroll
                for (int q = 0; q < 4; q++) {
                    float4 cur = __ldcs(&de[fi[q]]);
                    cur.x += dacc[4 * q + 0]; cur.y += dacc[4 * q + 1];
                    cur.z += dacc[4 * q + 2]; cur.w += dacc[4 * q + 3];
                    __stcs(&de[fi[q]], cur);
                    dfin[q] = cur;
                }
            } else {
                #pragma unroll
                for (int q = 0; q < 4; q++) dfin[q] = __ldcg(&de[fi[q]]);
            }
            int rowo = (row < NITEM) ? row + NITEM : row - NITEM;
            const float4* eg = (const float4*)(egoF + (size_t)row * EMB);
            const float4* og = (const float4*)(g_egoA + (size_t)rowo * EMB);
            float4* ho = (float4*)(g_hbuf + (size_t)row * EMB);
            #pragma unroll
            for (int q = 0; q < 4; q++) {
                float4 s = __ldcs(&so[fi[q]]);
                s.x += sacc[4 * q + 0]; s.y += sacc[4 * q + 1];
                s.z += sacc[4 * q + 2]; s.w += sacc[4 * q + 3];
                __stcs(&so[fi[q]], s);
                float4 e = eg[fi[q]];
                float4 o = og[fi[q]];
                float4 d = dfin[q];
                float4 h;
                h.x = fmaf(e.x, s.x, o.x * d.x);
                h.y = fmaf(e.y, s.y, o.y * d.y);
                h.z = fmaf(e.z, s.z, o.z * d.z);
                h.w = fmaf(e.w, s.w, o.w * d.w);
                __stcs(&ho[fi[q]], h);
            }
        }
    }
}

// ---------------- SpMM slots: warp per gathered slot (layer 2), h fused ----------------
__global__ void k_spmm_slots(const int* __restrict__ items)
{
    int lane = threadIdx.x & 31;
    int slot = (int)((blockIdx.x * blockDim.x + threadIdx.x) >> 5);
    if (slot >= NSLOT) return;
    int row = (slot < BATCH) ? items[slot] : (items[slot - BATCH] + NITEM);
    int b0 = g_rowptr[2 * row], b2 = g_rowptr[2 * row + 2];
    float sacc[16];
    #pragma unroll
    for (int q = 0; q < 16; q++) sacc[q] = 0.f;
    accum16(g_x16, b0, b2, 0, lane, sacc);
    int fi[4] = { 2 * lane, 2 * lane + 1, 2 * lane + 64, 2 * lane + 65 };
    int rowo = (row < NITEM) ? row + NITEM : row - NITEM;
    const float4* eg = (const float4*)(g_egoC + (size_t)row * EMB);
    const float4* og = (const float4*)(g_egoA + (size_t)rowo * EMB);
    const float4* de = (const float4*)(g_edis + (size_t)row * EMB);
    float4* so = (float4*)(g_side + (size_t)row * EMB);
    float4* ho = (float4*)(g_hbuf + (size_t)row * EMB);
    #pragma unroll
    for (int q = 0; q < 4; q++) {
        float4 s = *(float4*)(sacc + 4 * q);
        so[fi[q]] = s;
        float4 e = eg[fi[q]];
        float4 o = og[fi[q]];
        float4 d = de[fi[q]];
        float4 h;
        h.x = fmaf(e.x, s.x, o.x * d.x);
        h.y = fmaf(e.y, s.y, o.y * d.y);
        h.z = fmaf(e.z, s.z, o.z * d.z);
        h.w = fmaf(e.w, s.w, o.w * d.w);
        ho[fi[q]] = h;
    }
}

// ---------------- weight transpose + bf16 hi/lo split ----------------
__global__ void k_wtconv(const float* __restrict__ Wgc, const float* __restrict__ Wgc2,
                         const float* __restrict__ Wbi, int layer)
{
    __shared__ float t[32][33];
    int kb = blockIdx.x * 32;
    int nb = blockIdx.y * 32;
    int tx = threadIdx.x & 31, ty = threadIdx.x >> 5;
    int seg = kb >> 9, kloc = kb & 511;
    const float* W = (seg == 0) ? Wgc : (seg == 1) ? Wgc2 : Wbi;
    size_t lbase = (size_t)layer * 512 * 1536;
    #pragma unroll
    for (int j = 0; j < 4; j++)
        t[ty + 8 * j][tx] = W[(size_t)(kloc + ty + 8 * j) * 512 + nb + tx];
    __syncthreads();
    #pragma unroll
    for (int j = 0; j < 4; j++) {
        int n = nb + ty + 8 * j;
        float x = t[tx][ty + 8 * j];
        __nv_bfloat16 h = __float2bfloat16_rn(x);
        g_wthi[lbase + (size_t)n * 1536 + kb + tx] = h;
        g_wtlo[lbase + (size_t)n * 1536 + kb + tx] = __float2bfloat16_rn(x - __bfloat162float(h));
    }
}

// ---------------- mma.sync bf16x3 fused GEMM, 128x256, cp.async B ----------------
// A = [side | edis | hbuf]; outSel: 0=egoB 1=egoC 2=ego3
// outSel<2 also writes fp16 copy of the output to g_x16 (next layer's gather source).
__global__ void __launch_bounds__(512)
k_gemm(int outSel, int layer,
       const float* __restrict__ bgc, const float* __restrict__ bgc2,
       const float* __restrict__ bbi,
       int M, const int* __restrict__ items)
{
    extern __shared__ __align__(16) char smbuf[];
    const uint32_t OA_HI = 0, OA_LO = 10240, OB_HI = 20480, OB_LO = 40960;
    float* biasP = (float*)(smbuf + 2 * STAGE_SZ);
    uint32_t smb = smem_u32(smbuf);

    int tid = threadIdx.x;
    int wid = tid >> 5, lid = tid & 31;
    int col0 = blockIdx.x * 256;
    int row0 = blockIdx.y * 128;
    int wM = wid >> 2, wN = wid & 3;

    if (tid < 256) {
        int c = col0 + tid;
        biasP[tid] = bgc[c] + bgc2[c] + bbi[c];
    }

    float* Cout = (outSel == 0) ? g_egoB : (outSel == 1) ? g_egoC : g_ego3;
    const __nv_bfloat16* wthi = g_wthi + (size_t)layer * 512 * 1536;
    const __nv_bfloat16* wtlo = g_wtlo + (size_t)layer * 512 * 1536;

    int mA0 = tid >> 3, mA1 = (tid + 512) >> 3;
    int k4  = (tid & 7) * 4;
    int node0, node1;
    {
        int g0 = row0 + mA0, g1 = row0 + mA1;
        int s0 = (g0 < M) ? g0 : (M - 1);
        int s1 = (g1 < M) ? g1 : (M - 1);
        node0 = items ? ((s0 < BATCH) ? items[s0] : (items[s0 - BATCH] + NITEM)) : s0;
        node1 = items ? ((s1 < BATCH) ? items[s1] : (items[s1 - BATCH] + NITEM)) : s1;
    }
    int nB = tid >> 1, kqB = (tid & 1) * 16;

    float acc[2][8][4];
    #pragma unroll
    for (int mt = 0; mt < 2; mt++)
        #pragma unroll
        for (int nt = 0; nt < 8; nt++)
            #pragma unroll
            for (int q = 0; q < 4; q++) acc[mt][nt][q] = 0.f;

    float pa[2][4];

    auto prefetchA = [&](int c) {
        int seg = c >> 4;
        int kloc = (c & 15) * 32;
        const float* src = (seg == 0) ? g_side : (seg == 1) ? g_edis : g_hbuf;
        *(float4*)pa[0] = *(const float4*)(src + (size_t)node0 * EMB + kloc + k4);
        *(float4*)pa[1] = *(const float4*)(src + (size_t)node1 * EMB + kloc + k4);
    };

    auto storeA = [&](int stage) {
        uint32_t base = smb + stage * STAGE_SZ;
        #pragma unroll
        for (int l = 0; l < 2; l++) {
            int m = l ? mA1 : mA0;
            uint32_t ad = m * STRB + k4 * 2;
            uint32_t h0 = pack2(__float2bfloat16_rn(pa[l][0]), __float2bfloat16_rn(pa[l][1]));
            uint32_t h1 = pack2(__float2bfloat16_rn(pa[l][2]), __float2bfloat16_rn(pa[l][3]));
            uint32_t l0 = pack2(__float2bfloat16_rn(pa[l][0] - __bfloat162float(__float2bfloat16_rn(pa[l][0]))),
                                __float2bfloat16_rn(pa[l][1] - __bfloat162float(__float2bfloat16_rn(pa[l][1]))));
            uint32_t l1 = pack2(__float2bfloat16_rn(pa[l][2] - __bfloat162float(__float2bfloat16_rn(pa[l][2]))),
                                __float2bfloat16_rn(pa[l][3] - __bfloat162float(__float2bfloat16_rn(pa[l][3]))));
            asm volatile("st.shared.v2.b32 [%0], {%1,%2};" :: "r"(base + OA_HI + ad), "r"(h0), "r"(h1) : "memory");
            asm volatile("st.shared.v2.b32 [%0], {%1,%2};" :: "r"(base + OA_LO + ad), "r"(l0), "r"(l1) : "memory");
        }
    };

    auto cpasyncB = [&](int c) {
        uint32_t base = smb + (c & 1) * STAGE_SZ;
        const char* gh = (const char*)(wthi + (size_t)(col0 + nB) * 1536 + c * 32 + kqB);
        const char* gl = (const char*)(wtlo + (size_t)(col0 + nB) * 1536 + c * 32 + kqB);
        uint32_t bd  = base + OB_HI + nB * STRB + kqB * 2;
        uint32_t bdl = base + OB_LO + nB * STRB + kqB * 2;
        CP16(bd, gh);       CP16(bd + 16, gh + 16);
        CP16(bdl, gl);      CP16(bdl + 16, gl + 16);
    };

    uint32_t aOff = (uint32_t)((wM * 32 + (lid & 15)) * STRB + (lid >> 4) * 16);
    uint32_t bOff[4];
    #pragma unroll
    for (int p = 0; p < 4; p++)
        bOff[p] = (uint32_t)((wN * 64 + p * 16 + (lid & 7) + ((lid >> 4) << 3)) * STRB + (((lid >> 3) & 1) << 4));

    prefetchA(0);
    storeA(0);
    cpasyncB(0);
    CP_COMMIT();
    prefetchA(1);
    CP_WAIT0();
    __syncthreads();

    for (int c = 0; c < NCH; c++) {
        if (c + 1 < NCH) { cpasyncB(c + 1); CP_COMMIT(); }
        uint32_t sb = smb + (c & 1) * STAGE_SZ;
        #pragma unroll
        for (int kk = 0; kk < 2; kk++) {
            uint32_t ko = kk * 32;
            uint32_t ah[2][4], al[2][4];
            LDSM4(ah[0][0], ah[0][1], ah[0][2], ah[0][3], sb + OA_HI + aOff + ko);
            LDSM4(ah[1][0], ah[1][1], ah[1][2], ah[1][3], sb + OA_HI + aOff + 16 * STRB + ko);
            LDSM4(al[0][0], al[0][1], al[0][2], al[0][3], sb + OA_LO + aOff + ko);
            LDSM4(al[1][0], al[1][1], al[1][2], al[1][3], sb + OA_LO + aOff + 16 * STRB + ko);
            #pragma unroll
            for (int p = 0; p < 4; p++) {
                uint32_t bh4[4], bl4[4];
                LDSM4(bh4[0], bh4[1], bh4[2], bh4[3], sb + OB_HI + bOff[p] + ko);
                LDSM4(bl4[0], bl4[1], bl4[2], bl4[3], sb + OB_LO + bOff[p] + ko);
                #pragma unroll
                for (int mt = 0; mt < 2; mt++) {
                    MMA16816(acc[mt][2 * p],     ah[mt], (bh4 + 0));
                    MMA16816(acc[mt][2 * p + 1], ah[mt], (bh4 + 2));
                    MMA16816(acc[mt][2 * p],     ah[mt], (bl4 + 0));
                    MMA16816(acc[mt][2 * p + 1], ah[mt], (bl4 + 2));
                    MMA16816(acc[mt][2 * p],     al[mt], (bh4 + 0));
                    MMA16816(acc[mt][2 * p + 1], al[mt], (bh4 + 2));
                }
            }
        }
        if (c + 1 < NCH) {
            storeA((c + 1) & 1);
            if (c + 2 < NCH) prefetchA(c + 2);
            CP_WAIT0();
            __syncthreads();
        }
    }

    // ---- epilogue: bias + leaky_relu (fp32 out + fp16 gather copy) ----
    int rA = lid >> 2;
    int cA = (lid & 3) * 2;
    #pragma unroll
    for (int mt = 0; mt < 2; mt++) {
        #pragma unroll
        for (int half = 0; half < 2; half++) {
            int gr = row0 + wM * 32 + mt * 16 + rA + half * 8;
            if (gr < M) {
                float* cp = Cout + (size_t)gr * EMB + col0 + wN * 64;
                __half* hp = g_x16 + (size_t)gr * EMB + col0 + wN * 64;
                #pragma unroll
                for (int nt = 0; nt < 8; nt++) {
                    int cc = nt * 8 + cA;
                    float x0 = acc[mt][nt][half * 2 + 0] + biasP[wN * 64 + cc];
                    float x1 = acc[mt][nt][half * 2 + 1] + biasP[wN * 64 + cc + 1];
                    float2 o;
                    o.x = (x0 > 0.f) ? x0 : 0.2f * x0;
                    o.y = (x1 > 0.f) ? x1 : 0.2f * x1;
                    *(float2*)(cp + cc) = o;
                    if (outSel < 2)
                        *(__half2*)(hp + cc) = __floats2half2_rn(o.x, o.y);
                }
            }
        }
    }
}

// ---------------- out[slot] = ego0[node]  (acc init) ----------------
__global__ void k_out_init(const int* __restrict__ items, float* __restrict__ out)
{
    int slot = blockIdx.x;
    int node = (slot < BATCH) ? items[slot] : (items[slot - BATCH] + NITEM);
    int t = threadIdx.x;
    float4 x = *(const float4*)(g_egoA + (size_t)node * EMB + t * 4);
    *(float4*)(out + (size_t)slot * EMB + t * 4) = x;
}

// ---------------- out[slot] += normalize(src_row) ----------------
__global__ void k_norm_acc(int srcSel, const int* __restrict__ items, float* __restrict__ out)
{
    int slot = blockIdx.x;
    int node = (slot < BATCH) ? items[slot] : (items[slot - BATCH] + NITEM);
    const float* row;
    if (srcSel == 0)      row = g_egoB + (size_t)node * EMB;
    else if (srcSel == 1) row = g_egoC + (size_t)node * EMB;
    else                  row = g_ego3 + (size_t)slot * EMB;

    int t = threadIdx.x;  // 128 threads
    float4 x = *(const float4*)(row + t * 4);
    float ss = x.x * x.x + x.y * x.y + x.z * x.z + x.w * x.w;
    #pragma unroll
    for (int o = 16; o; o >>= 1) ss += __shfl_xor_sync(0xffffffffu, ss, o);
    __shared__ float ws[4];
    if ((t & 31) == 0) ws[t >> 5] = ss;
    __syncthreads();
    float tot = ws[0] + ws[1] + ws[2] + ws[3];
    float inv = 1.f / fmaxf(sqrtf(tot), 1e-12f);

    float* o4 = out + (size_t)slot * EMB + t * 4;
    float4 cur = *(float4*)o4;
    cur.x += x.x * inv; cur.y += x.y * inv; cur.z += x.z * inv; cur.w += x.w * inv;
    *(float4*)o4 = cur;
}

// ---------------- launch ----------------
extern "C" void kernel_launch(void* const* d_in, const int* in_sizes, int n_in,
                              void* d_out, int out_size)
{
    const float* vis   = (const float*)d_in[0];
    const float* txt   = (const float*)d_in[1];
    const int*   er    = (const int*)  d_in[2];
    const int*   ec    = (const int*)  d_in[3];
    const float* ev    = (const float*)d_in[4];
    const int*   items = (const int*)  d_in[5];
    const float* Wgc   = (const float*)d_in[6];
    const float* bgc   = (const float*)d_in[7];
    const float* Wgc2  = (const float*)d_in[8];
    const float* bgc2  = (const float*)d_in[9];
    const float* Wbi   = (const float*)d_in[10];
    const float* bbi   = (const float*)d_in[11];
    float* out = (float*)d_out;
    int nnz = in_sizes[2];

    cudaFuncSetAttribute(k_gemm, cudaFuncAttributeMaxDynamicSharedMemorySize, GEMM_SMEM);

    const int SPMM_B = 2048;
    dim3 gGrid(2, (NNODES + 127) / 128);   // (2, 782)
    dim3 gGrid3(2, NSLOT / 128);           // (2, 64)
    dim3 wGrid(48, 16);

    // init + CSR build (+ all weight conversions upfront)
    k_init<<<25000, 256>>>(vis, txt);
    k_zero2<<<782, 256>>>();
    k_hist<<<2048, 256>>>(er, ec, nnz);
    k_scan1<<<SCANB, 256>>>();
    k_scan2<<<1, 1024>>>();
    k_scan3<<<SCANB, 256>>>();
    k_scatter<<<2048, 256>>>(er, ec, ev, nnz);
    k_wtconv<<<wGrid, 256>>>(Wgc, Wgc2, Wbi, 0);
    k_wtconv<<<wGrid, 256>>>(Wgc + 1 * 512 * 512, Wgc2 + 1 * 512 * 512, Wbi + 1 * 512 * 512, 1);
    k_wtconv<<<wGrid, 256>>>(Wgc + 2 * 512 * 512, Wgc2 + 2 * 512 * 512, Wbi + 2 * 512 * 512, 2);

    // acc init
    k_out_init<<<NSLOT, 128>>>(items, out);

    // ---- layer 0: combined side+edis spmm (fp16 gathers from g_a16), h fused -> gemm -> egoB + g_x16 ----
    k_spmm_full<<<SPMM_B, 256>>>(0, 1, 0);
    k_spmm_full<<<SPMM_B, 256>>>(0, 1, 1);
    k_gemm<<<gGrid, 512, GEMM_SMEM>>>(0, 0, bgc, bgc2, bbi, NNODES, nullptr);
    k_norm_acc<<<NSLOT, 128>>>(0, items, out);

    // ---- layer 1: gathers from g_x16 (egoB fp16) -> gemm -> egoC + g_x16 ----
    k_spmm_full<<<SPMM_B, 256>>>(1, 0, 0);
    k_spmm_full<<<SPMM_B, 256>>>(1, 0, 1);
    k_gemm<<<gGrid, 512, GEMM_SMEM>>>(1, 1, bgc + 512, bgc2 + 512, bbi + 512, NNODES, nullptr);
    k_norm_acc<<<NSLOT, 128>>>(1, items, out);

    // ---- layer 2 (subset): gathers from g_x16 (egoC fp16) -> ego3 (gathered slots) ----
    k_spmm_slots<<<1024, 256>>>(items);
    k_gemm<<<gGrid3, 512, GEMM_SMEM>>>(2, 2, bgc + 1024, bgc2 + 1024, bbi + 1024, NSLOT, items);
    k_norm_acc<<<NSLOT, 128>>>(2, items, out);
}

// round 11
// speedup vs baseline: 5.3249x; 1.5892x over previous
#include <cuda_runtime.h>
#include <cuda_bf16.h>
#include <cuda_fp16.h>
#include <math.h>
#include <stdint.h>

#define NITEM   50000
#define NNODES  100000
#define NSEG    200000      // 2 * NNODES (row, col-half) segments
#define EMB     512
#define BATCH   4096
#define NSLOT   8192
#define NNZMAX  3200000
#define NCH     48          // 1536 / 32 K-chunks
#define STRB    80          // smem row stride bytes (40 halves)
#define STAGE_SZ 30720      // A 10KB + B 20KB (fp16 single)
#define GEMM_SMEM 62464     // 2 stages + 1KB bias
#define SCANB   782         // scan blocks (782*256 >= NSEG)

// ---------------- static device scratch ----------------
__device__ float g_egoA[51200000];   // ego0 = [vision;text], preserved
__device__ float g_egoB[51200000];   // layer-1 activations
__device__ float g_egoC[51200000];   // layer-2 activations
__device__ float g_edis[51200000];
__device__ float g_side[51200000];
__device__ float g_hbuf[51200000];   // h = ego*side + oge*edis (fused in spmm)
__device__ float g_ego3[4194304];    // 8192 x 512
__device__ __half g_a16[51200000];   // fp16 copy of ego0 (gather source, layer 0)
__device__ __half g_x16[51200000];   // fp16 copy of current layer ego (gather source)
__device__ int   g_rowptr[NSEG + 1];
__device__ int   g_ofs[NSEG];
__device__ int   g_bsum[1024];
__device__ int   g_boff[1024];
__device__ int   g_scol[NNZMAX];
__device__ float g_sval[NNZMAX];
__device__ __half g_wt16[3 * 512 * 1536];  // W^T fp16, [layer][N][K] K-contig

__device__ __forceinline__ uint32_t smem_u32(const void* p) {
    uint32_t a;
    asm("{ .reg .u64 t; cvta.to.shared.u64 t, %1; cvt.u32.u64 %0, t; }" : "=r"(a) : "l"(p));
    return a;
}
#define LDSM4(r0,r1,r2,r3,addr) \
    asm volatile("ldmatrix.sync.aligned.m8n8.x4.shared.b16 {%0,%1,%2,%3}, [%4];" \
                 : "=r"(r0),"=r"(r1),"=r"(r2),"=r"(r3) : "r"(addr))
#define MMAF16(d,a,b) \
    asm volatile("mma.sync.aligned.m16n8k16.row.col.f32.f16.f16.f32 " \
                 "{%0,%1,%2,%3}, {%4,%5,%6,%7}, {%8,%9}, {%0,%1,%2,%3};" \
                 : "+f"(d[0]),"+f"(d[1]),"+f"(d[2]),"+f"(d[3]) \
                 : "r"(a[0]),"r"(a[1]),"r"(a[2]),"r"(a[3]), "r"(b[0]),"r"(b[1]))
#define CP16(smaddr, gptr) \
    asm volatile("cp.async.ca.shared.global [%0], [%1], 16;" :: "r"(smaddr), "l"(gptr) : "memory")
#define CP_COMMIT() asm volatile("cp.async.commit_group;" ::: "memory")
#define CP_WAIT0()  asm volatile("cp.async.wait_group 0;" ::: "memory")

__device__ __forceinline__ uint32_t packh2(float a, float b) {
    __half2 p = __floats2half2_rn(a, b);
    return *reinterpret_cast<uint32_t*>(&p);
}

// ---------------- init: ego0 = [vision;text] (fp32 + fp16 copy) ----------------
__global__ void k_init(const float* __restrict__ vis, const float* __restrict__ txt)
{
    size_t i = (size_t)blockIdx.x * blockDim.x + threadIdx.x;
    size_t half = (size_t)NITEM * EMB / 4;
    if (i >= half) return;
    float4 v = ((const float4*)vis)[i];
    float4 t = ((const float4*)txt)[i];
    ((float4*)g_egoA)[i]        = v;
    ((float4*)g_egoA)[half + i] = t;
    __half2 hv[2] = { __floats2half2_rn(v.x, v.y), __floats2half2_rn(v.z, v.w) };
    __half2 ht[2] = { __floats2half2_rn(t.x, t.y), __floats2half2_rn(t.z, t.w) };
    *(uint2*)(g_a16 + 4 * i)              = *(uint2*)hv;
    *(uint2*)(g_a16 + 4 * (half + i))     = *(uint2*)ht;
}

__global__ void k_zero2()
{
    int i = blockIdx.x * blockDim.x + threadIdx.x;
    if (i < NSEG) g_ofs[i] = 0;
}

// ---------------- CSR build: key = 2*row + (col >= NITEM) ----------------
__global__ void k_hist(const int* __restrict__ er, const int* __restrict__ ec, int nnz)
{
    int i = blockIdx.x * blockDim.x + threadIdx.x;
    int stride = gridDim.x * blockDim.x;
    for (int e = i; e < nnz; e += stride)
        atomicAdd(&g_ofs[2 * er[e] + (ec[e] >= NITEM)], 1);
}

__global__ void k_scan1()
{
    __shared__ int sm[256];
    int t = threadIdx.x;
    int idx = blockIdx.x * 256 + t;
    int v = (idx < NSEG) ? g_ofs[idx] : 0;
    sm[t] = v;
    __syncthreads();
    #pragma unroll
    for (int off = 128; off; off >>= 1) {
        if (t < off) sm[t] += sm[t + off];
        __syncthreads();
    }
    if (t == 0) g_bsum[blockIdx.x] = sm[0];
}

__global__ void k_scan2()
{
    __shared__ int sm[1024];
    int t = threadIdx.x;
    int v = (t < SCANB) ? g_bsum[t] : 0;
    sm[t] = v;
    __syncthreads();
    #pragma unroll
    for (int off = 1; off < 1024; off <<= 1) {
        int add = (t >= off) ? sm[t - off] : 0;
        __syncthreads();
        sm[t] += add;
        __syncthreads();
    }
    if (t < SCANB) g_boff[t] = sm[t] - v;
    if (t == 1023) g_rowptr[NSEG] = sm[1023];
}

__global__ void k_scan3()
{
    __shared__ int sm[256];
    int t = threadIdx.x;
    int idx = blockIdx.x * 256 + t;
    int v = (idx < NSEG) ? g_ofs[idx] : 0;
    sm[t] = v;
    __syncthreads();
    #pragma unroll
    for (int off = 1; off < 256; off <<= 1) {
        int add = (t >= off) ? sm[t - off] : 0;
        __syncthreads();
        sm[t] += add;
        __syncthreads();
    }
    int ex = sm[t] - v + g_boff[blockIdx.x];
    if (idx < NSEG) { g_rowptr[idx] = ex; g_ofs[idx] = ex; }
}

__global__ void k_scatter(const int* __restrict__ er, const int* __restrict__ ec,
                          const float* __restrict__ ev, int nnz)
{
    int i = blockIdx.x * blockDim.x + threadIdx.x;
    int stride = gridDim.x * blockDim.x;
    for (int e = i; e < nnz; e += stride) {
        int c = ec[e];
        int pos = atomicAdd(&g_ofs[2 * er[e] + (c >= NITEM)], 1);
        g_scol[pos] = c;
        g_sval[pos] = ev[e];
    }
}

// ---------------- SpMM helpers (fp16 gathers, fp32 accumulate) ----------------
__device__ __forceinline__ void fma8(float* f, uint4 u, float v)
{
    const __half2* h = (const __half2*)&u;
    #pragma unroll
    for (int j = 0; j < 4; j++) {
        float2 t = __half22float2(h[j]);
        f[2 * j]     = fmaf(t.x, v, f[2 * j]);
        f[2 * j + 1] = fmaf(t.y, v, f[2 * j + 1]);
    }
}

__device__ __forceinline__ void accum16(const __half* __restrict__ x, int s, int e,
                                        int adj, int lane, float* f)
{
    int i = s;
    for (; i + 1 < e; i += 2) {
        int   c0 = g_scol[i] + adj, c1 = g_scol[i + 1] + adj;
        float v0 = g_sval[i],       v1 = g_sval[i + 1];
        const uint4* xa = (const uint4*)(x + (size_t)c0 * EMB);
        const uint4* xb = (const uint4*)(x + (size_t)c1 * EMB);
        uint4 a0 = __ldcg(&xa[lane]), a1 = __ldcg(&xa[lane + 32]);
        uint4 b0 = __ldcg(&xb[lane]), b1 = __ldcg(&xb[lane + 32]);
        fma8(f,     a0, v0); fma8(f + 8, a1, v0);
        fma8(f,     b0, v1); fma8(f + 8, b1, v1);
    }
    if (i < e) {
        int   c0 = g_scol[i] + adj;
        float v0 = g_sval[i];
        const uint4* xa = (const uint4*)(x + (size_t)c0 * EMB);
        uint4 a0 = __ldcg(&xa[lane]), a1 = __ldcg(&xa[lane + 32]);
        fma8(f, a0, v0); fma8(f + 8, a1, v0);
    }
}

// ---------------- SpMM full: warp per row, col-half split, 2 passes ----------------
__global__ void k_spmm_full(int srcSel, int doEdis, int pass)
{
    const __half* x16 = srcSel ? g_x16 : g_a16;
    const float* egoF = srcSel ? g_egoB : g_egoA;
    int lane = threadIdx.x & 31;
    int warp = (int)((blockIdx.x * blockDim.x + threadIdx.x) >> 5);
    int nw   = (int)((gridDim.x * blockDim.x) >> 5);

    int fi[4] = { 2 * lane, 2 * lane + 1, 2 * lane + 64, 2 * lane + 65 };

    for (int row = warp; row < NNODES; row += nw) {
        int b0 = g_rowptr[2 * row], b1 = g_rowptr[2 * row + 1], b2 = g_rowptr[2 * row + 2];
        float sacc[16];
        #pragma unroll
        for (int q = 0; q < 16; q++) sacc[q] = 0.f;
        if (pass == 0) accum16(x16, b0, b1, 0, lane, sacc);
        else           accum16(x16, b1, b2, 0, lane, sacc);

        float4* so = (float4*)(g_side + (size_t)row * EMB);
        float4* de = (float4*)(g_edis + (size_t)row * EMB);

        if (pass == 0) {
            if (doEdis) {
                float dacc[16];
                #pragma unroll
                for (int q = 0; q < 16; q++) dacc[q] = 0.f;
                accum16(x16, b1, b2, -NITEM, lane, dacc);
                #pragma unroll
                for (int q = 0; q < 4; q++)
                    __stcs(&de[fi[q]], *(float4*)(dacc + 4 * q));
            }
            #pragma unroll
            for (int q = 0; q < 4; q++)
                __stcs(&so[fi[q]], *(float4*)(sacc + 4 * q));
        } else {
            float4 dfin[4];
            if (doEdis) {
                float dacc[16];
                #pragma unroll
                for (int q = 0; q < 16; q++) dacc[q] = 0.f;
                accum16(x16, b0, b1, +NITEM, lane, dacc);
                #pragma unroll
                for (int q = 0; q < 4; q++) {
                    float4 cur = __ldcs(&de[fi[q]]);
                    cur.x += dacc[4 * q + 0]; cur.y += dacc[4 * q + 1];
                    cur.z += dacc[4 * q + 2]; cur.w += dacc[4 * q + 3];
                    __stcs(&de[fi[q]], cur);
                    dfin[q] = cur;
                }
            } else {
                #pragma unroll
                for (int q = 0; q < 4; q++) dfin[q] = __ldcg(&de[fi[q]]);
            }
            int rowo = (row < NITEM) ? row + NITEM : row - NITEM;
            const float4* eg = (const float4*)(egoF + (size_t)row * EMB);
            const float4* og = (const float4*)(g_egoA + (size_t)rowo * EMB);
            float4* ho = (float4*)(g_hbuf + (size_t)row * EMB);
            #pragma unroll
            for (int q = 0; q < 4; q++) {
                float4 s = __ldcs(&so[fi[q]]);
                s.x += sacc[4 * q + 0]; s.y += sacc[4 * q + 1];
                s.z += sacc[4 * q + 2]; s.w += sacc[4 * q + 3];
                __stcs(&so[fi[q]], s);
                float4 e = eg[fi[q]];
                float4 o = og[fi[q]];
                float4 d = dfin[q];
                float4 h;
                h.x = fmaf(e.x, s.x, o.x * d.x);
                h.y = fmaf(e.y, s.y, o.y * d.y);
                h.z = fmaf(e.z, s.z, o.z * d.z);
                h.w = fmaf(e.w, s.w, o.w * d.w);
                __stcs(&ho[fi[q]], h);
            }
        }
    }
}

// ---------------- SpMM slots: warp per gathered slot (layer 2), h fused ----------------
__global__ void k_spmm_slots(const int* __restrict__ items)
{
    int lane = threadIdx.x & 31;
    int slot = (int)((blockIdx.x * blockDim.x + threadIdx.x) >> 5);
    if (slot >= NSLOT) return;
    int row = (slot < BATCH) ? items[slot] : (items[slot - BATCH] + NITEM);
    int b0 = g_rowptr[2 * row], b2 = g_rowptr[2 * row + 2];
    float sacc[16];
    #pragma unroll
    for (int q = 0; q < 16; q++) sacc[q] = 0.f;
    accum16(g_x16, b0, b2, 0, lane, sacc);
    int fi[4] = { 2 * lane, 2 * lane + 1, 2 * lane + 64, 2 * lane + 65 };
    int rowo = (row < NITEM) ? row + NITEM : row - NITEM;
    const float4* eg = (const float4*)(g_egoC + (size_t)row * EMB);
    const float4* og = (const float4*)(g_egoA + (size_t)rowo * EMB);
    const float4* de = (const float4*)(g_edis + (size_t)row * EMB);
    float4* so = (float4*)(g_side + (size_t)row * EMB);
    float4* ho = (float4*)(g_hbuf + (size_t)row * EMB);
    #pragma unroll
    for (int q = 0; q < 4; q++) {
        float4 s = *(float4*)(sacc + 4 * q);
        so[fi[q]] = s;
        float4 e = eg[fi[q]];
        float4 o = og[fi[q]];
        float4 d = de[fi[q]];
        float4 h;
        h.x = fmaf(e.x, s.x, o.x * d.x);
        h.y = fmaf(e.y, s.y, o.y * d.y);
        h.z = fmaf(e.z, s.z, o.z * d.z);
        h.w = fmaf(e.w, s.w, o.w * d.w);
        ho[fi[q]] = h;
    }
}

// ---------------- weight transpose + fp16 convert ----------------
__global__ void k_wtconv(const float* __restrict__ Wgc, const float* __restrict__ Wgc2,
                         const float* __restrict__ Wbi, int layer)
{
    __shared__ float t[32][33];
    int kb = blockIdx.x * 32;
    int nb = blockIdx.y * 32;
    int tx = threadIdx.x & 31, ty = threadIdx.x >> 5;
    int seg = kb >> 9, kloc = kb & 511;
    const float* W = (seg == 0) ? Wgc : (seg == 1) ? Wgc2 : Wbi;
    size_t lbase = (size_t)layer * 512 * 1536;
    #pragma unroll
    for (int j = 0; j < 4; j++)
        t[ty + 8 * j][tx] = W[(size_t)(kloc + ty + 8 * j) * 512 + nb + tx];
    __syncthreads();
    #pragma unroll
    for (int j = 0; j < 4; j++) {
        int n = nb + ty + 8 * j;
        g_wt16[lbase + (size_t)n * 1536 + kb + tx] = __float2half_rn(t[tx][ty + 8 * j]);
    }
}

// ---------------- mma.sync fp16 fused GEMM, 128x256, cp.async B ----------------
// A = [side | edis | hbuf] (fp16-converted on the fly); outSel: 0=egoB 1=egoC 2=ego3
__global__ void __launch_bounds__(512)
k_gemm(int outSel, int layer,
       const float* __restrict__ bgc, const float* __restrict__ bgc2,
       const float* __restrict__ bbi,
       int M, const int* __restrict__ items)
{
    extern __shared__ __align__(16) char smbuf[];
    const uint32_t OA = 0, OB = 10240;
    float* biasP = (float*)(smbuf + 2 * STAGE_SZ);
    uint32_t smb = smem_u32(smbuf);

    int tid = threadIdx.x;
    int wid = tid >> 5, lid = tid & 31;
    int col0 = blockIdx.x * 256;
    int row0 = blockIdx.y * 128;
    int wM = wid >> 2, wN = wid & 3;

    if (tid < 256) {
        int c = col0 + tid;
        biasP[tid] = bgc[c] + bgc2[c] + bbi[c];
    }

    float* Cout = (outSel == 0) ? g_egoB : (outSel == 1) ? g_egoC : g_ego3;
    const __half* wt = g_wt16 + (size_t)layer * 512 * 1536;

    int mA0 = tid >> 3, mA1 = (tid + 512) >> 3;
    int k4  = (tid & 7) * 4;
    int node0, node1;
    {
        int g0 = row0 + mA0, g1 = row0 + mA1;
        int s0 = (g0 < M) ? g0 : (M - 1);
        int s1 = (g1 < M) ? g1 : (M - 1);
        node0 = items ? ((s0 < BATCH) ? items[s0] : (items[s0 - BATCH] + NITEM)) : s0;
        node1 = items ? ((s1 < BATCH) ? items[s1] : (items[s1 - BATCH] + NITEM)) : s1;
    }
    int nB = tid >> 1, kqB = (tid & 1) * 16;

    float acc[2][8][4];
    #pragma unroll
    for (int mt = 0; mt < 2; mt++)
        #pragma unroll
        for (int nt = 0; nt < 8; nt++)
            #pragma unroll
            for (int q = 0; q < 4; q++) acc[mt][nt][q] = 0.f;

    float pa[2][4];

    auto prefetchA = [&](int c) {
        int seg = c >> 4;
        int kloc = (c & 15) * 32;
        const float* src = (seg == 0) ? g_side : (seg == 1) ? g_edis : g_hbuf;
        *(float4*)pa[0] = *(const float4*)(src + (size_t)node0 * EMB + kloc + k4);
        *(float4*)pa[1] = *(const float4*)(src + (size_t)node1 * EMB + kloc + k4);
    };

    auto storeA = [&](int stage) {
        uint32_t base = smb + stage * STAGE_SZ;
        #pragma unroll
        for (int l = 0; l < 2; l++) {
            int m = l ? mA1 : mA0;
            uint32_t ad = m * STRB + k4 * 2;
            uint32_t h0 = packh2(pa[l][0], pa[l][1]);
            uint32_t h1 = packh2(pa[l][2], pa[l][3]);
            asm volatile("st.shared.v2.b32 [%0], {%1,%2};" :: "r"(base + OA + ad), "r"(h0), "r"(h1) : "memory");
        }
    };

    auto cpasyncB = [&](int c) {
        uint32_t base = smb + (c & 1) * STAGE_SZ;
        const char* gw = (const char*)(wt + (size_t)(col0 + nB) * 1536 + c * 32 + kqB);
        uint32_t bd = base + OB + nB * STRB + kqB * 2;
        CP16(bd, gw);
        CP16(bd + 16, gw + 16);
    };

    uint32_t aOff = (uint32_t)((wM * 32 + (lid & 15)) * STRB + (lid >> 4) * 16);
    uint32_t bOff[4];
    #pragma unroll
    for (int p = 0; p < 4; p++)
        bOff[p] = (uint32_t)((wN * 64 + p * 16 + (lid & 7) + ((lid >> 4) << 3)) * STRB + (((lid >> 3) & 1) << 4));

    prefetchA(0);
    storeA(0);
    cpasyncB(0);
    CP_COMMIT();
    prefetchA(1);
    CP_WAIT0();
    __syncthreads();

    for (int c = 0; c < NCH; c++) {
        if (c + 1 < NCH) { cpasyncB(c + 1); CP_COMMIT(); }
        uint32_t sb = smb + (c & 1) * STAGE_SZ;
        #pragma unroll
        for (int kk = 0; kk < 2; kk++) {
            uint32_t ko = kk * 32;
            uint32_t ah[2][4];
            LDSM4(ah[0][0], ah[0][1], ah[0][2], ah[0][3], sb + OA + aOff + ko);
            LDSM4(ah[1][0], ah[1][1], ah[1][2], ah[1][3], sb + OA + aOff + 16 * STRB + ko);
            #pragma unroll
            for (int p = 0; p < 4; p++) {
                uint32_t b4[4];
                LDSM4(b4[0], b4[1], b4[2], b4[3], sb + OB + bOff[p] + ko);
                #pragma unroll
                for (int mt = 0; mt < 2; mt++) {
                    MMAF16(acc[mt][2 * p],     ah[mt], (b4 + 0));
                    MMAF16(acc[mt][2 * p + 1], ah[mt], (b4 + 2));
                }
            }
        }
        if (c + 1 < NCH) {
            storeA((c + 1) & 1);
            if (c + 2 < NCH) prefetchA(c + 2);
            CP_WAIT0();
            __syncthreads();
        }
    }

    // ---- epilogue: bias + leaky_relu (fp32 out + fp16 gather copy) ----
    int rA = lid >> 2;
    int cA = (lid & 3) * 2;
    #pragma unroll
    for (int mt = 0; mt < 2; mt++) {
        #pragma unroll
        for (int half = 0; half < 2; half++) {
            int gr = row0 + wM * 32 + mt * 16 + rA + half * 8;
            if (gr < M) {
                float* cp = Cout + (size_t)gr * EMB + col0 + wN * 64;
                __half* hp = g_x16 + (size_t)gr * EMB + col0 + wN * 64;
                #pragma unroll
                for (int nt = 0; nt < 8; nt++) {
                    int cc = nt * 8 + cA;
                    float x0 = acc[mt][nt][half * 2 + 0] + biasP[wN * 64 + cc];
                    float x1 = acc[mt][nt][half * 2 + 1] + biasP[wN * 64 + cc + 1];
                    float2 o;
                    o.x = (x0 > 0.f) ? x0 : 0.2f * x0;
                    o.y = (x1 > 0.f) ? x1 : 0.2f * x1;
                    *(float2*)(cp + cc) = o;
                    if (outSel < 2)
                        *(__half2*)(hp + cc) = __floats2half2_rn(o.x, o.y);
                }
            }
        }
    }
}

// ---------------- out[slot] = ego0[node]  (acc init) ----------------
__global__ void k_out_init(const int* __restrict__ items, float* __restrict__ out)
{
    int slot = blockIdx.x;
    int node = (slot < BATCH) ? items[slot] : (items[slot - BATCH] + NITEM);
    int t = threadIdx.x;
    float4 x = *(const float4*)(g_egoA + (size_t)node * EMB + t * 4);
    *(float4*)(out + (size_t)slot * EMB + t * 4) = x;
}

// ---------------- out[slot] += normalize(src_row) ----------------
__global__ void k_norm_acc(int srcSel, const int* __restrict__ items, float* __restrict__ out)
{
    int slot = blockIdx.x;
    int node = (slot < BATCH) ? items[slot] : (items[slot - BATCH] + NITEM);
    const float* row;
    if (srcSel == 0)      row = g_egoB + (size_t)node * EMB;
    else if (srcSel == 1) row = g_egoC + (size_t)node * EMB;
    else                  row = g_ego3 + (size_t)slot * EMB;

    int t = threadIdx.x;  // 128 threads
    float4 x = *(const float4*)(row + t * 4);
    float ss = x.x * x.x + x.y * x.y + x.z * x.z + x.w * x.w;
    #pragma unroll
    for (int o = 16; o; o >>= 1) ss += __shfl_xor_sync(0xffffffffu, ss, o);
    __shared__ float ws[4];
    if ((t & 31) == 0) ws[t >> 5] = ss;
    __syncthreads();
    float tot = ws[0] + ws[1] + ws[2] + ws[3];
    float inv = 1.f / fmaxf(sqrtf(tot), 1e-12f);

    float* o4 = out + (size_t)slot * EMB + t * 4;
    float4 cur = *(float4*)o4;
    cur.x += x.x * inv; cur.y += x.y * inv; cur.z += x.z * inv; cur.w += x.w * inv;
    *(float4*)o4 = cur;
}

// ---------------- launch ----------------
extern "C" void kernel_launch(void* const* d_in, const int* in_sizes, int n_in,
                              void* d_out, int out_size)
{
    const float* vis   = (const float*)d_in[0];
    const float* txt   = (const float*)d_in[1];
    const int*   er    = (const int*)  d_in[2];
    const int*   ec    = (const int*)  d_in[3];
    const float* ev    = (const float*)d_in[4];
    const int*   items = (const int*)  d_in[5];
    const float* Wgc   = (const float*)d_in[6];
    const float* bgc   = (const float*)d_in[7];
    const float* Wgc2  = (const float*)d_in[8];
    const float* bgc2  = (const float*)d_in[9];
    const float* Wbi   = (const float*)d_in[10];
    const float* bbi   = (const float*)d_in[11];
    float* out = (float*)d_out;
    int nnz = in_sizes[2];

    cudaFuncSetAttribute(k_gemm, cudaFuncAttributeMaxDynamicSharedMemorySize, GEMM_SMEM);

    const int SPMM_B = 2048;
    dim3 gGrid(2, (NNODES + 127) / 128);   // (2, 782)
    dim3 gGrid3(2, NSLOT / 128);           // (2, 64)
    dim3 wGrid(48, 16);

    // init + CSR build (+ all weight conversions upfront)
    k_init<<<25000, 256>>>(vis, txt);
    k_zero2<<<782, 256>>>();
    k_hist<<<2048, 256>>>(er, ec, nnz);
    k_scan1<<<SCANB, 256>>>();
    k_scan2<<<1, 1024>>>();
    k_scan3<<<SCANB, 256>>>();
    k_scatter<<<2048, 256>>>(er, ec, ev, nnz);
    k_wtconv<<<wGrid, 256>>>(Wgc, Wgc2, Wbi, 0);
    k_wtconv<<<wGrid, 256>>>(Wgc + 1 * 512 * 512, Wgc2 + 1 * 512 * 512, Wbi + 1 * 512 * 512, 1);
    k_wtconv<<<wGrid, 256>>>(Wgc + 2 * 512 * 512, Wgc2 + 2 * 512 * 512, Wbi + 2 * 512 * 512, 2);

    // acc init
    k_out_init<<<NSLOT, 128>>>(items, out);

    // ---- layer 0 ----
    k_spmm_full<<<SPMM_B, 256>>>(0, 1, 0);
    k_spmm_full<<<SPMM_B, 256>>>(0, 1, 1);
    k_gemm<<<gGrid, 512, GEMM_SMEM>>>(0, 0, bgc, bgc2, bbi, NNODES, nullptr);
    k_norm_acc<<<NSLOT, 128>>>(0, items, out);

    // ---- layer 1 ----
    k_spmm_full<<<SPMM_B, 256>>>(1, 0, 0);
    k_spmm_full<<<SPMM_B, 256>>>(1, 0, 1);
    k_gemm<<<gGrid, 512, GEMM_SMEM>>>(1, 1, bgc + 512, bgc2 + 512, bbi + 512, NNODES, nullptr);
    k_norm_acc<<<NSLOT, 128>>>(1, items, out);

    // ---- layer 2 (subset) ----
    k_spmm_slots<<<1024, 256>>>(items);
    k_gemm<<<gGrid3, 512, GEMM_SMEM>>>(2, 2, bgc + 1024, bgc2 + 1024, bbi + 1024, NSLOT, items);
    k_norm_acc<<<NSLOT, 128>>>(2, items, out);
}